// round 9
// baseline (speedup 1.0000x reference)
#include <cuda_runtime.h>
#include <cuda_fp16.h>
#include <cstdint>

#define BSZ 2
#define LQ 2048
#define DM 256
#define MROWS (BSZ*LQ)
#define SPLITS 2

// scratch
__device__ __half g_Qh[MROWS*DM];
__device__ __half g_Kh[MROWS*DM];
__device__ __half g_Vh[MROWS*DM];
__device__ float g_msg[MROWS*DM];
__device__ float g_hid[MROWS*2*DM];
__device__ float g_part[SPLITS*MROWS*DM];
__device__ float g_pstat[SPLITS*MROWS*4*2];

// ---------------------------------------------------------------------------
__device__ __forceinline__ unsigned h2pk(float lo, float hi){
    unsigned r; asm("cvt.rn.f16x2.f32 %0, %1, %2;" : "=r"(r) : "f"(hi), "f"(lo)); return r;
}
__device__ __forceinline__ void ldsm4(unsigned* r, unsigned a){
    asm volatile("ldmatrix.sync.aligned.m8n8.x4.shared.b16 {%0,%1,%2,%3},[%4];"
        : "=r"(r[0]),"=r"(r[1]),"=r"(r[2]),"=r"(r[3]) : "r"(a));
}
__device__ __forceinline__ void ldsm4t(unsigned* r, unsigned a){
    asm volatile("ldmatrix.sync.aligned.m8n8.x4.trans.shared.b16 {%0,%1,%2,%3},[%4];"
        : "=r"(r[0]),"=r"(r[1]),"=r"(r[2]),"=r"(r[3]) : "r"(a));
}
__device__ __forceinline__ void mma16(float* c, const unsigned* a, const unsigned* b){
    asm volatile("mma.sync.aligned.m16n8k16.row.col.f32.f16.f16.f32 "
        "{%0,%1,%2,%3},{%4,%5,%6,%7},{%8,%9},{%0,%1,%2,%3};"
        : "+f"(c[0]), "+f"(c[1]), "+f"(c[2]), "+f"(c[3])
        : "r"(a[0]), "r"(a[1]), "r"(a[2]), "r"(a[3]), "r"(b[0]), "r"(b[1]));
}
// e^x for x <= 0, FMA-pipe only, degree-4 (err ~4e-5, < fp16 P rounding).
__device__ __forceinline__ float fast_exp(float x){
    float y = x * 1.44269504f;
    y = fmaxf(y, -126.0f);
    float z = y + 12582912.0f;
    int   n = __float_as_int(z) - 0x4B400000;
    float f = y - (z - 12582912.0f);
    float p = 9.61812e-3f;
    p = fmaf(p, f, 5.55041e-2f);
    p = fmaf(p, f, 2.40227e-1f);
    p = fmaf(p, f, 6.93147e-1f);
    p = fmaf(p, f, 1.0f);
    return p * __int_as_float((n + 127) << 23);
}

// ---------------------------------------------------------------------------
// fp16 GEMM: BM=16, BN=256, BK=32, 256 threads (8 warps, warp tile 16x32),
// double-buffered smem, ldmatrix, m16n8k16. Grid = M/16 -> 2-3 CTAs/SM.
// ---------------------------------------------------------------------------
#define AM_PLAIN 0
#define AM_ADD   1
#define AM_CAT   2
#define AM_MERGE 3
#define EPI_NONE 0
#define EPI_RELU 1
#define EPI_LN   2
#define EPI_LNR  3
#define EPI_H16  4

#define AS_H 40
#define BS_H 264
#define BUF_H (16*AS_H + 32*BS_H)    // 9088 halves
#define SM_GEMM (2*BUF_H*2)          // 36352 bytes

template<int KD, int AM>
__device__ __forceinline__ void gload(const float* __restrict__ A1, const float* __restrict__ A2,
    const float* __restrict__ B, int ldb, int n0, int row0, int kc, int tid,
    float4& pa, float4* pb)
{
    if (tid < 128){
        int ar = tid >> 3, ac4 = (tid & 7) << 2;
        int col = kc*32 + ac4;
        if (AM == AM_ADD){
            float4 x1 = *(const float4*)(A1 + (row0+ar)*KD + col);
            float4 x2 = *(const float4*)(A2 + (row0+ar)*KD + col);
            pa = make_float4(x1.x+x2.x, x1.y+x2.y, x1.z+x2.z, x1.w+x2.w);
        } else if (AM == AM_CAT){
            const float* s = (col < 256) ? (A1 + (row0+ar)*256 + col)
                                         : (A2 + (row0+ar)*256 + (col-256));
            pa = *(const float4*)s;
        } else if (AM == AM_MERGE){
            long r0 = row0 + ar;
            int hh = kc >> 1;     // 32-col chunk -> head
            float m0 = g_pstat[((0L*MROWS + r0)*4 + hh)*2];
            float s0 = g_pstat[((0L*MROWS + r0)*4 + hh)*2 + 1];
            float m1 = g_pstat[((1L*MROWS + r0)*4 + hh)*2];
            float s1 = g_pstat[((1L*MROWS + r0)*4 + hh)*2 + 1];
            float M = fmaxf(m0, m1);
            float w0 = fast_exp(m0 - M), w1 = fast_exp(m1 - M);
            float inv = 1.0f/(s0*w0 + s1*w1);
            w0 *= inv; w1 *= inv;
            float4 p0 = *(const float4*)(g_part + (0L*MROWS + r0)*256 + col);
            float4 p1 = *(const float4*)(g_part + (1L*MROWS + r0)*256 + col);
            pa = make_float4(p0.x*w0 + p1.x*w1, p0.y*w0 + p1.y*w1,
                             p0.z*w0 + p1.z*w1, p0.w*w0 + p1.w*w1);
        } else {
            pa = *(const float4*)(A1 + (row0+ar)*KD + col);
        }
    }
    #pragma unroll
    for (int i = 0; i < 8; i++){
        int id = tid + i*256;
        int r = id >> 6, c4 = (id & 63) << 2;
        pb[i] = *(const float4*)(B + (kc*32 + r)*ldb + n0 + c4);
    }
}

__device__ __forceinline__ void sstore_h(__half* buf, int tid, const float4& pa, const float4* pb)
{
    __half* Ab = buf;
    __half* Bb = buf + 16*AS_H;
    if (tid < 128){
        int ar = tid >> 3, ac4 = (tid & 7) << 2;
        *(uint2*)&Ab[ar*AS_H + ac4] = make_uint2(h2pk(pa.x, pa.y), h2pk(pa.z, pa.w));
    }
    #pragma unroll
    for (int i = 0; i < 8; i++){
        int id = tid + i*256;
        int r = id >> 6, c4 = (id & 63) << 2;
        *(uint2*)&Bb[r*BS_H + c4] = make_uint2(h2pk(pb[i].x, pb[i].y), h2pk(pb[i].z, pb[i].w));
    }
}

template<int KD, int AM, int EPI>
__device__ __forceinline__ void gemm_body(
    const float* __restrict__ A1, const float* __restrict__ A2,
    const float* __restrict__ B, int ldb, int n0,
    const float* __restrict__ gamma, const float* __restrict__ beta,
    const float* __restrict__ resid, void* __restrict__ Cv, int ldc)
{
    extern __shared__ unsigned char smraw[];
    __half* smh = (__half*)smraw;
    const int KC = KD/32;
    int tid = threadIdx.x;
    int wn = tid >> 5, lane = tid & 31;
    int g4 = lane >> 2, tig = lane & 3;
    int lrow = (lane & 7) + ((lane >> 3) & 1)*8;
    int lcol8 = (lane >> 4)*8;
    int row0 = blockIdx.x * 16;
    unsigned sb = (unsigned)__cvta_generic_to_shared(smh);

    float acc[4][4];
    #pragma unroll
    for (int nt = 0; nt < 4; nt++)
        #pragma unroll
        for (int i = 0; i < 4; i++) acc[nt][i] = 0.f;

    float4 pa, pb[8];
    gload<KD, AM>(A1, A2, B, ldb, n0, row0, 0, tid, pa, pb);
    sstore_h(smh, tid, pa, pb);
    __syncthreads();

    for (int kc = 0; kc < KC; kc++){
        unsigned ab = sb + ((kc & 1)*BUF_H)*2;
        unsigned bb = ab + 16*AS_H*2;
        if (kc + 1 < KC)
            gload<KD, AM>(A1, A2, B, ldb, n0, row0, kc+1, tid, pa, pb);
        #pragma unroll
        for (int kk = 0; kk < 2; kk++){
            int k0 = kk*16;
            unsigned a[4];
            ldsm4(a, ab + (lrow*AS_H + k0 + lcol8)*2);
            #pragma unroll
            for (int j = 0; j < 2; j++){
                unsigned bv[4];
                ldsm4t(bv, bb + ((k0 + lrow)*BS_H + wn*32 + j*16 + lcol8)*2);
                unsigned b0[2] = {bv[0], bv[1]};
                unsigned b1[2] = {bv[2], bv[3]};
                mma16(acc[2*j],   a, b0);
                mma16(acc[2*j+1], a, b1);
            }
        }
        if (kc + 1 < KC)
            sstore_h(smh + ((kc+1) & 1)*BUF_H, tid, pa, pb);
        __syncthreads();
    }

    if (EPI == EPI_H16){
        __half* C = (__half*)Cv;
        int rl = row0 + g4;
        #pragma unroll
        for (int nt = 0; nt < 4; nt++){
            int col = n0 + wn*32 + nt*8 + 2*tig;
            *(unsigned*)(C + rl*ldc + col)     = h2pk(acc[nt][0], acc[nt][1]);
            *(unsigned*)(C + (rl+8)*ldc + col) = h2pk(acc[nt][2], acc[nt][3]);
        }
    } else if (EPI == EPI_NONE || EPI == EPI_RELU){
        float* C = (float*)Cv;
        int rl = row0 + g4;
        #pragma unroll
        for (int nt = 0; nt < 4; nt++){
            int col = n0 + wn*32 + nt*8 + 2*tig;
            float v0 = acc[nt][0], v1 = acc[nt][1];
            float v2 = acc[nt][2], v3 = acc[nt][3];
            if (EPI == EPI_RELU){
                v0=fmaxf(v0,0.f); v1=fmaxf(v1,0.f); v2=fmaxf(v2,0.f); v3=fmaxf(v3,0.f);
            }
            *(float2*)(C + rl*ldc + col)     = make_float2(v0, v1);
            *(float2*)(C + (rl+8)*ldc + col) = make_float2(v2, v3);
        }
    } else {
        float* C = (float*)Cv;
        float2* red = (float2*)smraw;   // red[16][8]
        float s1[2] = {0,0}, s2[2] = {0,0};
        #pragma unroll
        for (int nt = 0; nt < 4; nt++){
            float c0=acc[nt][0], c1=acc[nt][1], c2=acc[nt][2], c3=acc[nt][3];
            s1[0] += c0+c1; s2[0] += c0*c0 + c1*c1;
            s1[1] += c2+c3; s2[1] += c2*c2 + c3*c3;
        }
        #pragma unroll
        for (int hb = 0; hb < 2; hb++){
            float v1 = s1[hb], v2 = s2[hb];
            v1 += __shfl_xor_sync(~0u, v1, 1); v1 += __shfl_xor_sync(~0u, v1, 2);
            v2 += __shfl_xor_sync(~0u, v2, 1); v2 += __shfl_xor_sync(~0u, v2, 2);
            if (tig == 0)
                red[(g4 + hb*8)*8 + wn] = make_float2(v1, v2);
        }
        __syncthreads();
        #pragma unroll
        for (int hb = 0; hb < 2; hb++){
            int r = g4 + hb*8;
            float S1 = 0.f, S2 = 0.f;
            #pragma unroll
            for (int j = 0; j < 8; j++){ float2 e = red[r*8+j]; S1 += e.x; S2 += e.y; }
            float mean = S1 * (1.f/256.f);
            float var  = S2 * (1.f/256.f) - mean*mean;
            float inv  = rsqrtf(var + 1e-5f);
            int grow = row0 + r;
            #pragma unroll
            for (int nt = 0; nt < 4; nt++){
                int col = wn*32 + nt*8 + 2*tig;
                float c0 = acc[nt][hb*2], c1 = acc[nt][hb*2+1];
                float o0 = (c0 - mean)*inv*gamma[col]   + beta[col];
                float o1 = (c1 - mean)*inv*gamma[col+1] + beta[col+1];
                if (EPI == EPI_LNR){
                    o0 += resid[grow*256 + col];
                    o1 += resid[grow*256 + col + 1];
                }
                *(float2*)(C + grow*ldc + col) = make_float2(o0, o1);
            }
        }
    }
}

__global__ void __launch_bounds__(256) k_qkv(
    const float* x, const float* xpe, const float* src, const float* spe,
    const float* Wq, const float* Wk, const float* Wv)
{
    if (blockIdx.z == 0)      gemm_body<256, AM_ADD,   EPI_H16>(x,   xpe, Wq, 256, 0, 0,0,0, g_Qh, 256);
    else if (blockIdx.z == 1) gemm_body<256, AM_ADD,   EPI_H16>(src, spe, Wk, 256, 0, 0,0,0, g_Kh, 256);
    else                      gemm_body<256, AM_PLAIN, EPI_H16>(src, 0,   Wv, 256, 0, 0,0,0, g_Vh, 256);
}
__global__ void __launch_bounds__(256) k_merge(const float* Wmg, const float* gg, const float* bb){
    gemm_body<256, AM_MERGE, EPI_LN>(0, 0, Wmg, 256, 0, gg, bb, 0, g_msg, 256);
}
__global__ void __launch_bounds__(256) k_mlp1(const float* x, const float* Wm1){
    gemm_body<512, AM_CAT, EPI_RELU>(x, g_msg, Wm1, 512, blockIdx.y*256, 0,0,0, g_hid, 512);
}
__global__ void __launch_bounds__(256) k_mlp2(const float* Wm2, const float* gg, const float* bb,
                                              const float* x, float* out){
    gemm_body<512, AM_PLAIN, EPI_LNR>(g_hid, 0, Wm2, 256, 0, gg, bb, x, out, 256);
}

// ---------------------------------------------------------------------------
// Flash attention v6: fp16 Q/K/V at rest; P in its OWN smem region (2 syncs
// per tile instead of 3); mask folded into per-tile bias array.
// CTA = (32 l, split, b); warp = (h=w&3, wm=w>>2).
// ---------------------------------------------------------------------------
#define QH 264
#define PH 40
#define CS_STR 33
#define AT_K   8448               // half offsets
#define AT_V   16896
#define AT_P   25344
#define AT_CB  60928              // byte offset of Cs
#define AT_BB  65152              // byte offset of Bs (bias)
#define AT_XM  69376
#define ATTN_BYTES 69504

__global__ void __launch_bounds__(256, 2) k_attn(
    const __half* __restrict__ Qm, const __half* __restrict__ Km, const __half* __restrict__ Vm,
    const float* __restrict__ comp, const int* __restrict__ xmask, const int* __restrict__ smask)
{
    extern __shared__ unsigned char smraw[];
    __half* smh = (__half*)smraw;
    __half* Qh = smh;
    __half* Kh = smh + AT_K;
    __half* Vh = smh + AT_V;
    float*  Cs = (float*)(smraw + AT_CB);
    float*  Bs = (float*)(smraw + AT_BB);
    int*    xm = (int*)(smraw + AT_XM);

    int tid = threadIdx.x;
    int w = tid >> 5, lane = tid & 31;
    int h = w & 3, wm = w >> 2;
    int g4 = lane >> 2, tig = lane & 3;
    int lrow = (lane & 7) + ((lane >> 3) & 1)*8;
    int lcol8 = (lane >> 4)*8;
    int l0 = blockIdx.x * 32;
    int sp = blockIdx.y, b = blockIdx.z;
    int dbase = h*64;

    unsigned sb = (unsigned)__cvta_generic_to_shared(smh);
    unsigned qb = sb;
    unsigned kb = sb + AT_K*2;
    unsigned vb = sb + AT_V*2;
    unsigned pbsu = sb + (AT_P + h*1280)*2;
    __half* Ph = smh + AT_P + h*1280;

    // stage Q (32x256 halves)
    #pragma unroll
    for (int i = 0; i < 4; i++){
        int id = tid + i*256;
        int r = id >> 5, c8 = (id & 31) << 3;
        *(uint4*)&Qh[r*QH + c8] = *(const uint4*)(Qm + (b*LQ + l0 + r)*256 + c8);
    }
    if (tid < 32) xm[tid] = xmask[b*LQ + l0 + tid];

    float o[8][4];
    #pragma unroll
    for (int nt = 0; nt < 8; nt++)
        #pragma unroll
        for (int i = 0; i < 4; i++) o[nt][i] = 0.f;
    float rmax[2] = {-1e30f, -1e30f};
    float rsum[2] = {0.f, 0.f};

    int rl = wm*16 + g4;
    for (int t = 0; t < (LQ/SPLITS)/32; t++){
        int s0 = sp*(LQ/SPLITS) + t*32;
        __syncthreads();     // prev tile fully consumed
        // K, V tiles (uint4 copies)
        #pragma unroll
        for (int i = 0; i < 4; i++){
            int id = tid + i*256;
            int r = id >> 5, c8 = (id & 31) << 3;
            long grow = (long)(b*LQ + s0 + r)*256 + c8;
            *(uint4*)&Kh[r*QH + c8] = *(const uint4*)(Km + grow);
            *(uint4*)&Vh[r*QH + c8] = *(const uint4*)(Vm + grow);
        }
        // comp*0.125 + mask-bias tiles
        {
            int r = tid >> 5, c = tid & 31;
            int sv = smask[b*LQ + s0 + c];
            #pragma unroll
            for (int i = 0; i < 4; i++){
                int rr = r + i*8;
                Cs[rr*CS_STR + c] = comp[(long)(b*LQ + l0 + rr)*LQ + s0 + c] * 0.125f;
                Bs[rr*CS_STR + c] = (xm[rr] && !sv) ? -1e30f : 0.f;
            }
        }
        __syncthreads();     // tiles ready

        // ---- QK^T: S[16l x 32s] per warp ----
        float S[4][4];
        #pragma unroll
        for (int nt = 0; nt < 4; nt++)
            #pragma unroll
            for (int i = 0; i < 4; i++) S[nt][i] = 0.f;
        #pragma unroll
        for (int kk = 0; kk < 4; kk++){
            int k0 = dbase + kk*16;
            unsigned a[4];
            ldsm4(a, qb + ((wm*16 + lrow)*QH + k0 + lcol8)*2);
            #pragma unroll
            for (int sh = 0; sh < 2; sh++){
                unsigned bk[4];
                ldsm4(bk, kb + ((sh*16 + lrow)*QH + k0 + lcol8)*2);
                unsigned b0[2] = {bk[0], bk[2]};
                unsigned b1[2] = {bk[1], bk[3]};
                mma16(S[sh*2],   a, b0);
                mma16(S[sh*2+1], a, b1);
            }
        }

        // ---- softmax (warp-local; scale+bias fused) ----
        float tmaxl = -1e30f, tmaxh = -1e30f;
        #pragma unroll
        for (int nt = 0; nt < 4; nt++){
            int se = nt*8 + 2*tig, so = se + 1;
            float v0 = fmaf(S[nt][0], Cs[rl*CS_STR + se],     Bs[rl*CS_STR + se]);
            float v1 = fmaf(S[nt][1], Cs[rl*CS_STR + so],     Bs[rl*CS_STR + so]);
            float v2 = fmaf(S[nt][2], Cs[(rl+8)*CS_STR + se], Bs[(rl+8)*CS_STR + se]);
            float v3 = fmaf(S[nt][3], Cs[(rl+8)*CS_STR + so], Bs[(rl+8)*CS_STR + so]);
            S[nt][0]=v0; S[nt][1]=v1; S[nt][2]=v2; S[nt][3]=v3;
            tmaxl = fmaxf(tmaxl, fmaxf(v0, v1));
            tmaxh = fmaxf(tmaxh, fmaxf(v2, v3));
        }
        tmaxl = fmaxf(tmaxl, __shfl_xor_sync(~0u, tmaxl, 1));
        tmaxl = fmaxf(tmaxl, __shfl_xor_sync(~0u, tmaxl, 2));
        tmaxh = fmaxf(tmaxh, __shfl_xor_sync(~0u, tmaxh, 1));
        tmaxh = fmaxf(tmaxh, __shfl_xor_sync(~0u, tmaxh, 2));
        float ml = fmaxf(rmax[0], tmaxl), mh = fmaxf(rmax[1], tmaxh);
        float al = fast_exp(rmax[0] - ml), ah = fast_exp(rmax[1] - mh);
        rmax[0] = ml; rmax[1] = mh;
        float tsl = 0.f, tsh = 0.f;
        #pragma unroll
        for (int nt = 0; nt < 4; nt++){
            float p0 = fast_exp(S[nt][0] - ml);
            float p1 = fast_exp(S[nt][1] - ml);
            float p2 = fast_exp(S[nt][2] - mh);
            float p3 = fast_exp(S[nt][3] - mh);
            tsl += p0 + p1; tsh += p2 + p3;
            int se = nt*8 + 2*tig;
            *(unsigned*)&Ph[rl*PH + se]     = h2pk(p0, p1);
            *(unsigned*)&Ph[(rl+8)*PH + se] = h2pk(p2, p3);
        }
        tsl += __shfl_xor_sync(~0u, tsl, 1); tsl += __shfl_xor_sync(~0u, tsl, 2);
        tsh += __shfl_xor_sync(~0u, tsh, 1); tsh += __shfl_xor_sync(~0u, tsh, 2);
        rsum[0] = rsum[0]*al + tsl;
        rsum[1] = rsum[1]*ah + tsh;
        #pragma unroll
        for (int nt = 0; nt < 8; nt++){
            o[nt][0] *= al; o[nt][1] *= al;
            o[nt][2] *= ah; o[nt][3] *= ah;
        }
        __syncwarp();        // P producer == consumer rows (same warp)

        // ---- P @ V: o[16l x 64d] ----
        #pragma unroll
        for (int kk = 0; kk < 2; kk++){
            unsigned a[4];
            ldsm4(a, pbsu + ((wm*16 + lrow)*PH + kk*16 + lcol8)*2);
            #pragma unroll
            for (int j = 0; j < 4; j++){
                unsigned bv[4];
                ldsm4t(bv, vb + ((kk*16 + lrow)*QH + dbase + j*16 + lcol8)*2);
                unsigned b0[2] = {bv[0], bv[1]};
                unsigned b1[2] = {bv[2], bv[3]};
                mma16(o[2*j],   a, b0);
                mma16(o[2*j+1], a, b1);
            }
        }
    }

    // ---- write unnormalized partials + stats ----
    long prow = (long)(sp*MROWS + b*LQ + l0 + rl);
    #pragma unroll
    for (int nt = 0; nt < 8; nt++){
        int col = dbase + nt*8 + 2*tig;
        *(float2*)(g_part + prow*256 + col)     = make_float2(o[nt][0], o[nt][1]);
        *(float2*)(g_part + (prow+8)*256 + col) = make_float2(o[nt][2], o[nt][3]);
    }
    if (tig == 0){
        long base = (prow*4 + h)*2;
        g_pstat[base]   = rmax[0];
        g_pstat[base+1] = rsum[0];
        long baseh = ((prow+8)*4 + h)*2;
        g_pstat[baseh]   = rmax[1];
        g_pstat[baseh+1] = rsum[1];
    }
}

// ---------------------------------------------------------------------------
extern "C" void kernel_launch(void* const* d_in, const int* in_sizes, int n_in,
                              void* d_out, int out_size)
{
    const float* x    = (const float*)d_in[0];
    const float* src  = (const float*)d_in[1];
    const float* xpe  = (const float*)d_in[2];
    const float* spe  = (const float*)d_in[3];
    const int* xmask  = (const int*)d_in[4];
    const int* smask  = (const int*)d_in[5];
    const float* comp = (const float*)d_in[6];
    const float* Wq   = (const float*)d_in[7];
    const float* Wk   = (const float*)d_in[8];
    const float* Wv   = (const float*)d_in[9];
    const float* Wmg  = (const float*)d_in[10];
    const float* Wm1  = (const float*)d_in[11];
    const float* Wm2  = (const float*)d_in[12];
    const float* ln1g = (const float*)d_in[13];
    const float* ln1b = (const float*)d_in[14];
    const float* ln2g = (const float*)d_in[15];
    const float* ln2b = (const float*)d_in[16];
    float* out = (float*)d_out;

    __half *Qp, *Kp, *Vp;
    cudaGetSymbolAddress((void**)&Qp, g_Qh);
    cudaGetSymbolAddress((void**)&Kp, g_Kh);
    cudaGetSymbolAddress((void**)&Vp, g_Vh);

    cudaFuncSetAttribute(k_attn, cudaFuncAttributeMaxDynamicSharedMemorySize, ATTN_BYTES);

    k_qkv <<<dim3(MROWS/16, 1, 3), 256, SM_GEMM>>>(x, xpe, src, spe, Wq, Wk, Wv);
    k_attn<<<dim3(LQ/32, SPLITS, BSZ), 256, ATTN_BYTES>>>(Qp, Kp, Vp, comp, xmask, smask);
    k_merge<<<MROWS/16,            256, SM_GEMM>>>(Wmg, ln1g, ln1b);
    k_mlp1<<<dim3(MROWS/16, 2),    256, SM_GEMM>>>(x, Wm1);
    k_mlp2<<<MROWS/16,             256, SM_GEMM>>>(Wm2, ln2g, ln2b, x, out);
}

// round 10
// speedup vs baseline: 1.3437x; 1.3437x over previous
#include <cuda_runtime.h>
#include <cuda_fp16.h>
#include <cstdint>

#define BSZ 2
#define LQ 2048
#define DM 256
#define MROWS (BSZ*LQ)
#define SPLITS 2

// scratch
__device__ __half g_Qh[MROWS*DM];
__device__ __half g_Kh[MROWS*DM];
__device__ __half g_Vh[MROWS*DM];
__device__ float g_msg[MROWS*DM];
__device__ float g_hid[MROWS*2*DM];
__device__ float g_part[SPLITS*MROWS*DM];
__device__ float g_pstat[SPLITS*MROWS*4*2];

// ---------------------------------------------------------------------------
__device__ __forceinline__ unsigned h2pk(float lo, float hi){
    unsigned r; asm("cvt.rn.f16x2.f32 %0, %1, %2;" : "=r"(r) : "f"(hi), "f"(lo)); return r;
}
__device__ __forceinline__ void ldsm4(unsigned* r, unsigned a){
    asm volatile("ldmatrix.sync.aligned.m8n8.x4.shared.b16 {%0,%1,%2,%3},[%4];"
        : "=r"(r[0]),"=r"(r[1]),"=r"(r[2]),"=r"(r[3]) : "r"(a));
}
__device__ __forceinline__ void ldsm4t(unsigned* r, unsigned a){
    asm volatile("ldmatrix.sync.aligned.m8n8.x4.trans.shared.b16 {%0,%1,%2,%3},[%4];"
        : "=r"(r[0]),"=r"(r[1]),"=r"(r[2]),"=r"(r[3]) : "r"(a));
}
__device__ __forceinline__ void mma16(float* c, const unsigned* a, const unsigned* b){
    asm volatile("mma.sync.aligned.m16n8k16.row.col.f32.f16.f16.f32 "
        "{%0,%1,%2,%3},{%4,%5,%6,%7},{%8,%9},{%0,%1,%2,%3};"
        : "+f"(c[0]), "+f"(c[1]), "+f"(c[2]), "+f"(c[3])
        : "r"(a[0]), "r"(a[1]), "r"(a[2]), "r"(a[3]), "r"(b[0]), "r"(b[1]));
}
__device__ __forceinline__ void cpa16(unsigned dst, const void* src){
    asm volatile("cp.async.cg.shared.global [%0], [%1], 16;" :: "r"(dst), "l"(src));
}
__device__ __forceinline__ void cpa4(unsigned dst, const void* src){
    asm volatile("cp.async.ca.shared.global [%0], [%1], 4;" :: "r"(dst), "l"(src));
}
#define CPA_COMMIT() asm volatile("cp.async.commit_group;" ::: "memory")
#define CPA_WAIT0()  asm volatile("cp.async.wait_group 0;" ::: "memory")

// e^x for x <= 0, FMA-pipe only. rel err ~2e-6.
__device__ __forceinline__ float fast_exp(float x){
    float y = x * 1.44269504f;
    y = fmaxf(y, -126.0f);
    float z = y + 12582912.0f;
    int   n = __float_as_int(z) - 0x4B400000;
    float f = y - (z - 12582912.0f);
    float p = 1.33336e-3f;
    p = fmaf(p, f, 9.61813e-3f);
    p = fmaf(p, f, 5.55041e-2f);
    p = fmaf(p, f, 2.40227e-1f);
    p = fmaf(p, f, 6.93147e-1f);
    p = fmaf(p, f, 1.0f);
    return p * __int_as_float((n + 127) << 23);
}

// ---------------------------------------------------------------------------
// fp16 GEMM: BM=32, BN=256, BK=32, 256 threads, double-buffered smem,
// ldmatrix frag loads, m16n8k16 mma. (R8 proven)
// ---------------------------------------------------------------------------
#define AM_PLAIN 0
#define AM_ADD   1
#define AM_CAT   2
#define AM_MERGE 3
#define EPI_NONE 0
#define EPI_RELU 1
#define EPI_LN   2
#define EPI_LNR  3
#define EPI_H16  4

#define AS_H 40
#define BS_H 264
#define BUF_H (32*AS_H + 32*BS_H)
#define SM_GEMM (2*BUF_H*2)

template<int KD, int AM>
__device__ __forceinline__ void gload(const float* __restrict__ A1, const float* __restrict__ A2,
    const float* __restrict__ B, int ldb, int n0, int row0, int kc, int tid,
    float4& pa, float4* pb)
{
    int ar = tid >> 3, ac4 = (tid & 7) << 2;
    int col = kc*32 + ac4;
    if (AM == AM_ADD){
        float4 x1 = *(const float4*)(A1 + (row0+ar)*KD + col);
        float4 x2 = *(const float4*)(A2 + (row0+ar)*KD + col);
        pa = make_float4(x1.x+x2.x, x1.y+x2.y, x1.z+x2.z, x1.w+x2.w);
    } else if (AM == AM_CAT){
        const float* s = (col < 256) ? (A1 + (row0+ar)*256 + col)
                                     : (A2 + (row0+ar)*256 + (col-256));
        pa = *(const float4*)s;
    } else if (AM == AM_MERGE){
        long r0 = row0 + ar;
        int hh = kc >> 1;      // KD=256: 32-col chunk -> head (64 cols per head)
        float m0 = g_pstat[((0L*MROWS + r0)*4 + hh)*2];
        float s0 = g_pstat[((0L*MROWS + r0)*4 + hh)*2 + 1];
        float m1 = g_pstat[((1L*MROWS + r0)*4 + hh)*2];
        float s1 = g_pstat[((1L*MROWS + r0)*4 + hh)*2 + 1];
        float M = fmaxf(m0, m1);
        float w0 = fast_exp(m0 - M), w1 = fast_exp(m1 - M);
        float inv = 1.0f/(s0*w0 + s1*w1);
        w0 *= inv; w1 *= inv;
        float4 p0 = *(const float4*)(g_part + (0L*MROWS + r0)*256 + col);
        float4 p1 = *(const float4*)(g_part + (1L*MROWS + r0)*256 + col);
        pa = make_float4(p0.x*w0 + p1.x*w1, p0.y*w0 + p1.y*w1,
                         p0.z*w0 + p1.z*w1, p0.w*w0 + p1.w*w1);
    } else {
        pa = *(const float4*)(A1 + (row0+ar)*KD + col);
    }
    #pragma unroll
    for (int i = 0; i < 8; i++){
        int id = tid + i*256;
        int r = id >> 6, c4 = (id & 63) << 2;
        pb[i] = *(const float4*)(B + (kc*32 + r)*ldb + n0 + c4);
    }
}

__device__ __forceinline__ void sstore_h(__half* buf, int tid, const float4& pa, const float4* pb)
{
    __half* Ab = buf;
    __half* Bb = buf + 32*AS_H;
    int ar = tid >> 3, ac4 = (tid & 7) << 2;
    *(uint2*)&Ab[ar*AS_H + ac4] = make_uint2(h2pk(pa.x, pa.y), h2pk(pa.z, pa.w));
    #pragma unroll
    for (int i = 0; i < 8; i++){
        int id = tid + i*256;
        int r = id >> 6, c4 = (id & 63) << 2;
        *(uint2*)&Bb[r*BS_H + c4] = make_uint2(h2pk(pb[i].x, pb[i].y), h2pk(pb[i].z, pb[i].w));
    }
}

template<int KD, int AM, int EPI>
__device__ __forceinline__ void gemm_body(
    const float* __restrict__ A1, const float* __restrict__ A2,
    const float* __restrict__ B, int ldb, int n0,
    const float* __restrict__ gamma, const float* __restrict__ beta,
    const float* __restrict__ resid, void* __restrict__ Cv, int ldc)
{
    extern __shared__ unsigned char smraw[];
    __half* smh = (__half*)smraw;
    const int KC = KD/32;
    int tid = threadIdx.x;
    int w = tid >> 5, lane = tid & 31;
    int wm = w >> 2, wn = w & 3;
    int g4 = lane >> 2, tig = lane & 3;
    int lrow = (lane & 7) + ((lane >> 3) & 1)*8;
    int lcol8 = (lane >> 4)*8;
    int row0 = blockIdx.x * 32;
    unsigned sb = (unsigned)__cvta_generic_to_shared(smh);

    float acc[8][4];
    #pragma unroll
    for (int nt = 0; nt < 8; nt++)
        #pragma unroll
        for (int i = 0; i < 4; i++) acc[nt][i] = 0.f;

    float4 pa, pb[8];
    gload<KD, AM>(A1, A2, B, ldb, n0, row0, 0, tid, pa, pb);
    sstore_h(smh, tid, pa, pb);
    __syncthreads();

    for (int kc = 0; kc < KC; kc++){
        unsigned ab = sb + ((kc & 1)*BUF_H)*2;
        unsigned bb = ab + 32*AS_H*2;
        if (kc + 1 < KC)
            gload<KD, AM>(A1, A2, B, ldb, n0, row0, kc+1, tid, pa, pb);
        #pragma unroll
        for (int kk = 0; kk < 2; kk++){
            int k0 = kk*16;
            unsigned a[4];
            ldsm4(a, ab + ((wm*16 + lrow)*AS_H + k0 + lcol8)*2);
            #pragma unroll
            for (int j = 0; j < 4; j++){
                unsigned bv[4];
                ldsm4t(bv, bb + ((k0 + lrow)*BS_H + wn*64 + j*16 + lcol8)*2);
                unsigned b0[2] = {bv[0], bv[1]};
                unsigned b1[2] = {bv[2], bv[3]};
                mma16(acc[2*j],   a, b0);
                mma16(acc[2*j+1], a, b1);
            }
        }
        if (kc + 1 < KC)
            sstore_h(smh + ((kc+1) & 1)*BUF_H, tid, pa, pb);
        __syncthreads();
    }

    if (EPI == EPI_H16){
        __half* C = (__half*)Cv;
        int rl = row0 + wm*16 + g4;
        #pragma unroll
        for (int nt = 0; nt < 8; nt++){
            int col = n0 + wn*64 + nt*8 + 2*tig;
            *(unsigned*)(C + rl*ldc + col)     = h2pk(acc[nt][0], acc[nt][1]);
            *(unsigned*)(C + (rl+8)*ldc + col) = h2pk(acc[nt][2], acc[nt][3]);
        }
    } else if (EPI == EPI_NONE || EPI == EPI_RELU){
        float* C = (float*)Cv;
        int rl = row0 + wm*16 + g4;
        #pragma unroll
        for (int nt = 0; nt < 8; nt++){
            int col = n0 + wn*64 + nt*8 + 2*tig;
            float v0 = acc[nt][0], v1 = acc[nt][1];
            float v2 = acc[nt][2], v3 = acc[nt][3];
            if (EPI == EPI_RELU){
                v0=fmaxf(v0,0.f); v1=fmaxf(v1,0.f); v2=fmaxf(v2,0.f); v3=fmaxf(v3,0.f);
            }
            *(float2*)(C + rl*ldc + col)     = make_float2(v0, v1);
            *(float2*)(C + (rl+8)*ldc + col) = make_float2(v2, v3);
        }
    } else {
        float* C = (float*)Cv;
        float2* red = (float2*)smraw;
        float s1[2] = {0,0}, s2[2] = {0,0};
        #pragma unroll
        for (int nt = 0; nt < 8; nt++){
            float c0=acc[nt][0], c1=acc[nt][1], c2=acc[nt][2], c3=acc[nt][3];
            s1[0] += c0+c1; s2[0] += c0*c0 + c1*c1;
            s1[1] += c2+c3; s2[1] += c2*c2 + c3*c3;
        }
        #pragma unroll
        for (int hb = 0; hb < 2; hb++){
            float v1 = s1[hb], v2 = s2[hb];
            v1 += __shfl_xor_sync(~0u, v1, 1); v1 += __shfl_xor_sync(~0u, v1, 2);
            v2 += __shfl_xor_sync(~0u, v2, 1); v2 += __shfl_xor_sync(~0u, v2, 2);
            if (tig == 0){
                int r = wm*16 + g4 + hb*8;
                red[r*4 + wn] = make_float2(v1, v2);
            }
        }
        __syncthreads();
        #pragma unroll
        for (int hb = 0; hb < 2; hb++){
            int r = wm*16 + g4 + hb*8;
            float S1 = 0.f, S2 = 0.f;
            #pragma unroll
            for (int j = 0; j < 4; j++){ float2 e = red[r*4+j]; S1 += e.x; S2 += e.y; }
            float mean = S1 * (1.f/256.f);
            float var  = S2 * (1.f/256.f) - mean*mean;
            float inv  = rsqrtf(var + 1e-5f);
            int grow = row0 + r;
            #pragma unroll
            for (int nt = 0; nt < 8; nt++){
                int col = wn*64 + nt*8 + 2*tig;
                float c0 = acc[nt][hb*2], c1 = acc[nt][hb*2+1];
                float o0 = (c0 - mean)*inv*gamma[col]   + beta[col];
                float o1 = (c1 - mean)*inv*gamma[col+1] + beta[col+1];
                if (EPI == EPI_LNR){
                    o0 += resid[grow*256 + col];
                    o1 += resid[grow*256 + col + 1];
                }
                *(float2*)(C + grow*ldc + col) = make_float2(o0, o1);
            }
        }
    }
}

__global__ void __launch_bounds__(256) k_qkv(
    const float* x, const float* xpe, const float* src, const float* spe,
    const float* Wq, const float* Wk, const float* Wv)
{
    if (blockIdx.z == 0)      gemm_body<256, AM_ADD,   EPI_H16>(x,   xpe, Wq, 256, 0, 0,0,0, g_Qh, 256);
    else if (blockIdx.z == 1) gemm_body<256, AM_ADD,   EPI_H16>(src, spe, Wk, 256, 0, 0,0,0, g_Kh, 256);
    else                      gemm_body<256, AM_PLAIN, EPI_H16>(src, 0,   Wv, 256, 0, 0,0,0, g_Vh, 256);
}
__global__ void __launch_bounds__(256) k_merge(const float* Wmg, const float* gg, const float* bb){
    gemm_body<256, AM_MERGE, EPI_LN>(0, 0, Wmg, 256, 0, gg, bb, 0, g_msg, 256);
}
__global__ void __launch_bounds__(256) k_mlp1(const float* x, const float* Wm1){
    gemm_body<512, AM_CAT, EPI_RELU>(x, g_msg, Wm1, 512, blockIdx.y*256, 0,0,0, g_hid, 512);
}
__global__ void __launch_bounds__(256) k_mlp2(const float* Wm2, const float* gg, const float* bb,
                                              const float* x, float* out){
    gemm_body<512, AM_PLAIN, EPI_LNR>(g_hid, 0, Wm2, 256, 0, gg, bb, x, out, 256);
}

// ---------------------------------------------------------------------------
// Flash attention v7: R8 structure + cp.async DOUBLE-BUFFERED K/V/comp/mask.
// One __syncthreads per tile; P in its own region; Q pre-scaled by 1/8 (exact).
// CTA = (32 l, split, b); warp = (h=w&3, wm=w>>2).
// ---------------------------------------------------------------------------
#define QH 264
#define PH 40
#define CS_STR 36
// half offsets
#define AT_K   8448               // K buffers: +buf*8448
#define AT_V   25344              // V buffers: +buf*8448
#define AT_P   42240              // P: 4 heads x 1280
// byte offsets
#define AT_CB  94720              // Cs: 2 x 1152 floats
#define AT_SMS 103936             // sms: 2 x 32 ints
#define AT_XM  104192             // xm: 32 ints
#define ATTN_BYTES 104320

__device__ __forceinline__ void attn_issue_tile(
    const __half* __restrict__ Km, const __half* __restrict__ Vm,
    const float* __restrict__ comp, const int* __restrict__ smask,
    unsigned sb, int buf, int b, int l0, int s0, int tid)
{
    unsigned kdst = sb + (AT_K + buf*8448)*2;
    unsigned vdst = sb + (AT_V + buf*8448)*2;
    #pragma unroll
    for (int i = 0; i < 4; i++){
        int id = tid + i*256;
        int r = id >> 5, c8 = (id & 31) << 3;
        long grow = (long)(b*LQ + s0 + r)*256 + c8;
        cpa16(kdst + (r*QH + c8)*2, Km + grow);
        cpa16(vdst + (r*QH + c8)*2, Vm + grow);
    }
    {
        int r = tid >> 3, c4 = (tid & 7) << 2;
        unsigned cdst = sb + AT_CB + buf*1152*4 + (r*CS_STR + c4)*4;
        cpa16(cdst, comp + (long)(b*LQ + l0 + r)*LQ + s0 + c4);
    }
    if (tid < 32)
        cpa4(sb + AT_SMS + buf*128 + tid*4, smask + b*LQ + s0 + tid);
}

__global__ void __launch_bounds__(256, 2) k_attn(
    const __half* __restrict__ Qm, const __half* __restrict__ Km, const __half* __restrict__ Vm,
    const float* __restrict__ comp, const int* __restrict__ xmask, const int* __restrict__ smask)
{
    extern __shared__ unsigned char smraw[];
    __half* smh = (__half*)smraw;
    __half* Qh = smh;
    float*  CsBase = (float*)(smraw + AT_CB);
    int*    smsBase = (int*)(smraw + AT_SMS);
    int*    xm = (int*)(smraw + AT_XM);

    int tid = threadIdx.x;
    int w = tid >> 5, lane = tid & 31;
    int h = w & 3, wm = w >> 2;
    int g4 = lane >> 2, tig = lane & 3;
    int lrow = (lane & 7) + ((lane >> 3) & 1)*8;
    int lcol8 = (lane >> 4)*8;
    int l0 = blockIdx.x * 32;
    int sp = blockIdx.y, b = blockIdx.z;
    int dbase = h*64;

    unsigned sb = (unsigned)__cvta_generic_to_shared(smh);
    unsigned qb = sb;
    unsigned pbsu = sb + (AT_P + h*1280)*2;
    __half* Ph = smh + AT_P + h*1280;

    // prefetch tile 0
    int sbase = sp*(LQ/SPLITS);
    attn_issue_tile(Km, Vm, comp, smask, sb, 0, b, l0, sbase, tid);
    CPA_COMMIT();

    // stage Q (32x256 halves), pre-scaled by 0.125 (exact exponent shift)
    {
        __half2 sc = __half2half2(__float2half(0.125f));
        #pragma unroll
        for (int i = 0; i < 4; i++){
            int id = tid + i*256;
            int r = id >> 5, c8 = (id & 31) << 3;
            uint4 v = *(const uint4*)(Qm + (b*LQ + l0 + r)*256 + c8);
            __half2* ph = (__half2*)&v;
            ph[0] = __hmul2(ph[0], sc); ph[1] = __hmul2(ph[1], sc);
            ph[2] = __hmul2(ph[2], sc); ph[3] = __hmul2(ph[3], sc);
            *(uint4*)&Qh[r*QH + c8] = v;
        }
    }
    if (tid < 32) xm[tid] = xmask[b*LQ + l0 + tid];

    float o[8][4];
    #pragma unroll
    for (int nt = 0; nt < 8; nt++)
        #pragma unroll
        for (int i = 0; i < 4; i++) o[nt][i] = 0.f;
    float rmax[2] = {-1e30f, -1e30f};
    float rsum[2] = {0.f, 0.f};

    CPA_WAIT0();
    __syncthreads();

    int rl = wm*16 + g4;
    const int NT = (LQ/SPLITS)/32;
    for (int t = 0; t < NT; t++){
        int buf = t & 1;
        unsigned kb = sb + (AT_K + buf*8448)*2;
        unsigned vb = sb + (AT_V + buf*8448)*2;
        float* Cs = CsBase + buf*1152;
        int*   sms = smsBase + buf*32;

        // prefetch next tile into the other buffer
        if (t + 1 < NT){
            attn_issue_tile(Km, Vm, comp, smask, sb, buf^1, b, l0, sbase + (t+1)*32, tid);
            CPA_COMMIT();
        }

        // ---- QK^T: S[16l x 32s] per warp ----
        float S[4][4];
        #pragma unroll
        for (int nt = 0; nt < 4; nt++)
            #pragma unroll
            for (int i = 0; i < 4; i++) S[nt][i] = 0.f;
        #pragma unroll
        for (int kk = 0; kk < 4; kk++){
            int k0 = dbase + kk*16;
            unsigned a[4];
            ldsm4(a, qb + ((wm*16 + lrow)*QH + k0 + lcol8)*2);
            #pragma unroll
            for (int sh = 0; sh < 2; sh++){
                unsigned bk[4];
                ldsm4(bk, kb + ((sh*16 + lrow)*QH + k0 + lcol8)*2);
                unsigned b0[2] = {bk[0], bk[2]};
                unsigned b1[2] = {bk[1], bk[3]};
                mma16(S[sh*2],   a, b0);
                mma16(S[sh*2+1], a, b1);
            }
        }

        // ---- softmax (warp-local rows; Q pre-scaled so S already has 1/8) ----
        int xml = xm[rl], xmh = xm[rl + 8];
        float tmaxl = -1e30f, tmaxh = -1e30f;
        #pragma unroll
        for (int nt = 0; nt < 4; nt++){
            int se = nt*8 + 2*tig, so = se + 1;
            int mse = sms[se], mso = sms[so];
            float ce = Cs[rl*CS_STR + se],      co = Cs[rl*CS_STR + so];
            float de = Cs[(rl+8)*CS_STR + se],  dox = Cs[(rl+8)*CS_STR + so];
            float v0 = (xml && !mse) ? -1e30f : S[nt][0]*ce;
            float v1 = (xml && !mso) ? -1e30f : S[nt][1]*co;
            float v2 = (xmh && !mse) ? -1e30f : S[nt][2]*de;
            float v3 = (xmh && !mso) ? -1e30f : S[nt][3]*dox;
            S[nt][0]=v0; S[nt][1]=v1; S[nt][2]=v2; S[nt][3]=v3;
            tmaxl = fmaxf(tmaxl, fmaxf(v0, v1));
            tmaxh = fmaxf(tmaxh, fmaxf(v2, v3));
        }
        tmaxl = fmaxf(tmaxl, __shfl_xor_sync(~0u, tmaxl, 1));
        tmaxl = fmaxf(tmaxl, __shfl_xor_sync(~0u, tmaxl, 2));
        tmaxh = fmaxf(tmaxh, __shfl_xor_sync(~0u, tmaxh, 1));
        tmaxh = fmaxf(tmaxh, __shfl_xor_sync(~0u, tmaxh, 2));
        float ml = fmaxf(rmax[0], tmaxl), mh = fmaxf(rmax[1], tmaxh);
        float al = fast_exp(rmax[0] - ml), ah = fast_exp(rmax[1] - mh);
        rmax[0] = ml; rmax[1] = mh;
        float tsl = 0.f, tsh = 0.f;
        #pragma unroll
        for (int nt = 0; nt < 4; nt++){
            float p0 = fast_exp(S[nt][0] - ml);
            float p1 = fast_exp(S[nt][1] - ml);
            float p2 = fast_exp(S[nt][2] - mh);
            float p3 = fast_exp(S[nt][3] - mh);
            tsl += p0 + p1; tsh += p2 + p3;
            int se = nt*8 + 2*tig;
            *(unsigned*)&Ph[rl*PH + se]     = h2pk(p0, p1);
            *(unsigned*)&Ph[(rl+8)*PH + se] = h2pk(p2, p3);
        }
        tsl += __shfl_xor_sync(~0u, tsl, 1); tsl += __shfl_xor_sync(~0u, tsl, 2);
        tsh += __shfl_xor_sync(~0u, tsh, 1); tsh += __shfl_xor_sync(~0u, tsh, 2);
        rsum[0] = rsum[0]*al + tsl;
        rsum[1] = rsum[1]*ah + tsh;
        #pragma unroll
        for (int nt = 0; nt < 8; nt++){
            o[nt][0] *= al; o[nt][1] *= al;
            o[nt][2] *= ah; o[nt][3] *= ah;
        }
        __syncwarp();        // P producer == consumer rows (same warp)

        // ---- P @ V: o[16l x 64d] ----
        #pragma unroll
        for (int kk = 0; kk < 2; kk++){
            unsigned a[4];
            ldsm4(a, pbsu + ((wm*16 + lrow)*PH + kk*16 + lcol8)*2);
            #pragma unroll
            for (int j = 0; j < 4; j++){
                unsigned bv[4];
                ldsm4t(bv, vb + ((kk*16 + lrow)*QH + dbase + j*16 + lcol8)*2);
                unsigned b0[2] = {bv[0], bv[1]};
                unsigned b1[2] = {bv[2], bv[3]};
                mma16(o[2*j],   a, b0);
                mma16(o[2*j+1], a, b1);
            }
        }

        // wait for prefetch, make visible to all warps
        if (t + 1 < NT){
            CPA_WAIT0();
            __syncthreads();
        }
    }

    // ---- write unnormalized partials + stats ----
    long prow = (long)(sp*MROWS + b*LQ + l0 + rl);
    #pragma unroll
    for (int nt = 0; nt < 8; nt++){
        int col = dbase + nt*8 + 2*tig;
        *(float2*)(g_part + prow*256 + col)     = make_float2(o[nt][0], o[nt][1]);
        *(float2*)(g_part + (prow+8)*256 + col) = make_float2(o[nt][2], o[nt][3]);
    }
    if (tig == 0){
        long base = (prow*4 + h)*2;
        g_pstat[base]   = rmax[0];
        g_pstat[base+1] = rsum[0];
        long baseh = ((prow+8)*4 + h)*2;
        g_pstat[baseh]   = rmax[1];
        g_pstat[baseh+1] = rsum[1];
    }
}

// ---------------------------------------------------------------------------
extern "C" void kernel_launch(void* const* d_in, const int* in_sizes, int n_in,
                              void* d_out, int out_size)
{
    const float* x    = (const float*)d_in[0];
    const float* src  = (const float*)d_in[1];
    const float* xpe  = (const float*)d_in[2];
    const float* spe  = (const float*)d_in[3];
    const int* xmask  = (const int*)d_in[4];
    const int* smask  = (const int*)d_in[5];
    const float* comp = (const float*)d_in[6];
    const float* Wq   = (const float*)d_in[7];
    const float* Wk   = (const float*)d_in[8];
    const float* Wv   = (const float*)d_in[9];
    const float* Wmg  = (const float*)d_in[10];
    const float* Wm1  = (const float*)d_in[11];
    const float* Wm2  = (const float*)d_in[12];
    const float* ln1g = (const float*)d_in[13];
    const float* ln1b = (const float*)d_in[14];
    const float* ln2g = (const float*)d_in[15];
    const float* ln2b = (const float*)d_in[16];
    float* out = (float*)d_out;

    __half *Qp, *Kp, *Vp;
    cudaGetSymbolAddress((void**)&Qp, g_Qh);
    cudaGetSymbolAddress((void**)&Kp, g_Kh);
    cudaGetSymbolAddress((void**)&Vp, g_Vh);

    cudaFuncSetAttribute(k_attn, cudaFuncAttributeMaxDynamicSharedMemorySize, ATTN_BYTES);

    k_qkv <<<dim3(MROWS/32, 1, 3), 256, SM_GEMM>>>(x, xpe, src, spe, Wq, Wk, Wv);
    k_attn<<<dim3(LQ/32, SPLITS, BSZ), 256, ATTN_BYTES>>>(Qp, Kp, Vp, comp, xmask, smask);
    k_merge<<<MROWS/32,            256, SM_GEMM>>>(Wmg, ln1g, ln1b);
    k_mlp1<<<dim3(MROWS/32, 2),    256, SM_GEMM>>>(x, Wm1);
    k_mlp2<<<MROWS/32,             256, SM_GEMM>>>(Wm2, ln2g, ln2b, x, out);
}

// round 11
// speedup vs baseline: 1.4218x; 1.0581x over previous
#include <cuda_runtime.h>
#include <cuda_fp16.h>
#include <cstdint>

#define BSZ 2
#define LQ 2048
#define DM 256
#define MROWS (BSZ*LQ)
#define SPLITS 2

// scratch
__device__ __half g_Qh[MROWS*DM];
__device__ __half g_Kh[MROWS*DM];
__device__ __half g_Vh[MROWS*DM];
__device__ __half g_xs[MROWS*DM];     // x + xpe
__device__ __half g_ss[MROWS*DM];     // src + spe
__device__ __half g_sv[MROWS*DM];     // src
__device__ __half g_xp[MROWS*DM];     // x
__device__ __half g_msgh[MROWS*DM];
__device__ __half g_hidh[MROWS*2*DM];
__device__ __half g_Wqh[DM*DM];
__device__ __half g_Wkh[DM*DM];
__device__ __half g_Wvh[DM*DM];
__device__ __half g_Wm1h[2*DM*2*DM];
__device__ __half g_Wm2h[2*DM*DM];
__device__ float g_part[SPLITS*MROWS*DM];
__device__ float g_pstat[SPLITS*MROWS*4*2];

// ---------------------------------------------------------------------------
__device__ __forceinline__ unsigned h2pk(float lo, float hi){
    unsigned r; asm("cvt.rn.f16x2.f32 %0, %1, %2;" : "=r"(r) : "f"(hi), "f"(lo)); return r;
}
__device__ __forceinline__ void ldsm4(unsigned* r, unsigned a){
    asm volatile("ldmatrix.sync.aligned.m8n8.x4.shared.b16 {%0,%1,%2,%3},[%4];"
        : "=r"(r[0]),"=r"(r[1]),"=r"(r[2]),"=r"(r[3]) : "r"(a));
}
__device__ __forceinline__ void ldsm4t(unsigned* r, unsigned a){
    asm volatile("ldmatrix.sync.aligned.m8n8.x4.trans.shared.b16 {%0,%1,%2,%3},[%4];"
        : "=r"(r[0]),"=r"(r[1]),"=r"(r[2]),"=r"(r[3]) : "r"(a));
}
__device__ __forceinline__ void mma16(float* c, const unsigned* a, const unsigned* b){
    asm volatile("mma.sync.aligned.m16n8k16.row.col.f32.f16.f16.f32 "
        "{%0,%1,%2,%3},{%4,%5,%6,%7},{%8,%9},{%0,%1,%2,%3};"
        : "+f"(c[0]), "+f"(c[1]), "+f"(c[2]), "+f"(c[3])
        : "r"(a[0]), "r"(a[1]), "r"(a[2]), "r"(a[3]), "r"(b[0]), "r"(b[1]));
}
__device__ __forceinline__ void cpa16(unsigned dst, const void* src){
    asm volatile("cp.async.cg.shared.global [%0], [%1], 16;" :: "r"(dst), "l"(src));
}
__device__ __forceinline__ void cpa4(unsigned dst, const void* src){
    asm volatile("cp.async.ca.shared.global [%0], [%1], 4;" :: "r"(dst), "l"(src));
}
#define CPA_COMMIT() asm volatile("cp.async.commit_group;" ::: "memory")
#define CPA_WAIT0()  asm volatile("cp.async.wait_group 0;" ::: "memory")

// e^x for x <= 0, FMA-pipe only. rel err ~2e-6.
__device__ __forceinline__ float fast_exp(float x){
    float y = x * 1.44269504f;
    y = fmaxf(y, -126.0f);
    float z = y + 12582912.0f;
    int   n = __float_as_int(z) - 0x4B400000;
    float f = y - (z - 12582912.0f);
    float p = 1.33336e-3f;
    p = fmaf(p, f, 9.61813e-3f);
    p = fmaf(p, f, 5.55041e-2f);
    p = fmaf(p, f, 2.40227e-1f);
    p = fmaf(p, f, 6.93147e-1f);
    p = fmaf(p, f, 1.0f);
    return p * __int_as_float((n + 127) << 23);
}

// ---------------------------------------------------------------------------
// prep: convert A-matrices and weights to fp16 once. float4-vectorized.
// ---------------------------------------------------------------------------
#define P_S0 262144L   // xs  (x+xpe)
#define P_S1 524288L   // ss  (src+spe)
#define P_S2 786432L   // sv  (src)
#define P_S3 1048576L  // xp  (x)
#define P_S4 1064960L  // Wq
#define P_S5 1081344L  // Wk
#define P_S6 1097728L  // Wv
#define P_S7 1163264L  // Wm1
#define P_S8 1196032L  // Wm2 end
#define PREP_GRID ((P_S8 + 255) / 256)

__global__ void __launch_bounds__(256) k_prep(
    const float* x, const float* xpe, const float* src, const float* spe,
    const float* Wq, const float* Wk, const float* Wv,
    const float* Wm1, const float* Wm2)
{
    long i = (long)blockIdx.x*256 + threadIdx.x;
    if (i >= P_S8) return;
    float4 v; __half* dst;
    if (i < P_S0){
        float4 a = ((const float4*)x)[i], b = ((const float4*)xpe)[i];
        v = make_float4(a.x+b.x, a.y+b.y, a.z+b.z, a.w+b.w); dst = g_xs + i*4;
    } else if (i < P_S1){
        long j = i - P_S0;
        float4 a = ((const float4*)src)[j], b = ((const float4*)spe)[j];
        v = make_float4(a.x+b.x, a.y+b.y, a.z+b.z, a.w+b.w); dst = g_ss + j*4;
    } else if (i < P_S2){
        long j = i - P_S1; v = ((const float4*)src)[j]; dst = g_sv + j*4;
    } else if (i < P_S3){
        long j = i - P_S2; v = ((const float4*)x)[j]; dst = g_xp + j*4;
    } else if (i < P_S4){
        long j = i - P_S3; v = ((const float4*)Wq)[j]; dst = g_Wqh + j*4;
    } else if (i < P_S5){
        long j = i - P_S4; v = ((const float4*)Wk)[j]; dst = g_Wkh + j*4;
    } else if (i < P_S6){
        long j = i - P_S5; v = ((const float4*)Wv)[j]; dst = g_Wvh + j*4;
    } else if (i < P_S7){
        long j = i - P_S6; v = ((const float4*)Wm1)[j]; dst = g_Wm1h + j*4;
    } else {
        long j = i - P_S7; v = ((const float4*)Wm2)[j]; dst = g_Wm2h + j*4;
    }
    *(uint2*)dst = make_uint2(h2pk(v.x, v.y), h2pk(v.z, v.w));
}

// ---------------------------------------------------------------------------
// all-fp16 GEMM: BM=32, BN=256, BK=32, 256 threads, cp.async double-buffered.
// ---------------------------------------------------------------------------
#define EPI_RELU 1
#define EPI_LNR  3
#define EPI_H16  4

#define AS_H 40
#define BS_H 264
#define BUF_H (32*AS_H + 32*BS_H)    // 9088 halves
#define SM_GEMM (2*BUF_H*2)          // 36352 bytes

template<int KD, bool CAT, int EPI>
__device__ __forceinline__ void gemm_h(
    const __half* __restrict__ A1, const __half* __restrict__ A2,
    const __half* __restrict__ Bw, int ldb, int n0,
    const float* __restrict__ gamma, const float* __restrict__ beta,
    const float* __restrict__ resid, void* __restrict__ Cv, int ldc)
{
    extern __shared__ unsigned char smraw[];
    const int KC = KD/32;
    int tid = threadIdx.x;
    int w = tid >> 5, lane = tid & 31;
    int wm = w >> 2, wn = w & 3;
    int g4 = lane >> 2, tig = lane & 3;
    int lrow = (lane & 7) + ((lane >> 3) & 1)*8;
    int lcol8 = (lane >> 4)*8;
    int row0 = blockIdx.x * 32;
    unsigned sb = (unsigned)__cvta_generic_to_shared(smraw);

    float acc[8][4];
    #pragma unroll
    for (int nt = 0; nt < 8; nt++)
        #pragma unroll
        for (int i = 0; i < 4; i++) acc[nt][i] = 0.f;

    // cp.async issue of K-chunk kc into buffer kc&1
    auto issue = [&](int kc){
        unsigned ab = sb + ((kc & 1)*BUF_H)*2;
        unsigned bb = ab + 32*AS_H*2;
        if (tid < 128){
            int r = tid >> 2, c8 = (tid & 3) << 3;
            int col = kc*32 + c8;
            const __half* s;
            if (CAT) s = (col < 256) ? (A1 + (row0+r)*256 + col)
                                     : (A2 + (row0+r)*256 + (col - 256));
            else     s = A1 + (row0+r)*KD + col;
            cpa16(ab + (r*AS_H + c8)*2, s);
        }
        #pragma unroll
        for (int i = 0; i < 4; i++){
            int id = tid + i*256;
            int r = id >> 5, c8 = (id & 31) << 3;
            cpa16(bb + (r*BS_H + c8)*2, Bw + (kc*32 + r)*ldb + n0 + c8);
        }
    };

    issue(0); CPA_COMMIT();
    CPA_WAIT0(); __syncthreads();

    for (int kc = 0; kc < KC; kc++){
        if (kc + 1 < KC){ issue(kc+1); CPA_COMMIT(); }
        unsigned ab = sb + ((kc & 1)*BUF_H)*2;
        unsigned bb = ab + 32*AS_H*2;
        #pragma unroll
        for (int kk = 0; kk < 2; kk++){
            int k0 = kk*16;
            unsigned a[4];
            ldsm4(a, ab + ((wm*16 + lrow)*AS_H + k0 + lcol8)*2);
            #pragma unroll
            for (int j = 0; j < 4; j++){
                unsigned bv[4];
                ldsm4t(bv, bb + ((k0 + lrow)*BS_H + wn*64 + j*16 + lcol8)*2);
                unsigned b0[2] = {bv[0], bv[1]};
                unsigned b1[2] = {bv[2], bv[3]};
                mma16(acc[2*j],   a, b0);
                mma16(acc[2*j+1], a, b1);
            }
        }
        if (kc + 1 < KC){ CPA_WAIT0(); __syncthreads(); }
    }

    if (EPI == EPI_H16 || EPI == EPI_RELU){
        __half* C = (__half*)Cv;
        int rl = row0 + wm*16 + g4;
        #pragma unroll
        for (int nt = 0; nt < 8; nt++){
            int col = n0 + wn*64 + nt*8 + 2*tig;
            float v0 = acc[nt][0], v1 = acc[nt][1];
            float v2 = acc[nt][2], v3 = acc[nt][3];
            if (EPI == EPI_RELU){
                v0=fmaxf(v0,0.f); v1=fmaxf(v1,0.f); v2=fmaxf(v2,0.f); v3=fmaxf(v3,0.f);
            }
            *(unsigned*)(C + rl*ldc + col)     = h2pk(v0, v1);
            *(unsigned*)(C + (rl+8)*ldc + col) = h2pk(v2, v3);
        }
    } else {   // EPI_LNR: LayerNorm + residual, fp32 out
        float* C = (float*)Cv;
        __syncthreads();                 // smem free after last mma (all warps)
        float2* red = (float2*)smraw;    // red[32][4]
        float s1[2] = {0,0}, s2[2] = {0,0};
        #pragma unroll
        for (int nt = 0; nt < 8; nt++){
            float c0=acc[nt][0], c1=acc[nt][1], c2=acc[nt][2], c3=acc[nt][3];
            s1[0] += c0+c1; s2[0] += c0*c0 + c1*c1;
            s1[1] += c2+c3; s2[1] += c2*c2 + c3*c3;
        }
        #pragma unroll
        for (int hb = 0; hb < 2; hb++){
            float v1 = s1[hb], v2 = s2[hb];
            v1 += __shfl_xor_sync(~0u, v1, 1); v1 += __shfl_xor_sync(~0u, v1, 2);
            v2 += __shfl_xor_sync(~0u, v2, 1); v2 += __shfl_xor_sync(~0u, v2, 2);
            if (tig == 0){
                int r = wm*16 + g4 + hb*8;
                red[r*4 + wn] = make_float2(v1, v2);
            }
        }
        __syncthreads();
        #pragma unroll
        for (int hb = 0; hb < 2; hb++){
            int r = wm*16 + g4 + hb*8;
            float S1 = 0.f, S2 = 0.f;
            #pragma unroll
            for (int j = 0; j < 4; j++){ float2 e = red[r*4+j]; S1 += e.x; S2 += e.y; }
            float mean = S1 * (1.f/256.f);
            float var  = S2 * (1.f/256.f) - mean*mean;
            float inv  = rsqrtf(var + 1e-5f);
            int grow = row0 + r;
            #pragma unroll
            for (int nt = 0; nt < 8; nt++){
                int col = wn*64 + nt*8 + 2*tig;
                float c0 = acc[nt][hb*2], c1 = acc[nt][hb*2+1];
                float o0 = (c0 - mean)*inv*gamma[col]   + beta[col] + resid[grow*256 + col];
                float o1 = (c1 - mean)*inv*gamma[col+1] + beta[col+1] + resid[grow*256 + col + 1];
                *(float2*)(C + grow*ldc + col) = make_float2(o0, o1);
            }
        }
    }
}

__global__ void __launch_bounds__(256) k_qkv(){
    if (blockIdx.z == 0)      gemm_h<256, false, EPI_H16>(g_xs, 0, g_Wqh, 256, 0, 0,0,0, g_Qh, 256);
    else if (blockIdx.z == 1) gemm_h<256, false, EPI_H16>(g_ss, 0, g_Wkh, 256, 0, 0,0,0, g_Kh, 256);
    else                      gemm_h<256, false, EPI_H16>(g_sv, 0, g_Wvh, 256, 0, 0,0,0, g_Vh, 256);
}
__global__ void __launch_bounds__(256) k_mlp1(){
    gemm_h<512, true, EPI_RELU>(g_xp, g_msgh, g_Wm1h, 512, blockIdx.y*256, 0,0,0, g_hidh, 512);
}
__global__ void __launch_bounds__(256) k_mlp2(const float* gg, const float* bb,
                                              const float* x, float* out){
    gemm_h<512, false, EPI_LNR>(g_hidh, 0, g_Wm2h, 256, 0, gg, bb, x, out, 256);
}

// ---------------------------------------------------------------------------
// k_merge: fp32 body (R10 proven): A = merged split-KV partials, B = Wmg fp32,
// LN epilogue -> fp16 g_msgh.
// ---------------------------------------------------------------------------
#define MAS_H 40
#define MBS_H 264
#define MBUF_H (32*MAS_H + 32*MBS_H)
#define SM_MERGE (2*MBUF_H*2)

__global__ void __launch_bounds__(256) k_merge(const float* __restrict__ Wmg,
                                               const float* __restrict__ gamma,
                                               const float* __restrict__ beta)
{
    extern __shared__ unsigned char smraw[];
    __half* smh = (__half*)smraw;
    int tid = threadIdx.x;
    int w = tid >> 5, lane = tid & 31;
    int wm = w >> 2, wn = w & 3;
    int g4 = lane >> 2, tig = lane & 3;
    int lrow = (lane & 7) + ((lane >> 3) & 1)*8;
    int lcol8 = (lane >> 4)*8;
    int row0 = blockIdx.x * 32;
    unsigned sb = (unsigned)__cvta_generic_to_shared(smh);

    float acc[8][4];
    #pragma unroll
    for (int nt = 0; nt < 8; nt++)
        #pragma unroll
        for (int i = 0; i < 4; i++) acc[nt][i] = 0.f;

    float4 pa, pb[8];
    auto gload = [&](int kc){
        int ar = tid >> 3, ac4 = (tid & 7) << 2;
        int col = kc*32 + ac4;
        long r0 = row0 + ar;
        int hh = kc >> 1;
        float m0 = g_pstat[((0L*MROWS + r0)*4 + hh)*2];
        float s0 = g_pstat[((0L*MROWS + r0)*4 + hh)*2 + 1];
        float m1 = g_pstat[((1L*MROWS + r0)*4 + hh)*2];
        float s1 = g_pstat[((1L*MROWS + r0)*4 + hh)*2 + 1];
        float M = fmaxf(m0, m1);
        float w0 = fast_exp(m0 - M), w1 = fast_exp(m1 - M);
        float inv = 1.0f/(s0*w0 + s1*w1);
        w0 *= inv; w1 *= inv;
        float4 p0 = *(const float4*)(g_part + (0L*MROWS + r0)*256 + col);
        float4 p1 = *(const float4*)(g_part + (1L*MROWS + r0)*256 + col);
        pa = make_float4(p0.x*w0 + p1.x*w1, p0.y*w0 + p1.y*w1,
                         p0.z*w0 + p1.z*w1, p0.w*w0 + p1.w*w1);
        #pragma unroll
        for (int i = 0; i < 8; i++){
            int id = tid + i*256;
            int r = id >> 6, c4 = (id & 63) << 2;
            pb[i] = *(const float4*)(Wmg + (kc*32 + r)*256 + c4);
        }
    };
    auto sstore = [&](int buf){
        __half* Ab = smh + buf*MBUF_H;
        __half* Bb = Ab + 32*MAS_H;
        int ar = tid >> 3, ac4 = (tid & 7) << 2;
        *(uint2*)&Ab[ar*MAS_H + ac4] = make_uint2(h2pk(pa.x, pa.y), h2pk(pa.z, pa.w));
        #pragma unroll
        for (int i = 0; i < 8; i++){
            int id = tid + i*256;
            int r = id >> 6, c4 = (id & 63) << 2;
            *(uint2*)&Bb[r*MBS_H + c4] = make_uint2(h2pk(pb[i].x, pb[i].y), h2pk(pb[i].z, pb[i].w));
        }
    };

    gload(0); sstore(0);
    __syncthreads();
    for (int kc = 0; kc < 8; kc++){
        unsigned ab = sb + ((kc & 1)*MBUF_H)*2;
        unsigned bb = ab + 32*MAS_H*2;
        if (kc + 1 < 8) gload(kc+1);
        #pragma unroll
        for (int kk = 0; kk < 2; kk++){
            int k0 = kk*16;
            unsigned a[4];
            ldsm4(a, ab + ((wm*16 + lrow)*MAS_H + k0 + lcol8)*2);
            #pragma unroll
            for (int j = 0; j < 4; j++){
                unsigned bv[4];
                ldsm4t(bv, bb + ((k0 + lrow)*MBS_H + wn*64 + j*16 + lcol8)*2);
                unsigned b0[2] = {bv[0], bv[1]};
                unsigned b1[2] = {bv[2], bv[3]};
                mma16(acc[2*j],   a, b0);
                mma16(acc[2*j+1], a, b1);
            }
        }
        if (kc + 1 < 8) sstore((kc+1) & 1);
        __syncthreads();
    }

    // LN epilogue -> fp16 g_msgh
    float2* red = (float2*)smraw;
    float s1[2] = {0,0}, s2[2] = {0,0};
    #pragma unroll
    for (int nt = 0; nt < 8; nt++){
        float c0=acc[nt][0], c1=acc[nt][1], c2=acc[nt][2], c3=acc[nt][3];
        s1[0] += c0+c1; s2[0] += c0*c0 + c1*c1;
        s1[1] += c2+c3; s2[1] += c2*c2 + c3*c3;
    }
    #pragma unroll
    for (int hb = 0; hb < 2; hb++){
        float v1 = s1[hb], v2 = s2[hb];
        v1 += __shfl_xor_sync(~0u, v1, 1); v1 += __shfl_xor_sync(~0u, v1, 2);
        v2 += __shfl_xor_sync(~0u, v2, 1); v2 += __shfl_xor_sync(~0u, v2, 2);
        if (tig == 0){
            int r = wm*16 + g4 + hb*8;
            red[r*4 + wn] = make_float2(v1, v2);
        }
    }
    __syncthreads();
    #pragma unroll
    for (int hb = 0; hb < 2; hb++){
        int r = wm*16 + g4 + hb*8;
        float S1 = 0.f, S2 = 0.f;
        #pragma unroll
        for (int j = 0; j < 4; j++){ float2 e = red[r*4+j]; S1 += e.x; S2 += e.y; }
        float mean = S1 * (1.f/256.f);
        float var  = S2 * (1.f/256.f) - mean*mean;
        float inv  = rsqrtf(var + 1e-5f);
        int grow = row0 + r;
        #pragma unroll
        for (int nt = 0; nt < 8; nt++){
            int col = wn*64 + nt*8 + 2*tig;
            float c0 = acc[nt][hb*2], c1 = acc[nt][hb*2+1];
            float o0 = (c0 - mean)*inv*gamma[col]   + beta[col];
            float o1 = (c1 - mean)*inv*gamma[col+1] + beta[col+1];
            *(unsigned*)(g_msgh + grow*256 + col) = h2pk(o0, o1);
        }
    }
}

// ---------------------------------------------------------------------------
// Flash attention v7 (R10 proven): cp.async double-buffered K/V/comp/mask.
// ---------------------------------------------------------------------------
#define QH 264
#define PH 40
#define CS_STR 36
#define AT_K   8448
#define AT_V   25344
#define AT_P   42240
#define AT_CB  94720
#define AT_SMS 103936
#define AT_XM  104192
#define ATTN_BYTES 104320

__device__ __forceinline__ void attn_issue_tile(
    const __half* __restrict__ Km, const __half* __restrict__ Vm,
    const float* __restrict__ comp, const int* __restrict__ smask,
    unsigned sb, int buf, int b, int l0, int s0, int tid)
{
    unsigned kdst = sb + (AT_K + buf*8448)*2;
    unsigned vdst = sb + (AT_V + buf*8448)*2;
    #pragma unroll
    for (int i = 0; i < 4; i++){
        int id = tid + i*256;
        int r = id >> 5, c8 = (id & 31) << 3;
        long grow = (long)(b*LQ + s0 + r)*256 + c8;
        cpa16(kdst + (r*QH + c8)*2, Km + grow);
        cpa16(vdst + (r*QH + c8)*2, Vm + grow);
    }
    {
        int r = tid >> 3, c4 = (tid & 7) << 2;
        unsigned cdst = sb + AT_CB + buf*1152*4 + (r*CS_STR + c4)*4;
        cpa16(cdst, comp + (long)(b*LQ + l0 + r)*LQ + s0 + c4);
    }
    if (tid < 32)
        cpa4(sb + AT_SMS + buf*128 + tid*4, smask + b*LQ + s0 + tid);
}

__global__ void __launch_bounds__(256, 2) k_attn(
    const __half* __restrict__ Qm, const __half* __restrict__ Km, const __half* __restrict__ Vm,
    const float* __restrict__ comp, const int* __restrict__ xmask, const int* __restrict__ smask)
{
    extern __shared__ unsigned char smraw[];
    __half* smh = (__half*)smraw;
    __half* Qh = smh;
    float*  CsBase = (float*)(smraw + AT_CB);
    int*    smsBase = (int*)(smraw + AT_SMS);
    int*    xm = (int*)(smraw + AT_XM);

    int tid = threadIdx.x;
    int w = tid >> 5, lane = tid & 31;
    int h = w & 3, wm = w >> 2;
    int g4 = lane >> 2, tig = lane & 3;
    int lrow = (lane & 7) + ((lane >> 3) & 1)*8;
    int lcol8 = (lane >> 4)*8;
    int l0 = blockIdx.x * 32;
    int sp = blockIdx.y, b = blockIdx.z;
    int dbase = h*64;

    unsigned sb = (unsigned)__cvta_generic_to_shared(smh);
    unsigned qb = sb;
    unsigned pbsu = sb + (AT_P + h*1280)*2;
    __half* Ph = smh + AT_P + h*1280;

    int sbase = sp*(LQ/SPLITS);
    attn_issue_tile(Km, Vm, comp, smask, sb, 0, b, l0, sbase, tid);
    CPA_COMMIT();

    {
        __half2 sc = __half2half2(__float2half(0.125f));
        #pragma unroll
        for (int i = 0; i < 4; i++){
            int id = tid + i*256;
            int r = id >> 5, c8 = (id & 31) << 3;
            uint4 v = *(const uint4*)(Qm + (b*LQ + l0 + r)*256 + c8);
            __half2* ph = (__half2*)&v;
            ph[0] = __hmul2(ph[0], sc); ph[1] = __hmul2(ph[1], sc);
            ph[2] = __hmul2(ph[2], sc); ph[3] = __hmul2(ph[3], sc);
            *(uint4*)&Qh[r*QH + c8] = v;
        }
    }
    if (tid < 32) xm[tid] = xmask[b*LQ + l0 + tid];

    float o[8][4];
    #pragma unroll
    for (int nt = 0; nt < 8; nt++)
        #pragma unroll
        for (int i = 0; i < 4; i++) o[nt][i] = 0.f;
    float rmax[2] = {-1e30f, -1e30f};
    float rsum[2] = {0.f, 0.f};

    CPA_WAIT0();
    __syncthreads();

    int rl = wm*16 + g4;
    const int NT = (LQ/SPLITS)/32;
    for (int t = 0; t < NT; t++){
        int buf = t & 1;
        unsigned kb = sb + (AT_K + buf*8448)*2;
        unsigned vb = sb + (AT_V + buf*8448)*2;
        float* Cs = CsBase + buf*1152;
        int*   sms = smsBase + buf*32;

        if (t + 1 < NT){
            attn_issue_tile(Km, Vm, comp, smask, sb, buf^1, b, l0, sbase + (t+1)*32, tid);
            CPA_COMMIT();
        }

        float S[4][4];
        #pragma unroll
        for (int nt = 0; nt < 4; nt++)
            #pragma unroll
            for (int i = 0; i < 4; i++) S[nt][i] = 0.f;
        #pragma unroll
        for (int kk = 0; kk < 4; kk++){
            int k0 = dbase + kk*16;
            unsigned a[4];
            ldsm4(a, qb + ((wm*16 + lrow)*QH + k0 + lcol8)*2);
            #pragma unroll
            for (int sh = 0; sh < 2; sh++){
                unsigned bk[4];
                ldsm4(bk, kb + ((sh*16 + lrow)*QH + k0 + lcol8)*2);
                unsigned b0[2] = {bk[0], bk[2]};
                unsigned b1[2] = {bk[1], bk[3]};
                mma16(S[sh*2],   a, b0);
                mma16(S[sh*2+1], a, b1);
            }
        }

        int xml = xm[rl], xmh = xm[rl + 8];
        float tmaxl = -1e30f, tmaxh = -1e30f;
        #pragma unroll
        for (int nt = 0; nt < 4; nt++){
            int se = nt*8 + 2*tig, so = se + 1;
            int mse = sms[se], mso = sms[so];
            float ce = Cs[rl*CS_STR + se],      co = Cs[rl*CS_STR + so];
            float de = Cs[(rl+8)*CS_STR + se],  dox = Cs[(rl+8)*CS_STR + so];
            float v0 = (xml && !mse) ? -1e30f : S[nt][0]*ce;
            float v1 = (xml && !mso) ? -1e30f : S[nt][1]*co;
            float v2 = (xmh && !mse) ? -1e30f : S[nt][2]*de;
            float v3 = (xmh && !mso) ? -1e30f : S[nt][3]*dox;
            S[nt][0]=v0; S[nt][1]=v1; S[nt][2]=v2; S[nt][3]=v3;
            tmaxl = fmaxf(tmaxl, fmaxf(v0, v1));
            tmaxh = fmaxf(tmaxh, fmaxf(v2, v3));
        }
        tmaxl = fmaxf(tmaxl, __shfl_xor_sync(~0u, tmaxl, 1));
        tmaxl = fmaxf(tmaxl, __shfl_xor_sync(~0u, tmaxl, 2));
        tmaxh = fmaxf(tmaxh, __shfl_xor_sync(~0u, tmaxh, 1));
        tmaxh = fmaxf(tmaxh, __shfl_xor_sync(~0u, tmaxh, 2));
        float ml = fmaxf(rmax[0], tmaxl), mh = fmaxf(rmax[1], tmaxh);
        float al = fast_exp(rmax[0] - ml), ah = fast_exp(rmax[1] - mh);
        rmax[0] = ml; rmax[1] = mh;
        float tsl = 0.f, tsh = 0.f;
        #pragma unroll
        for (int nt = 0; nt < 4; nt++){
            float p0 = fast_exp(S[nt][0] - ml);
            float p1 = fast_exp(S[nt][1] - ml);
            float p2 = fast_exp(S[nt][2] - mh);
            float p3 = fast_exp(S[nt][3] - mh);
            tsl += p0 + p1; tsh += p2 + p3;
            int se = nt*8 + 2*tig;
            *(unsigned*)&Ph[rl*PH + se]     = h2pk(p0, p1);
            *(unsigned*)&Ph[(rl+8)*PH + se] = h2pk(p2, p3);
        }
        tsl += __shfl_xor_sync(~0u, tsl, 1); tsl += __shfl_xor_sync(~0u, tsl, 2);
        tsh += __shfl_xor_sync(~0u, tsh, 1); tsh += __shfl_xor_sync(~0u, tsh, 2);
        rsum[0] = rsum[0]*al + tsl;
        rsum[1] = rsum[1]*ah + tsh;
        #pragma unroll
        for (int nt = 0; nt < 8; nt++){
            o[nt][0] *= al; o[nt][1] *= al;
            o[nt][2] *= ah; o[nt][3] *= ah;
        }
        __syncwarp();

        #pragma unroll
        for (int kk = 0; kk < 2; kk++){
            unsigned a[4];
            ldsm4(a, pbsu + ((wm*16 + lrow)*PH + kk*16 + lcol8)*2);
            #pragma unroll
            for (int j = 0; j < 4; j++){
                unsigned bv[4];
                ldsm4t(bv, vb + ((kk*16 + lrow)*QH + dbase + j*16 + lcol8)*2);
                unsigned b0[2] = {bv[0], bv[1]};
                unsigned b1[2] = {bv[2], bv[3]};
                mma16(o[2*j],   a, b0);
                mma16(o[2*j+1], a, b1);
            }
        }

        if (t + 1 < NT){
            CPA_WAIT0();
            __syncthreads();
        }
    }

    long prow = (long)(sp*MROWS + b*LQ + l0 + rl);
    #pragma unroll
    for (int nt = 0; nt < 8; nt++){
        int col = dbase + nt*8 + 2*tig;
        *(float2*)(g_part + prow*256 + col)     = make_float2(o[nt][0], o[nt][1]);
        *(float2*)(g_part + (prow+8)*256 + col) = make_float2(o[nt][2], o[nt][3]);
    }
    if (tig == 0){
        long base = (prow*4 + h)*2;
        g_pstat[base]   = rmax[0];
        g_pstat[base+1] = rsum[0];
        long baseh = ((prow+8)*4 + h)*2;
        g_pstat[baseh]   = rmax[1];
        g_pstat[baseh+1] = rsum[1];
    }
}

// ---------------------------------------------------------------------------
extern "C" void kernel_launch(void* const* d_in, const int* in_sizes, int n_in,
                              void* d_out, int out_size)
{
    const float* x    = (const float*)d_in[0];
    const float* src  = (const float*)d_in[1];
    const float* xpe  = (const float*)d_in[2];
    const float* spe  = (const float*)d_in[3];
    const int* xmask  = (const int*)d_in[4];
    const int* smask  = (const int*)d_in[5];
    const float* comp = (const float*)d_in[6];
    const float* Wq   = (const float*)d_in[7];
    const float* Wk   = (const float*)d_in[8];
    const float* Wv   = (const float*)d_in[9];
    const float* Wmg  = (const float*)d_in[10];
    const float* Wm1  = (const float*)d_in[11];
    const float* Wm2  = (const float*)d_in[12];
    const float* ln1g = (const float*)d_in[13];
    const float* ln1b = (const float*)d_in[14];
    const float* ln2g = (const float*)d_in[15];
    const float* ln2b = (const float*)d_in[16];
    float* out = (float*)d_out;

    __half *Qp, *Kp, *Vp;
    cudaGetSymbolAddress((void**)&Qp, g_Qh);
    cudaGetSymbolAddress((void**)&Kp, g_Kh);
    cudaGetSymbolAddress((void**)&Vp, g_Vh);

    cudaFuncSetAttribute(k_attn, cudaFuncAttributeMaxDynamicSharedMemorySize, ATTN_BYTES);

    k_prep<<<(int)PREP_GRID, 256>>>(x, xpe, src, spe, Wq, Wk, Wv, Wm1, Wm2);
    k_qkv <<<dim3(MROWS/32, 1, 3), 256, SM_GEMM>>>();
    k_attn<<<dim3(LQ/32, SPLITS, BSZ), 256, ATTN_BYTES>>>(Qp, Kp, Vp, comp, xmask, smask);
    k_merge<<<MROWS/32,            256, SM_MERGE>>>(Wmg, ln1g, ln1b);
    k_mlp1<<<dim3(MROWS/32, 2),    256, SM_GEMM>>>();
    k_mlp2<<<MROWS/32,             256, SM_GEMM>>>(ln2g, ln2b, x, out);
}

// round 12
// speedup vs baseline: 1.4229x; 1.0007x over previous
#include <cuda_runtime.h>
#include <cuda_fp16.h>
#include <cstdint>

#define BSZ 2
#define LQ 2048
#define DM 256
#define MROWS (BSZ*LQ)
#define SPLITS 2

// scratch
__device__ __half g_Qh[MROWS*DM];
__device__ __half g_Kh[MROWS*DM];
__device__ __half g_Vh[MROWS*DM];
__device__ __half g_Oh[MROWS*DM];
__device__ __half g_xs[MROWS*DM];     // x + xpe
__device__ __half g_ss[MROWS*DM];     // src + spe
__device__ __half g_sv[MROWS*DM];     // src
__device__ __half g_xp[MROWS*DM];     // x
__device__ __half g_msgh[MROWS*DM];
__device__ __half g_hidh[MROWS*2*DM];
__device__ __half g_Wqh[DM*DM];
__device__ __half g_Wkh[DM*DM];
__device__ __half g_Wvh[DM*DM];
__device__ __half g_Wmgh[DM*DM];
__device__ __half g_Wm1h[2*DM*2*DM];
__device__ __half g_Wm2h[2*DM*DM];
__device__ float g_part[SPLITS*MROWS*DM];
__device__ float g_pstat[SPLITS*MROWS*4*2];

// ---------------------------------------------------------------------------
__device__ __forceinline__ unsigned h2pk(float lo, float hi){
    unsigned r; asm("cvt.rn.f16x2.f32 %0, %1, %2;" : "=r"(r) : "f"(hi), "f"(lo)); return r;
}
__device__ __forceinline__ void ldsm4(unsigned* r, unsigned a){
    asm volatile("ldmatrix.sync.aligned.m8n8.x4.shared.b16 {%0,%1,%2,%3},[%4];"
        : "=r"(r[0]),"=r"(r[1]),"=r"(r[2]),"=r"(r[3]) : "r"(a));
}
__device__ __forceinline__ void ldsm4t(unsigned* r, unsigned a){
    asm volatile("ldmatrix.sync.aligned.m8n8.x4.trans.shared.b16 {%0,%1,%2,%3},[%4];"
        : "=r"(r[0]),"=r"(r[1]),"=r"(r[2]),"=r"(r[3]) : "r"(a));
}
__device__ __forceinline__ void mma16(float* c, const unsigned* a, const unsigned* b){
    asm volatile("mma.sync.aligned.m16n8k16.row.col.f32.f16.f16.f32 "
        "{%0,%1,%2,%3},{%4,%5,%6,%7},{%8,%9},{%0,%1,%2,%3};"
        : "+f"(c[0]), "+f"(c[1]), "+f"(c[2]), "+f"(c[3])
        : "r"(a[0]), "r"(a[1]), "r"(a[2]), "r"(a[3]), "r"(b[0]), "r"(b[1]));
}
__device__ __forceinline__ void cpa16(unsigned dst, const void* src){
    asm volatile("cp.async.cg.shared.global [%0], [%1], 16;" :: "r"(dst), "l"(src));
}
__device__ __forceinline__ void cpa4(unsigned dst, const void* src){
    asm volatile("cp.async.ca.shared.global [%0], [%1], 4;" :: "r"(dst), "l"(src));
}
#define CPA_COMMIT() asm volatile("cp.async.commit_group;" ::: "memory")
#define CPA_WAIT0()  asm volatile("cp.async.wait_group 0;" ::: "memory")

// e^x for x <= 0, FMA-pipe only. rel err ~2e-6.
__device__ __forceinline__ float fast_exp(float x){
    float y = x * 1.44269504f;
    y = fmaxf(y, -126.0f);
    float z = y + 12582912.0f;
    int   n = __float_as_int(z) - 0x4B400000;
    float f = y - (z - 12582912.0f);
    float p = 1.33336e-3f;
    p = fmaf(p, f, 9.61813e-3f);
    p = fmaf(p, f, 5.55041e-2f);
    p = fmaf(p, f, 2.40227e-1f);
    p = fmaf(p, f, 6.93147e-1f);
    p = fmaf(p, f, 1.0f);
    return p * __int_as_float((n + 127) << 23);
}

// ---------------------------------------------------------------------------
// prep: convert A-matrices and weights to fp16 once. float4-vectorized.
// ---------------------------------------------------------------------------
#define P_S0 262144L   // xs
#define P_S1 524288L   // ss
#define P_S2 786432L   // sv
#define P_S3 1048576L  // xp
#define P_S4 1064960L  // Wq
#define P_S5 1081344L  // Wk
#define P_S6 1097728L  // Wv
#define P_S7 1114112L  // Wmg
#define P_S8 1179648L  // Wm1
#define P_S9 1212416L  // Wm2 end
#define PREP_GRID ((P_S9 + 255) / 256)

__global__ void __launch_bounds__(256) k_prep(
    const float* x, const float* xpe, const float* src, const float* spe,
    const float* Wq, const float* Wk, const float* Wv, const float* Wmg,
    const float* Wm1, const float* Wm2)
{
    long i = (long)blockIdx.x*256 + threadIdx.x;
    if (i >= P_S9) return;
    float4 v; __half* dst;
    if (i < P_S0){
        float4 a = ((const float4*)x)[i], b = ((const float4*)xpe)[i];
        v = make_float4(a.x+b.x, a.y+b.y, a.z+b.z, a.w+b.w); dst = g_xs + i*4;
    } else if (i < P_S1){
        long j = i - P_S0;
        float4 a = ((const float4*)src)[j], b = ((const float4*)spe)[j];
        v = make_float4(a.x+b.x, a.y+b.y, a.z+b.z, a.w+b.w); dst = g_ss + j*4;
    } else if (i < P_S2){
        long j = i - P_S1; v = ((const float4*)src)[j]; dst = g_sv + j*4;
    } else if (i < P_S3){
        long j = i - P_S2; v = ((const float4*)x)[j]; dst = g_xp + j*4;
    } else if (i < P_S4){
        long j = i - P_S3; v = ((const float4*)Wq)[j]; dst = g_Wqh + j*4;
    } else if (i < P_S5){
        long j = i - P_S4; v = ((const float4*)Wk)[j]; dst = g_Wkh + j*4;
    } else if (i < P_S6){
        long j = i - P_S5; v = ((const float4*)Wv)[j]; dst = g_Wvh + j*4;
    } else if (i < P_S7){
        long j = i - P_S6; v = ((const float4*)Wmg)[j]; dst = g_Wmgh + j*4;
    } else if (i < P_S8){
        long j = i - P_S7; v = ((const float4*)Wm1)[j]; dst = g_Wm1h + j*4;
    } else {
        long j = i - P_S8; v = ((const float4*)Wm2)[j]; dst = g_Wm2h + j*4;
    }
    *(uint2*)dst = make_uint2(h2pk(v.x, v.y), h2pk(v.z, v.w));
}

// ---------------------------------------------------------------------------
// all-fp16 GEMM: BM=32, BN=256, BK=32, 256 threads, cp.async double-buffered.
// ---------------------------------------------------------------------------
#define EPI_RELU  1
#define EPI_LNR   3
#define EPI_H16   4
#define EPI_LNH16 5

#define AS_H 40
#define BS_H 264
#define BUF_H (32*AS_H + 32*BS_H)
#define SM_GEMM (2*BUF_H*2)

template<int KD, bool CAT, int EPI>
__device__ __forceinline__ void gemm_h(
    const __half* __restrict__ A1, const __half* __restrict__ A2,
    const __half* __restrict__ Bw, int ldb, int n0,
    const float* __restrict__ gamma, const float* __restrict__ beta,
    const float* __restrict__ resid, void* __restrict__ Cv, int ldc)
{
    extern __shared__ unsigned char smraw[];
    const int KC = KD/32;
    int tid = threadIdx.x;
    int w = tid >> 5, lane = tid & 31;
    int wm = w >> 2, wn = w & 3;
    int g4 = lane >> 2, tig = lane & 3;
    int lrow = (lane & 7) + ((lane >> 3) & 1)*8;
    int lcol8 = (lane >> 4)*8;
    int row0 = blockIdx.x * 32;
    unsigned sb = (unsigned)__cvta_generic_to_shared(smraw);

    float acc[8][4];
    #pragma unroll
    for (int nt = 0; nt < 8; nt++)
        #pragma unroll
        for (int i = 0; i < 4; i++) acc[nt][i] = 0.f;

    auto issue = [&](int kc){
        unsigned ab = sb + ((kc & 1)*BUF_H)*2;
        unsigned bb = ab + 32*AS_H*2;
        if (tid < 128){
            int r = tid >> 2, c8 = (tid & 3) << 3;
            int col = kc*32 + c8;
            const __half* s;
            if (CAT) s = (col < 256) ? (A1 + (row0+r)*256 + col)
                                     : (A2 + (row0+r)*256 + (col - 256));
            else     s = A1 + (row0+r)*KD + col;
            cpa16(ab + (r*AS_H + c8)*2, s);
        }
        #pragma unroll
        for (int i = 0; i < 4; i++){
            int id = tid + i*256;
            int r = id >> 5, c8 = (id & 31) << 3;
            cpa16(bb + (r*BS_H + c8)*2, Bw + (kc*32 + r)*ldb + n0 + c8);
        }
    };

    issue(0); CPA_COMMIT();
    CPA_WAIT0(); __syncthreads();

    for (int kc = 0; kc < KC; kc++){
        if (kc + 1 < KC){ issue(kc+1); CPA_COMMIT(); }
        unsigned ab = sb + ((kc & 1)*BUF_H)*2;
        unsigned bb = ab + 32*AS_H*2;
        #pragma unroll
        for (int kk = 0; kk < 2; kk++){
            int k0 = kk*16;
            unsigned a[4];
            ldsm4(a, ab + ((wm*16 + lrow)*AS_H + k0 + lcol8)*2);
            #pragma unroll
            for (int j = 0; j < 4; j++){
                unsigned bv[4];
                ldsm4t(bv, bb + ((k0 + lrow)*BS_H + wn*64 + j*16 + lcol8)*2);
                unsigned b0[2] = {bv[0], bv[1]};
                unsigned b1[2] = {bv[2], bv[3]};
                mma16(acc[2*j],   a, b0);
                mma16(acc[2*j+1], a, b1);
            }
        }
        if (kc + 1 < KC){ CPA_WAIT0(); __syncthreads(); }
    }

    if (EPI == EPI_H16 || EPI == EPI_RELU){
        __half* C = (__half*)Cv;
        int rl = row0 + wm*16 + g4;
        #pragma unroll
        for (int nt = 0; nt < 8; nt++){
            int col = n0 + wn*64 + nt*8 + 2*tig;
            float v0 = acc[nt][0], v1 = acc[nt][1];
            float v2 = acc[nt][2], v3 = acc[nt][3];
            if (EPI == EPI_RELU){
                v0=fmaxf(v0,0.f); v1=fmaxf(v1,0.f); v2=fmaxf(v2,0.f); v3=fmaxf(v3,0.f);
            }
            *(unsigned*)(C + rl*ldc + col)     = h2pk(v0, v1);
            *(unsigned*)(C + (rl+8)*ldc + col) = h2pk(v2, v3);
        }
    } else {   // EPI_LNR / EPI_LNH16
        __syncthreads();
        float2* red = (float2*)smraw;    // red[32][4]
        float s1[2] = {0,0}, s2[2] = {0,0};
        #pragma unroll
        for (int nt = 0; nt < 8; nt++){
            float c0=acc[nt][0], c1=acc[nt][1], c2=acc[nt][2], c3=acc[nt][3];
            s1[0] += c0+c1; s2[0] += c0*c0 + c1*c1;
            s1[1] += c2+c3; s2[1] += c2*c2 + c3*c3;
        }
        #pragma unroll
        for (int hb = 0; hb < 2; hb++){
            float v1 = s1[hb], v2 = s2[hb];
            v1 += __shfl_xor_sync(~0u, v1, 1); v1 += __shfl_xor_sync(~0u, v1, 2);
            v2 += __shfl_xor_sync(~0u, v2, 1); v2 += __shfl_xor_sync(~0u, v2, 2);
            if (tig == 0){
                int r = wm*16 + g4 + hb*8;
                red[r*4 + wn] = make_float2(v1, v2);
            }
        }
        __syncthreads();
        #pragma unroll
        for (int hb = 0; hb < 2; hb++){
            int r = wm*16 + g4 + hb*8;
            float S1 = 0.f, S2 = 0.f;
            #pragma unroll
            for (int j = 0; j < 4; j++){ float2 e = red[r*4+j]; S1 += e.x; S2 += e.y; }
            float mean = S1 * (1.f/256.f);
            float var  = S2 * (1.f/256.f) - mean*mean;
            float inv  = rsqrtf(var + 1e-5f);
            int grow = row0 + r;
            #pragma unroll
            for (int nt = 0; nt < 8; nt++){
                int col = wn*64 + nt*8 + 2*tig;
                float c0 = acc[nt][hb*2], c1 = acc[nt][hb*2+1];
                float o0 = (c0 - mean)*inv*gamma[col]   + beta[col];
                float o1 = (c1 - mean)*inv*gamma[col+1] + beta[col+1];
                if (EPI == EPI_LNR){
                    float* C = (float*)Cv;
                    o0 += resid[grow*256 + col];
                    o1 += resid[grow*256 + col + 1];
                    *(float2*)(C + grow*ldc + col) = make_float2(o0, o1);
                } else {
                    __half* C = (__half*)Cv;
                    *(unsigned*)(C + grow*ldc + col) = h2pk(o0, o1);
                }
            }
        }
    }
}

__global__ void __launch_bounds__(256) k_qkv(){
    if (blockIdx.z == 0)      gemm_h<256, false, EPI_H16>(g_xs, 0, g_Wqh, 256, 0, 0,0,0, g_Qh, 256);
    else if (blockIdx.z == 1) gemm_h<256, false, EPI_H16>(g_ss, 0, g_Wkh, 256, 0, 0,0,0, g_Kh, 256);
    else                      gemm_h<256, false, EPI_H16>(g_sv, 0, g_Wvh, 256, 0, 0,0,0, g_Vh, 256);
}
__global__ void __launch_bounds__(256) k_merge(const float* gg, const float* bb){
    gemm_h<256, false, EPI_LNH16>(g_Oh, 0, g_Wmgh, 256, 0, gg, bb, 0, g_msgh, 256);
}
__global__ void __launch_bounds__(256) k_mlp1(){
    gemm_h<512, true, EPI_RELU>(g_xp, g_msgh, g_Wm1h, 512, blockIdx.y*256, 0,0,0, g_hidh, 512);
}
__global__ void __launch_bounds__(256) k_mlp2(const float* gg, const float* bb,
                                              const float* x, float* out){
    gemm_h<512, false, EPI_LNR>(g_hidh, 0, g_Wm2h, 256, 0, gg, bb, x, out, 256);
}

// ---------------------------------------------------------------------------
// attnmerge: collapse split partials -> fp16 g_Oh. grid = MROWS/2, 256 thr.
// ---------------------------------------------------------------------------
__global__ void __launch_bounds__(256) k_attnmerge(){
    long idx = (long)blockIdx.x*256 + threadIdx.x;
    long r = idx >> 7;
    int c = (int)(idx & 127) * 2;
    int h = c >> 6;
    float m0 = g_pstat[((0L*MROWS + r)*4 + h)*2];
    float s0 = g_pstat[((0L*MROWS + r)*4 + h)*2 + 1];
    float m1 = g_pstat[((1L*MROWS + r)*4 + h)*2];
    float s1 = g_pstat[((1L*MROWS + r)*4 + h)*2 + 1];
    float M = fmaxf(m0, m1);
    float w0 = fast_exp(m0 - M), w1 = fast_exp(m1 - M);
    float inv = 1.0f/(s0*w0 + s1*w1);
    w0 *= inv; w1 *= inv;
    float2 p0 = *(const float2*)(g_part + (0L*MROWS + r)*256 + c);
    float2 p1 = *(const float2*)(g_part + (1L*MROWS + r)*256 + c);
    *(unsigned*)(g_Oh + r*256 + c) = h2pk(p0.x*w0 + p1.x*w1, p0.y*w0 + p1.y*w1);
}

// ---------------------------------------------------------------------------
// Flash attention v8: cp.async double-buffered K/V/comp/mask + REGISTER P
// (S C-frag reused directly as PV A-frag; no P smem, no syncwarp).
// ---------------------------------------------------------------------------
#define QH 264
#define CS_STR 36
#define AT_K   8448               // half offsets; K bufs 2x8448
#define AT_V   25344              // V bufs 2x8448
#define AT_CB  84480              // byte offsets
#define AT_SMS 93696
#define AT_XM  93952
#define ATTN_BYTES 94080

__device__ __forceinline__ void attn_issue_tile(
    const __half* __restrict__ Km, const __half* __restrict__ Vm,
    const float* __restrict__ comp, const int* __restrict__ smask,
    unsigned sb, int buf, int b, int l0, int s0, int tid)
{
    unsigned kdst = sb + (AT_K + buf*8448)*2;
    unsigned vdst = sb + (AT_V + buf*8448)*2;
    #pragma unroll
    for (int i = 0; i < 4; i++){
        int id = tid + i*256;
        int r = id >> 5, c8 = (id & 31) << 3;
        long grow = (long)(b*LQ + s0 + r)*256 + c8;
        cpa16(kdst + (r*QH + c8)*2, Km + grow);
        cpa16(vdst + (r*QH + c8)*2, Vm + grow);
    }
    {
        int r = tid >> 3, c4 = (tid & 7) << 2;
        unsigned cdst = sb + AT_CB + buf*1152*4 + (r*CS_STR + c4)*4;
        cpa16(cdst, comp + (long)(b*LQ + l0 + r)*LQ + s0 + c4);
    }
    if (tid < 32)
        cpa4(sb + AT_SMS + buf*128 + tid*4, smask + b*LQ + s0 + tid);
}

__global__ void __launch_bounds__(256, 2) k_attn(
    const __half* __restrict__ Qm, const __half* __restrict__ Km, const __half* __restrict__ Vm,
    const float* __restrict__ comp, const int* __restrict__ xmask, const int* __restrict__ smask)
{
    extern __shared__ unsigned char smraw[];
    __half* smh = (__half*)smraw;
    __half* Qh = smh;
    float*  CsBase = (float*)(smraw + AT_CB);
    int*    smsBase = (int*)(smraw + AT_SMS);
    int*    xm = (int*)(smraw + AT_XM);

    int tid = threadIdx.x;
    int w = tid >> 5, lane = tid & 31;
    int h = w & 3, wm = w >> 2;
    int g4 = lane >> 2, tig = lane & 3;
    int lrow = (lane & 7) + ((lane >> 3) & 1)*8;
    int lcol8 = (lane >> 4)*8;
    int l0 = blockIdx.x * 32;
    int sp = blockIdx.y, b = blockIdx.z;
    int dbase = h*64;

    unsigned sb = (unsigned)__cvta_generic_to_shared(smh);
    unsigned qb = sb;

    int sbase = sp*(LQ/SPLITS);
    attn_issue_tile(Km, Vm, comp, smask, sb, 0, b, l0, sbase, tid);
    CPA_COMMIT();

    {
        __half2 sc = __half2half2(__float2half(0.125f));
        #pragma unroll
        for (int i = 0; i < 4; i++){
            int id = tid + i*256;
            int r = id >> 5, c8 = (id & 31) << 3;
            uint4 v = *(const uint4*)(Qm + (b*LQ + l0 + r)*256 + c8);
            __half2* ph = (__half2*)&v;
            ph[0] = __hmul2(ph[0], sc); ph[1] = __hmul2(ph[1], sc);
            ph[2] = __hmul2(ph[2], sc); ph[3] = __hmul2(ph[3], sc);
            *(uint4*)&Qh[r*QH + c8] = v;
        }
    }
    if (tid < 32) xm[tid] = xmask[b*LQ + l0 + tid];

    float o[8][4];
    #pragma unroll
    for (int nt = 0; nt < 8; nt++)
        #pragma unroll
        for (int i = 0; i < 4; i++) o[nt][i] = 0.f;
    float rmax[2] = {-1e30f, -1e30f};
    float rsum[2] = {0.f, 0.f};

    CPA_WAIT0();
    __syncthreads();

    int rl = wm*16 + g4;
    const int NT = (LQ/SPLITS)/32;
    for (int t = 0; t < NT; t++){
        int buf = t & 1;
        unsigned kb = sb + (AT_K + buf*8448)*2;
        unsigned vb = sb + (AT_V + buf*8448)*2;
        float* Cs = CsBase + buf*1152;
        int*   sms = smsBase + buf*32;

        if (t + 1 < NT){
            attn_issue_tile(Km, Vm, comp, smask, sb, buf^1, b, l0, sbase + (t+1)*32, tid);
            CPA_COMMIT();
        }

        // ---- QK^T ----
        float S[4][4];
        #pragma unroll
        for (int nt = 0; nt < 4; nt++)
            #pragma unroll
            for (int i = 0; i < 4; i++) S[nt][i] = 0.f;
        #pragma unroll
        for (int kk = 0; kk < 4; kk++){
            int k0 = dbase + kk*16;
            unsigned a[4];
            ldsm4(a, qb + ((wm*16 + lrow)*QH + k0 + lcol8)*2);
            #pragma unroll
            for (int sh = 0; sh < 2; sh++){
                unsigned bk[4];
                ldsm4(bk, kb + ((sh*16 + lrow)*QH + k0 + lcol8)*2);
                unsigned b0[2] = {bk[0], bk[2]};
                unsigned b1[2] = {bk[1], bk[3]};
                mma16(S[sh*2],   a, b0);
                mma16(S[sh*2+1], a, b1);
            }
        }

        // ---- softmax; P packed straight into A-fragment registers ----
        int xml = xm[rl], xmh = xm[rl + 8];
        float tmaxl = -1e30f, tmaxh = -1e30f;
        #pragma unroll
        for (int nt = 0; nt < 4; nt++){
            int se = nt*8 + 2*tig, so = se + 1;
            int mse = sms[se], mso = sms[so];
            float ce = Cs[rl*CS_STR + se],      co = Cs[rl*CS_STR + so];
            float de = Cs[(rl+8)*CS_STR + se],  dox = Cs[(rl+8)*CS_STR + so];
            float v0 = (xml && !mse) ? -1e30f : S[nt][0]*ce;
            float v1 = (xml && !mso) ? -1e30f : S[nt][1]*co;
            float v2 = (xmh && !mse) ? -1e30f : S[nt][2]*de;
            float v3 = (xmh && !mso) ? -1e30f : S[nt][3]*dox;
            S[nt][0]=v0; S[nt][1]=v1; S[nt][2]=v2; S[nt][3]=v3;
            tmaxl = fmaxf(tmaxl, fmaxf(v0, v1));
            tmaxh = fmaxf(tmaxh, fmaxf(v2, v3));
        }
        tmaxl = fmaxf(tmaxl, __shfl_xor_sync(~0u, tmaxl, 1));
        tmaxl = fmaxf(tmaxl, __shfl_xor_sync(~0u, tmaxl, 2));
        tmaxh = fmaxf(tmaxh, __shfl_xor_sync(~0u, tmaxh, 1));
        tmaxh = fmaxf(tmaxh, __shfl_xor_sync(~0u, tmaxh, 2));
        float ml = fmaxf(rmax[0], tmaxl), mh = fmaxf(rmax[1], tmaxh);
        float al = fast_exp(rmax[0] - ml), ah = fast_exp(rmax[1] - mh);
        rmax[0] = ml; rmax[1] = mh;
        float tsl = 0.f, tsh = 0.f;
        unsigned Pa[4][2];
        #pragma unroll
        for (int nt = 0; nt < 4; nt++){
            float p0 = fast_exp(S[nt][0] - ml);
            float p1 = fast_exp(S[nt][1] - ml);
            float p2 = fast_exp(S[nt][2] - mh);
            float p3 = fast_exp(S[nt][3] - mh);
            tsl += p0 + p1; tsh += p2 + p3;
            Pa[nt][0] = h2pk(p0, p1);   // row g4,   cols 2tig/2tig+1
            Pa[nt][1] = h2pk(p2, p3);   // row g4+8, cols 2tig/2tig+1
        }
        tsl += __shfl_xor_sync(~0u, tsl, 1); tsl += __shfl_xor_sync(~0u, tsl, 2);
        tsh += __shfl_xor_sync(~0u, tsh, 1); tsh += __shfl_xor_sync(~0u, tsh, 2);
        rsum[0] = rsum[0]*al + tsl;
        rsum[1] = rsum[1]*ah + tsh;
        #pragma unroll
        for (int nt = 0; nt < 8; nt++){
            o[nt][0] *= al; o[nt][1] *= al;
            o[nt][2] *= ah; o[nt][3] *= ah;
        }

        // ---- P @ V: A-frag = packed S fragments (no smem round trip) ----
        #pragma unroll
        for (int kk = 0; kk < 2; kk++){
            unsigned a[4] = {Pa[kk*2][0], Pa[kk*2][1], Pa[kk*2+1][0], Pa[kk*2+1][1]};
            #pragma unroll
            for (int j = 0; j < 4; j++){
                unsigned bv[4];
                ldsm4t(bv, vb + ((kk*16 + lrow)*QH + dbase + j*16 + lcol8)*2);
                unsigned b0[2] = {bv[0], bv[1]};
                unsigned b1[2] = {bv[2], bv[3]};
                mma16(o[2*j],   a, b0);
                mma16(o[2*j+1], a, b1);
            }
        }

        if (t + 1 < NT){
            CPA_WAIT0();
            __syncthreads();
        }
    }

    long prow = (long)(sp*MROWS + b*LQ + l0 + rl);
    #pragma unroll
    for (int nt = 0; nt < 8; nt++){
        int col = dbase + nt*8 + 2*tig;
        *(float2*)(g_part + prow*256 + col)     = make_float2(o[nt][0], o[nt][1]);
        *(float2*)(g_part + (prow+8)*256 + col) = make_float2(o[nt][2], o[nt][3]);
    }
    if (tig == 0){
        long base = (prow*4 + h)*2;
        g_pstat[base]   = rmax[0];
        g_pstat[base+1] = rsum[0];
        long baseh = ((prow+8)*4 + h)*2;
        g_pstat[baseh]   = rmax[1];
        g_pstat[baseh+1] = rsum[1];
    }
}

// ---------------------------------------------------------------------------
extern "C" void kernel_launch(void* const* d_in, const int* in_sizes, int n_in,
                              void* d_out, int out_size)
{
    const float* x    = (const float*)d_in[0];
    const float* src  = (const float*)d_in[1];
    const float* xpe  = (const float*)d_in[2];
    const float* spe  = (const float*)d_in[3];
    const int* xmask  = (const int*)d_in[4];
    const int* smask  = (const int*)d_in[5];
    const float* comp = (const float*)d_in[6];
    const float* Wq   = (const float*)d_in[7];
    const float* Wk   = (const float*)d_in[8];
    const float* Wv   = (const float*)d_in[9];
    const float* Wmg  = (const float*)d_in[10];
    const float* Wm1  = (const float*)d_in[11];
    const float* Wm2  = (const float*)d_in[12];
    const float* ln1g = (const float*)d_in[13];
    const float* ln1b = (const float*)d_in[14];
    const float* ln2g = (const float*)d_in[15];
    const float* ln2b = (const float*)d_in[16];
    float* out = (float*)d_out;

    __half *Qp, *Kp, *Vp;
    cudaGetSymbolAddress((void**)&Qp, g_Qh);
    cudaGetSymbolAddress((void**)&Kp, g_Kh);
    cudaGetSymbolAddress((void**)&Vp, g_Vh);

    cudaFuncSetAttribute(k_attn, cudaFuncAttributeMaxDynamicSharedMemorySize, ATTN_BYTES);

    k_prep<<<(int)PREP_GRID, 256>>>(x, xpe, src, spe, Wq, Wk, Wv, Wmg, Wm1, Wm2);
    k_qkv <<<dim3(MROWS/32, 1, 3), 256, SM_GEMM>>>();
    k_attn<<<dim3(LQ/32, SPLITS, BSZ), 256, ATTN_BYTES>>>(Qp, Kp, Vp, comp, xmask, smask);
    k_attnmerge<<<MROWS/2, 256>>>();
    k_merge<<<MROWS/32,            256, SM_GEMM>>>(ln1g, ln1b);
    k_mlp1<<<dim3(MROWS/32, 2),    256, SM_GEMM>>>();
    k_mlp2<<<MROWS/32,             256, SM_GEMM>>>(ln2g, ln2b, x, out);
}

// round 13
// speedup vs baseline: 1.4664x; 1.0306x over previous
#include <cuda_runtime.h>
#include <cuda_fp16.h>
#include <cstdint>

#define BSZ 2
#define LQ 2048
#define DM 256
#define MROWS (BSZ*LQ)
#define SPLITS 2

// scratch
__device__ __half g_Qh[MROWS*DM];
__device__ __half g_Kh[MROWS*DM];
__device__ __half g_Vh[MROWS*DM];
__device__ __half g_Oh[MROWS*DM];
__device__ __half g_xs[MROWS*DM];     // x + xpe
__device__ __half g_ss[MROWS*DM];     // src + spe
__device__ __half g_sv[MROWS*DM];     // src
__device__ __half g_xp[MROWS*DM];     // x
__device__ __half g_msgh[MROWS*DM];
__device__ __half g_hidh[MROWS*2*DM];
__device__ __half g_Wqh[DM*DM];
__device__ __half g_Wkh[DM*DM];
__device__ __half g_Wvh[DM*DM];
__device__ __half g_Wmgh[DM*DM];
__device__ __half g_Wm1h[2*DM*2*DM];
__device__ __half g_Wm2h[2*DM*DM];
__device__ __half g_parth[SPLITS*MROWS*DM];
__device__ float g_pstat[SPLITS*MROWS*4*2];

// ---------------------------------------------------------------------------
__device__ __forceinline__ unsigned h2pk(float lo, float hi){
    unsigned r; asm("cvt.rn.f16x2.f32 %0, %1, %2;" : "=r"(r) : "f"(hi), "f"(lo)); return r;
}
__device__ __forceinline__ void ldsm4(unsigned* r, unsigned a){
    asm volatile("ldmatrix.sync.aligned.m8n8.x4.shared.b16 {%0,%1,%2,%3},[%4];"
        : "=r"(r[0]),"=r"(r[1]),"=r"(r[2]),"=r"(r[3]) : "r"(a));
}
__device__ __forceinline__ void ldsm4t(unsigned* r, unsigned a){
    asm volatile("ldmatrix.sync.aligned.m8n8.x4.trans.shared.b16 {%0,%1,%2,%3},[%4];"
        : "=r"(r[0]),"=r"(r[1]),"=r"(r[2]),"=r"(r[3]) : "r"(a));
}
__device__ __forceinline__ void mma16(float* c, const unsigned* a, const unsigned* b){
    asm volatile("mma.sync.aligned.m16n8k16.row.col.f32.f16.f16.f32 "
        "{%0,%1,%2,%3},{%4,%5,%6,%7},{%8,%9},{%0,%1,%2,%3};"
        : "+f"(c[0]), "+f"(c[1]), "+f"(c[2]), "+f"(c[3])
        : "r"(a[0]), "r"(a[1]), "r"(a[2]), "r"(a[3]), "r"(b[0]), "r"(b[1]));
}
__device__ __forceinline__ void cpa16(unsigned dst, const void* src){
    asm volatile("cp.async.cg.shared.global [%0], [%1], 16;" :: "r"(dst), "l"(src));
}
__device__ __forceinline__ void cpa4(unsigned dst, const void* src){
    asm volatile("cp.async.ca.shared.global [%0], [%1], 4;" :: "r"(dst), "l"(src));
}
#define CPA_COMMIT() asm volatile("cp.async.commit_group;" ::: "memory")
#define CPA_WAIT0()  asm volatile("cp.async.wait_group 0;" ::: "memory")

// e^x for x <= 0, FMA-pipe only. rel err ~2e-6.
__device__ __forceinline__ float fast_exp(float x){
    float y = x * 1.44269504f;
    y = fmaxf(y, -126.0f);
    float z = y + 12582912.0f;
    int   n = __float_as_int(z) - 0x4B400000;
    float f = y - (z - 12582912.0f);
    float p = 1.33336e-3f;
    p = fmaf(p, f, 9.61813e-3f);
    p = fmaf(p, f, 5.55041e-2f);
    p = fmaf(p, f, 2.40227e-1f);
    p = fmaf(p, f, 6.93147e-1f);
    p = fmaf(p, f, 1.0f);
    return p * __int_as_float((n + 127) << 23);
}

// ---------------------------------------------------------------------------
// prep: convert A-matrices and weights to fp16 once. float4-vectorized.
// ---------------------------------------------------------------------------
#define P_S0 262144L   // xs
#define P_S1 524288L   // ss
#define P_S2 786432L   // sv
#define P_S3 1048576L  // xp
#define P_S4 1064960L  // Wq
#define P_S5 1081344L  // Wk
#define P_S6 1097728L  // Wv
#define P_S7 1114112L  // Wmg
#define P_S8 1179648L  // Wm1
#define P_S9 1212416L  // Wm2 end
#define PREP_GRID ((P_S9 + 255) / 256)

__global__ void __launch_bounds__(256) k_prep(
    const float* x, const float* xpe, const float* src, const float* spe,
    const float* Wq, const float* Wk, const float* Wv, const float* Wmg,
    const float* Wm1, const float* Wm2)
{
    long i = (long)blockIdx.x*256 + threadIdx.x;
    if (i >= P_S9) return;
    float4 v; __half* dst;
    if (i < P_S0){
        float4 a = ((const float4*)x)[i], b = ((const float4*)xpe)[i];
        v = make_float4(a.x+b.x, a.y+b.y, a.z+b.z, a.w+b.w); dst = g_xs + i*4;
    } else if (i < P_S1){
        long j = i - P_S0;
        float4 a = ((const float4*)src)[j], b = ((const float4*)spe)[j];
        v = make_float4(a.x+b.x, a.y+b.y, a.z+b.z, a.w+b.w); dst = g_ss + j*4;
    } else if (i < P_S2){
        long j = i - P_S1; v = ((const float4*)src)[j]; dst = g_sv + j*4;
    } else if (i < P_S3){
        long j = i - P_S2; v = ((const float4*)x)[j]; dst = g_xp + j*4;
    } else if (i < P_S4){
        long j = i - P_S3; v = ((const float4*)Wq)[j]; dst = g_Wqh + j*4;
    } else if (i < P_S5){
        long j = i - P_S4; v = ((const float4*)Wk)[j]; dst = g_Wkh + j*4;
    } else if (i < P_S6){
        long j = i - P_S5; v = ((const float4*)Wv)[j]; dst = g_Wvh + j*4;
    } else if (i < P_S7){
        long j = i - P_S6; v = ((const float4*)Wmg)[j]; dst = g_Wmgh + j*4;
    } else if (i < P_S8){
        long j = i - P_S7; v = ((const float4*)Wm1)[j]; dst = g_Wm1h + j*4;
    } else {
        long j = i - P_S8; v = ((const float4*)Wm2)[j]; dst = g_Wm2h + j*4;
    }
    *(uint2*)dst = make_uint2(h2pk(v.x, v.y), h2pk(v.z, v.w));
}

// ---------------------------------------------------------------------------
// all-fp16 GEMM: BM=32, BN=256, BK=32, 256 threads, cp.async double-buffered.
// ---------------------------------------------------------------------------
#define EPI_RELU  1
#define EPI_LNR   3
#define EPI_H16   4
#define EPI_LNH16 5

#define AS_H 40
#define BS_H 264
#define BUF_H (32*AS_H + 32*BS_H)
#define SM_GEMM (2*BUF_H*2)

template<int KD, bool CAT, int EPI>
__device__ __forceinline__ void gemm_h(
    const __half* __restrict__ A1, const __half* __restrict__ A2,
    const __half* __restrict__ Bw, int ldb, int n0,
    const float* __restrict__ gamma, const float* __restrict__ beta,
    const float* __restrict__ resid, void* __restrict__ Cv, int ldc)
{
    extern __shared__ unsigned char smraw[];
    const int KC = KD/32;
    int tid = threadIdx.x;
    int w = tid >> 5, lane = tid & 31;
    int wm = w >> 2, wn = w & 3;
    int g4 = lane >> 2, tig = lane & 3;
    int lrow = (lane & 7) + ((lane >> 3) & 1)*8;
    int lcol8 = (lane >> 4)*8;
    int row0 = blockIdx.x * 32;
    unsigned sb = (unsigned)__cvta_generic_to_shared(smraw);

    float acc[8][4];
    #pragma unroll
    for (int nt = 0; nt < 8; nt++)
        #pragma unroll
        for (int i = 0; i < 4; i++) acc[nt][i] = 0.f;

    auto issue = [&](int kc){
        unsigned ab = sb + ((kc & 1)*BUF_H)*2;
        unsigned bb = ab + 32*AS_H*2;
        if (tid < 128){
            int r = tid >> 2, c8 = (tid & 3) << 3;
            int col = kc*32 + c8;
            const __half* s;
            if (CAT) s = (col < 256) ? (A1 + (row0+r)*256 + col)
                                     : (A2 + (row0+r)*256 + (col - 256));
            else     s = A1 + (row0+r)*KD + col;
            cpa16(ab + (r*AS_H + c8)*2, s);
        }
        #pragma unroll
        for (int i = 0; i < 4; i++){
            int id = tid + i*256;
            int r = id >> 5, c8 = (id & 31) << 3;
            cpa16(bb + (r*BS_H + c8)*2, Bw + (kc*32 + r)*ldb + n0 + c8);
        }
    };

    issue(0); CPA_COMMIT();
    CPA_WAIT0(); __syncthreads();

    for (int kc = 0; kc < KC; kc++){
        if (kc + 1 < KC){ issue(kc+1); CPA_COMMIT(); }
        unsigned ab = sb + ((kc & 1)*BUF_H)*2;
        unsigned bb = ab + 32*AS_H*2;
        #pragma unroll
        for (int kk = 0; kk < 2; kk++){
            int k0 = kk*16;
            unsigned a[4];
            ldsm4(a, ab + ((wm*16 + lrow)*AS_H + k0 + lcol8)*2);
            #pragma unroll
            for (int j = 0; j < 4; j++){
                unsigned bv[4];
                ldsm4t(bv, bb + ((k0 + lrow)*BS_H + wn*64 + j*16 + lcol8)*2);
                unsigned b0[2] = {bv[0], bv[1]};
                unsigned b1[2] = {bv[2], bv[3]};
                mma16(acc[2*j],   a, b0);
                mma16(acc[2*j+1], a, b1);
            }
        }
        if (kc + 1 < KC){ CPA_WAIT0(); __syncthreads(); }
    }

    if (EPI == EPI_H16 || EPI == EPI_RELU){
        __half* C = (__half*)Cv;
        int rl = row0 + wm*16 + g4;
        #pragma unroll
        for (int nt = 0; nt < 8; nt++){
            int col = n0 + wn*64 + nt*8 + 2*tig;
            float v0 = acc[nt][0], v1 = acc[nt][1];
            float v2 = acc[nt][2], v3 = acc[nt][3];
            if (EPI == EPI_RELU){
                v0=fmaxf(v0,0.f); v1=fmaxf(v1,0.f); v2=fmaxf(v2,0.f); v3=fmaxf(v3,0.f);
            }
            *(unsigned*)(C + rl*ldc + col)     = h2pk(v0, v1);
            *(unsigned*)(C + (rl+8)*ldc + col) = h2pk(v2, v3);
        }
    } else {   // EPI_LNR / EPI_LNH16
        __syncthreads();
        float2* red = (float2*)smraw;    // red[32][4]
        float s1[2] = {0,0}, s2[2] = {0,0};
        #pragma unroll
        for (int nt = 0; nt < 8; nt++){
            float c0=acc[nt][0], c1=acc[nt][1], c2=acc[nt][2], c3=acc[nt][3];
            s1[0] += c0+c1; s2[0] += c0*c0 + c1*c1;
            s1[1] += c2+c3; s2[1] += c2*c2 + c3*c3;
        }
        #pragma unroll
        for (int hb = 0; hb < 2; hb++){
            float v1 = s1[hb], v2 = s2[hb];
            v1 += __shfl_xor_sync(~0u, v1, 1); v1 += __shfl_xor_sync(~0u, v1, 2);
            v2 += __shfl_xor_sync(~0u, v2, 1); v2 += __shfl_xor_sync(~0u, v2, 2);
            if (tig == 0){
                int r = wm*16 + g4 + hb*8;
                red[r*4 + wn] = make_float2(v1, v2);
            }
        }
        __syncthreads();
        #pragma unroll
        for (int hb = 0; hb < 2; hb++){
            int r = wm*16 + g4 + hb*8;
            float S1 = 0.f, S2 = 0.f;
            #pragma unroll
            for (int j = 0; j < 4; j++){ float2 e = red[r*4+j]; S1 += e.x; S2 += e.y; }
            float mean = S1 * (1.f/256.f);
            float var  = S2 * (1.f/256.f) - mean*mean;
            float inv  = rsqrtf(var + 1e-5f);
            int grow = row0 + r;
            #pragma unroll
            for (int nt = 0; nt < 8; nt++){
                int col = wn*64 + nt*8 + 2*tig;
                float c0 = acc[nt][hb*2], c1 = acc[nt][hb*2+1];
                float o0 = (c0 - mean)*inv*gamma[col]   + beta[col];
                float o1 = (c1 - mean)*inv*gamma[col+1] + beta[col+1];
                if (EPI == EPI_LNR){
                    float* C = (float*)Cv;
                    o0 += resid[grow*256 + col];
                    o1 += resid[grow*256 + col + 1];
                    *(float2*)(C + grow*ldc + col) = make_float2(o0, o1);
                } else {
                    __half* C = (__half*)Cv;
                    *(unsigned*)(C + grow*ldc + col) = h2pk(o0, o1);
                }
            }
        }
    }
}

__global__ void __launch_bounds__(256) k_qkv(){
    if (blockIdx.z == 0)      gemm_h<256, false, EPI_H16>(g_xs, 0, g_Wqh, 256, 0, 0,0,0, g_Qh, 256);
    else if (blockIdx.z == 1) gemm_h<256, false, EPI_H16>(g_ss, 0, g_Wkh, 256, 0, 0,0,0, g_Kh, 256);
    else                      gemm_h<256, false, EPI_H16>(g_sv, 0, g_Wvh, 256, 0, 0,0,0, g_Vh, 256);
}
__global__ void __launch_bounds__(256) k_merge(const float* gg, const float* bb){
    gemm_h<256, false, EPI_LNH16>(g_Oh, 0, g_Wmgh, 256, 0, gg, bb, 0, g_msgh, 256);
}
__global__ void __launch_bounds__(256) k_mlp1(){
    gemm_h<512, true, EPI_RELU>(g_xp, g_msgh, g_Wm1h, 512, blockIdx.y*256, 0,0,0, g_hidh, 512);
}
__global__ void __launch_bounds__(256) k_mlp2(const float* gg, const float* bb,
                                              const float* x, float* out){
    gemm_h<512, false, EPI_LNR>(g_hidh, 0, g_Wm2h, 256, 0, gg, bb, x, out, 256);
}

// ---------------------------------------------------------------------------
// attnmerge: collapse fp16 split partials -> fp16 g_Oh.
// ---------------------------------------------------------------------------
__global__ void __launch_bounds__(256) k_attnmerge(){
    long idx = (long)blockIdx.x*256 + threadIdx.x;
    long r = idx >> 7;
    int c = (int)(idx & 127) * 2;
    int h = c >> 6;
    float m0 = g_pstat[((0L*MROWS + r)*4 + h)*2];
    float s0 = g_pstat[((0L*MROWS + r)*4 + h)*2 + 1];
    float m1 = g_pstat[((1L*MROWS + r)*4 + h)*2];
    float s1 = g_pstat[((1L*MROWS + r)*4 + h)*2 + 1];
    float M = fmaxf(m0, m1);
    float w0 = fast_exp(m0 - M), w1 = fast_exp(m1 - M);
    float inv = 1.0f/(s0*w0 + s1*w1);
    w0 *= inv; w1 *= inv;
    float2 p0 = __half22float2(*(const __half2*)(g_parth + (0L*MROWS + r)*256 + c));
    float2 p1 = __half22float2(*(const __half2*)(g_parth + (1L*MROWS + r)*256 + c));
    *(unsigned*)(g_Oh + r*256 + c) = h2pk(p0.x*w0 + p1.x*w1, p0.y*w0 + p1.y*w1);
}

// ---------------------------------------------------------------------------
// Flash attention v9: BM=64 q-rows, 512 threads (16 warps = 4 row-quarters x
// 4 heads). cp.async double-buffered K/V/comp/mask; register P (FA2 frag
// reuse); fp16 partial output. Grid 32 x SPLITS x BSZ = 128 CTAs, 1 CTA/SM.
// ---------------------------------------------------------------------------
#define QH 264
#define CS_STR 36
// half offsets
#define AT_K   16896              // K bufs 2x8448
#define AT_V   33792              // V bufs 2x8448
// byte offsets
#define AT_CB  101376             // Cs: 2 x 64 x 36 floats
#define AT_SMS 119808             // sms: 2 x 32 ints
#define AT_XM  120064             // xm: 64 ints
#define ATTN_BYTES 120320

__device__ __forceinline__ void attn_issue_tile(
    const __half* __restrict__ Km, const __half* __restrict__ Vm,
    const float* __restrict__ comp, const int* __restrict__ smask,
    unsigned sb, int buf, int b, int l0, int s0, int tid)
{
    unsigned kdst = sb + (AT_K + buf*8448)*2;
    unsigned vdst = sb + (AT_V + buf*8448)*2;
    #pragma unroll
    for (int i = 0; i < 2; i++){
        int id = tid + i*512;
        int r = id >> 5, c8 = (id & 31) << 3;
        long grow = (long)(b*LQ + s0 + r)*256 + c8;
        cpa16(kdst + (r*QH + c8)*2, Km + grow);
        cpa16(vdst + (r*QH + c8)*2, Vm + grow);
    }
    {
        int r = tid >> 3, c4 = (tid & 7) << 2;
        unsigned cdst = sb + AT_CB + buf*(64*CS_STR*4) + (r*CS_STR + c4)*4;
        cpa16(cdst, comp + (long)(b*LQ + l0 + r)*LQ + s0 + c4);
    }
    if (tid < 32)
        cpa4(sb + AT_SMS + buf*128 + tid*4, smask + b*LQ + s0 + tid);
}

__global__ void __launch_bounds__(512, 1) k_attn(
    const __half* __restrict__ Qm, const __half* __restrict__ Km, const __half* __restrict__ Vm,
    const float* __restrict__ comp, const int* __restrict__ xmask, const int* __restrict__ smask)
{
    extern __shared__ unsigned char smraw[];
    __half* smh = (__half*)smraw;
    __half* Qh = smh;
    float*  CsBase = (float*)(smraw + AT_CB);
    int*    smsBase = (int*)(smraw + AT_SMS);
    int*    xm = (int*)(smraw + AT_XM);

    int tid = threadIdx.x;
    int w = tid >> 5, lane = tid & 31;
    int h = w & 3, wm = w >> 2;          // wm in 0..3
    int g4 = lane >> 2, tig = lane & 3;
    int lrow = (lane & 7) + ((lane >> 3) & 1)*8;
    int lcol8 = (lane >> 4)*8;
    int l0 = blockIdx.x * 64;
    int sp = blockIdx.y, b = blockIdx.z;
    int dbase = h*64;

    unsigned sb = (unsigned)__cvta_generic_to_shared(smh);
    unsigned qb = sb;

    int sbase = sp*(LQ/SPLITS);
    attn_issue_tile(Km, Vm, comp, smask, sb, 0, b, l0, sbase, tid);
    CPA_COMMIT();

    // stage Q (64x256 halves), pre-scaled by 0.125 (exact exponent shift)
    {
        __half2 sc = __half2half2(__float2half(0.125f));
        #pragma unroll
        for (int i = 0; i < 4; i++){
            int id = tid + i*512;
            int r = id >> 5, c8 = (id & 31) << 3;
            uint4 v = *(const uint4*)(Qm + (b*LQ + l0 + r)*256 + c8);
            __half2* ph = (__half2*)&v;
            ph[0] = __hmul2(ph[0], sc); ph[1] = __hmul2(ph[1], sc);
            ph[2] = __hmul2(ph[2], sc); ph[3] = __hmul2(ph[3], sc);
            *(uint4*)&Qh[r*QH + c8] = v;
        }
    }
    if (tid < 64) xm[tid] = xmask[b*LQ + l0 + tid];

    float o[8][4];
    #pragma unroll
    for (int nt = 0; nt < 8; nt++)
        #pragma unroll
        for (int i = 0; i < 4; i++) o[nt][i] = 0.f;
    float rmax[2] = {-1e30f, -1e30f};
    float rsum[2] = {0.f, 0.f};

    CPA_WAIT0();
    __syncthreads();

    int rl = wm*16 + g4;
    const int NT = (LQ/SPLITS)/32;
    for (int t = 0; t < NT; t++){
        int buf = t & 1;
        unsigned kb = sb + (AT_K + buf*8448)*2;
        unsigned vb = sb + (AT_V + buf*8448)*2;
        float* Cs = CsBase + buf*(64*CS_STR);
        int*   sms = smsBase + buf*32;

        if (t + 1 < NT){
            attn_issue_tile(Km, Vm, comp, smask, sb, buf^1, b, l0, sbase + (t+1)*32, tid);
            CPA_COMMIT();
        }

        // ---- QK^T: S[16l x 32s] per warp ----
        float S[4][4];
        #pragma unroll
        for (int nt = 0; nt < 4; nt++)
            #pragma unroll
            for (int i = 0; i < 4; i++) S[nt][i] = 0.f;
        #pragma unroll
        for (int kk = 0; kk < 4; kk++){
            int k0 = dbase + kk*16;
            unsigned a[4];
            ldsm4(a, qb + ((wm*16 + lrow)*QH + k0 + lcol8)*2);
            #pragma unroll
            for (int sh = 0; sh < 2; sh++){
                unsigned bk[4];
                ldsm4(bk, kb + ((sh*16 + lrow)*QH + k0 + lcol8)*2);
                unsigned b0[2] = {bk[0], bk[2]};
                unsigned b1[2] = {bk[1], bk[3]};
                mma16(S[sh*2],   a, b0);
                mma16(S[sh*2+1], a, b1);
            }
        }

        // ---- softmax; P packed straight into A-fragment registers ----
        int xml = xm[rl], xmh = xm[rl + 8];
        float tmaxl = -1e30f, tmaxh = -1e30f;
        #pragma unroll
        for (int nt = 0; nt < 4; nt++){
            int se = nt*8 + 2*tig, so = se + 1;
            int mse = sms[se], mso = sms[so];
            float ce = Cs[rl*CS_STR + se],      co = Cs[rl*CS_STR + so];
            float de = Cs[(rl+8)*CS_STR + se],  dox = Cs[(rl+8)*CS_STR + so];
            float v0 = (xml && !mse) ? -1e30f : S[nt][0]*ce;
            float v1 = (xml && !mso) ? -1e30f : S[nt][1]*co;
            float v2 = (xmh && !mse) ? -1e30f : S[nt][2]*de;
            float v3 = (xmh && !mso) ? -1e30f : S[nt][3]*dox;
            S[nt][0]=v0; S[nt][1]=v1; S[nt][2]=v2; S[nt][3]=v3;
            tmaxl = fmaxf(tmaxl, fmaxf(v0, v1));
            tmaxh = fmaxf(tmaxh, fmaxf(v2, v3));
        }
        tmaxl = fmaxf(tmaxl, __shfl_xor_sync(~0u, tmaxl, 1));
        tmaxl = fmaxf(tmaxl, __shfl_xor_sync(~0u, tmaxl, 2));
        tmaxh = fmaxf(tmaxh, __shfl_xor_sync(~0u, tmaxh, 1));
        tmaxh = fmaxf(tmaxh, __shfl_xor_sync(~0u, tmaxh, 2));
        float ml = fmaxf(rmax[0], tmaxl), mh = fmaxf(rmax[1], tmaxh);
        float al = fast_exp(rmax[0] - ml), ah = fast_exp(rmax[1] - mh);
        rmax[0] = ml; rmax[1] = mh;
        float tsl = 0.f, tsh = 0.f;
        unsigned Pa[4][2];
        #pragma unroll
        for (int nt = 0; nt < 4; nt++){
            float p0 = fast_exp(S[nt][0] - ml);
            float p1 = fast_exp(S[nt][1] - ml);
            float p2 = fast_exp(S[nt][2] - mh);
            float p3 = fast_exp(S[nt][3] - mh);
            tsl += p0 + p1; tsh += p2 + p3;
            Pa[nt][0] = h2pk(p0, p1);
            Pa[nt][1] = h2pk(p2, p3);
        }
        tsl += __shfl_xor_sync(~0u, tsl, 1); tsl += __shfl_xor_sync(~0u, tsl, 2);
        tsh += __shfl_xor_sync(~0u, tsh, 1); tsh += __shfl_xor_sync(~0u, tsh, 2);
        rsum[0] = rsum[0]*al + tsl;
        rsum[1] = rsum[1]*ah + tsh;
        #pragma unroll
        for (int nt = 0; nt < 8; nt++){
            o[nt][0] *= al; o[nt][1] *= al;
            o[nt][2] *= ah; o[nt][3] *= ah;
        }

        // ---- P @ V: A-frag = packed S fragments ----
        #pragma unroll
        for (int kk = 0; kk < 2; kk++){
            unsigned a[4] = {Pa[kk*2][0], Pa[kk*2][1], Pa[kk*2+1][0], Pa[kk*2+1][1]};
            #pragma unroll
            for (int j = 0; j < 4; j++){
                unsigned bv[4];
                ldsm4t(bv, vb + ((kk*16 + lrow)*QH + dbase + j*16 + lcol8)*2);
                unsigned b0[2] = {bv[0], bv[1]};
                unsigned b1[2] = {bv[2], bv[3]};
                mma16(o[2*j],   a, b0);
                mma16(o[2*j+1], a, b1);
            }
        }

        if (t + 1 < NT){
            CPA_WAIT0();
            __syncthreads();
        }
    }

    // ---- write unnormalized fp16 partials + stats ----
    long prow = (long)(sp*MROWS + b*LQ + l0 + rl);
    #pragma unroll
    for (int nt = 0; nt < 8; nt++){
        int col = dbase + nt*8 + 2*tig;
        *(unsigned*)(g_parth + prow*256 + col)     = h2pk(o[nt][0], o[nt][1]);
        *(unsigned*)(g_parth + (prow+8)*256 + col) = h2pk(o[nt][2], o[nt][3]);
    }
    if (tig == 0){
        long base = (prow*4 + h)*2;
        g_pstat[base]   = rmax[0];
        g_pstat[base+1] = rsum[0];
        long baseh = ((prow+8)*4 + h)*2;
        g_pstat[baseh]   = rmax[1];
        g_pstat[baseh+1] = rsum[1];
    }
}

// ---------------------------------------------------------------------------
extern "C" void kernel_launch(void* const* d_in, const int* in_sizes, int n_in,
                              void* d_out, int out_size)
{
    const float* x    = (const float*)d_in[0];
    const float* src  = (const float*)d_in[1];
    const float* xpe  = (const float*)d_in[2];
    const float* spe  = (const float*)d_in[3];
    const int* xmask  = (const int*)d_in[4];
    const int* smask  = (const int*)d_in[5];
    const float* comp = (const float*)d_in[6];
    const float* Wq   = (const float*)d_in[7];
    const float* Wk   = (const float*)d_in[8];
    const float* Wv   = (const float*)d_in[9];
    const float* Wmg  = (const float*)d_in[10];
    const float* Wm1  = (const float*)d_in[11];
    const float* Wm2  = (const float*)d_in[12];
    const float* ln1g = (const float*)d_in[13];
    const float* ln1b = (const float*)d_in[14];
    const float* ln2g = (const float*)d_in[15];
    const float* ln2b = (const float*)d_in[16];
    float* out = (float*)d_out;

    __half *Qp, *Kp, *Vp;
    cudaGetSymbolAddress((void**)&Qp, g_Qh);
    cudaGetSymbolAddress((void**)&Kp, g_Kh);
    cudaGetSymbolAddress((void**)&Vp, g_Vh);

    cudaFuncSetAttribute(k_attn, cudaFuncAttributeMaxDynamicSharedMemorySize, ATTN_BYTES);

    k_prep<<<(int)PREP_GRID, 256>>>(x, xpe, src, spe, Wq, Wk, Wv, Wmg, Wm1, Wm2);
    k_qkv <<<dim3(MROWS/32, 1, 3), 256, SM_GEMM>>>();
    k_attn<<<dim3(LQ/64, SPLITS, BSZ), 512, ATTN_BYTES>>>(Qp, Kp, Vp, comp, xmask, smask);
    k_attnmerge<<<MROWS/2, 256>>>();
    k_merge<<<MROWS/32,            256, SM_GEMM>>>(ln1g, ln1b);
    k_mlp1<<<dim3(MROWS/32, 2),    256, SM_GEMM>>>();
    k_mlp2<<<MROWS/32,             256, SM_GEMM>>>(ln2g, ln2b, x, out);
}

// round 14
// speedup vs baseline: 1.5373x; 1.0484x over previous
#include <cuda_runtime.h>
#include <cuda_fp16.h>
#include <cstdint>

#define BSZ 2
#define LQ 2048
#define DM 256
#define MROWS (BSZ*LQ)
#define SPLITS 2

// scratch
__device__ __half g_Qh[MROWS*DM];
__device__ __half g_Kh[MROWS*DM];
__device__ __half g_Vh[MROWS*DM];
__device__ __half g_Oh[MROWS*DM];
__device__ __half g_xs[MROWS*DM];     // x + xpe
__device__ __half g_ss[MROWS*DM];     // src + spe
__device__ __half g_sv[MROWS*DM];     // src
__device__ __half g_xp[MROWS*DM];     // x
__device__ __half g_msgh[MROWS*DM];
__device__ __half g_hidh[MROWS*2*DM];
__device__ __half g_Wqh[DM*DM];
__device__ __half g_Wkh[DM*DM];
__device__ __half g_Wvh[DM*DM];
__device__ __half g_Wmgh[DM*DM];
__device__ __half g_Wm1h[2*DM*2*DM];
__device__ __half g_Wm2h[2*DM*DM];
__device__ __half g_parth[SPLITS*MROWS*DM];
__device__ float g_pstat[SPLITS*MROWS*4*2];

// ---------------------------------------------------------------------------
__device__ __forceinline__ unsigned h2pk(float lo, float hi){
    unsigned r; asm("cvt.rn.f16x2.f32 %0, %1, %2;" : "=r"(r) : "f"(hi), "f"(lo)); return r;
}
__device__ __forceinline__ void ldsm4(unsigned* r, unsigned a){
    asm volatile("ldmatrix.sync.aligned.m8n8.x4.shared.b16 {%0,%1,%2,%3},[%4];"
        : "=r"(r[0]),"=r"(r[1]),"=r"(r[2]),"=r"(r[3]) : "r"(a));
}
__device__ __forceinline__ void ldsm4t(unsigned* r, unsigned a){
    asm volatile("ldmatrix.sync.aligned.m8n8.x4.trans.shared.b16 {%0,%1,%2,%3},[%4];"
        : "=r"(r[0]),"=r"(r[1]),"=r"(r[2]),"=r"(r[3]) : "r"(a));
}
__device__ __forceinline__ void mma16(float* c, const unsigned* a, const unsigned* b){
    asm volatile("mma.sync.aligned.m16n8k16.row.col.f32.f16.f16.f32 "
        "{%0,%1,%2,%3},{%4,%5,%6,%7},{%8,%9},{%0,%1,%2,%3};"
        : "+f"(c[0]), "+f"(c[1]), "+f"(c[2]), "+f"(c[3])
        : "r"(a[0]), "r"(a[1]), "r"(a[2]), "r"(a[3]), "r"(b[0]), "r"(b[1]));
}
__device__ __forceinline__ void cpa16(unsigned dst, const void* src){
    asm volatile("cp.async.cg.shared.global [%0], [%1], 16;" :: "r"(dst), "l"(src));
}
__device__ __forceinline__ void cpa4(unsigned dst, const void* src){
    asm volatile("cp.async.ca.shared.global [%0], [%1], 4;" :: "r"(dst), "l"(src));
}
#define CPA_COMMIT() asm volatile("cp.async.commit_group;" ::: "memory")
#define CPA_WAIT0()  asm volatile("cp.async.wait_group 0;" ::: "memory")

// e^x for x <= 0, FMA-pipe only. rel err ~2e-6.
__device__ __forceinline__ float fast_exp(float x){
    float y = x * 1.44269504f;
    y = fmaxf(y, -126.0f);
    float z = y + 12582912.0f;
    int   n = __float_as_int(z) - 0x4B400000;
    float f = y - (z - 12582912.0f);
    float p = 1.33336e-3f;
    p = fmaf(p, f, 9.61813e-3f);
    p = fmaf(p, f, 5.55041e-2f);
    p = fmaf(p, f, 2.40227e-1f);
    p = fmaf(p, f, 6.93147e-1f);
    p = fmaf(p, f, 1.0f);
    return p * __int_as_float((n + 127) << 23);
}

// ---------------------------------------------------------------------------
// prep: convert A-matrices and weights to fp16 once. Wq pre-scaled by 1/8
// (exact exponent shift; folds the softmax 1/sqrt(d) into the Q projection).
// ---------------------------------------------------------------------------
#define P_S0 262144L   // xs
#define P_S1 524288L   // ss
#define P_S2 786432L   // sv
#define P_S3 1048576L  // xp
#define P_S4 1064960L  // Wq
#define P_S5 1081344L  // Wk
#define P_S6 1097728L  // Wv
#define P_S7 1114112L  // Wmg
#define P_S8 1179648L  // Wm1
#define P_S9 1212416L  // Wm2 end
#define PREP_GRID ((P_S9 + 255) / 256)

__global__ void __launch_bounds__(256) k_prep(
    const float* x, const float* xpe, const float* src, const float* spe,
    const float* Wq, const float* Wk, const float* Wv, const float* Wmg,
    const float* Wm1, const float* Wm2)
{
    long i = (long)blockIdx.x*256 + threadIdx.x;
    if (i >= P_S9) return;
    float4 v; __half* dst;
    if (i < P_S0){
        float4 a = ((const float4*)x)[i], b = ((const float4*)xpe)[i];
        v = make_float4(a.x+b.x, a.y+b.y, a.z+b.z, a.w+b.w); dst = g_xs + i*4;
    } else if (i < P_S1){
        long j = i - P_S0;
        float4 a = ((const float4*)src)[j], b = ((const float4*)spe)[j];
        v = make_float4(a.x+b.x, a.y+b.y, a.z+b.z, a.w+b.w); dst = g_ss + j*4;
    } else if (i < P_S2){
        long j = i - P_S1; v = ((const float4*)src)[j]; dst = g_sv + j*4;
    } else if (i < P_S3){
        long j = i - P_S2; v = ((const float4*)x)[j]; dst = g_xp + j*4;
    } else if (i < P_S4){
        long j = i - P_S3; v = ((const float4*)Wq)[j];
        v.x *= 0.125f; v.y *= 0.125f; v.z *= 0.125f; v.w *= 0.125f;
        dst = g_Wqh + j*4;
    } else if (i < P_S5){
        long j = i - P_S4; v = ((const float4*)Wk)[j]; dst = g_Wkh + j*4;
    } else if (i < P_S6){
        long j = i - P_S5; v = ((const float4*)Wv)[j]; dst = g_Wvh + j*4;
    } else if (i < P_S7){
        long j = i - P_S6; v = ((const float4*)Wmg)[j]; dst = g_Wmgh + j*4;
    } else if (i < P_S8){
        long j = i - P_S7; v = ((const float4*)Wm1)[j]; dst = g_Wm1h + j*4;
    } else {
        long j = i - P_S8; v = ((const float4*)Wm2)[j]; dst = g_Wm2h + j*4;
    }
    *(uint2*)dst = make_uint2(h2pk(v.x, v.y), h2pk(v.z, v.w));
}

// ---------------------------------------------------------------------------
// all-fp16 GEMM: BM=32, BN=256, BK=32, 256 threads, cp.async double-buffered.
// ---------------------------------------------------------------------------
#define EPI_RELU  1
#define EPI_LNR   3
#define EPI_H16   4
#define EPI_LNH16 5

#define AS_H 40
#define BS_H 264
#define BUF_H (32*AS_H + 32*BS_H)
#define SM_GEMM (2*BUF_H*2)

template<int KD, bool CAT, int EPI>
__device__ __forceinline__ void gemm_h(
    const __half* __restrict__ A1, const __half* __restrict__ A2,
    const __half* __restrict__ Bw, int ldb, int n0,
    const float* __restrict__ gamma, const float* __restrict__ beta,
    const float* __restrict__ resid, void* __restrict__ Cv, int ldc)
{
    extern __shared__ unsigned char smraw[];
    const int KC = KD/32;
    int tid = threadIdx.x;
    int w = tid >> 5, lane = tid & 31;
    int wm = w >> 2, wn = w & 3;
    int g4 = lane >> 2, tig = lane & 3;
    int lrow = (lane & 7) + ((lane >> 3) & 1)*8;
    int lcol8 = (lane >> 4)*8;
    int row0 = blockIdx.x * 32;
    unsigned sb = (unsigned)__cvta_generic_to_shared(smraw);

    float acc[8][4];
    #pragma unroll
    for (int nt = 0; nt < 8; nt++)
        #pragma unroll
        for (int i = 0; i < 4; i++) acc[nt][i] = 0.f;

    auto issue = [&](int kc){
        unsigned ab = sb + ((kc & 1)*BUF_H)*2;
        unsigned bb = ab + 32*AS_H*2;
        if (tid < 128){
            int r = tid >> 2, c8 = (tid & 3) << 3;
            int col = kc*32 + c8;
            const __half* s;
            if (CAT) s = (col < 256) ? (A1 + (row0+r)*256 + col)
                                     : (A2 + (row0+r)*256 + (col - 256));
            else     s = A1 + (row0+r)*KD + col;
            cpa16(ab + (r*AS_H + c8)*2, s);
        }
        #pragma unroll
        for (int i = 0; i < 4; i++){
            int id = tid + i*256;
            int r = id >> 5, c8 = (id & 31) << 3;
            cpa16(bb + (r*BS_H + c8)*2, Bw + (kc*32 + r)*ldb + n0 + c8);
        }
    };

    issue(0); CPA_COMMIT();
    CPA_WAIT0(); __syncthreads();

    for (int kc = 0; kc < KC; kc++){
        if (kc + 1 < KC){ issue(kc+1); CPA_COMMIT(); }
        unsigned ab = sb + ((kc & 1)*BUF_H)*2;
        unsigned bb = ab + 32*AS_H*2;
        #pragma unroll
        for (int kk = 0; kk < 2; kk++){
            int k0 = kk*16;
            unsigned a[4];
            ldsm4(a, ab + ((wm*16 + lrow)*AS_H + k0 + lcol8)*2);
            #pragma unroll
            for (int j = 0; j < 4; j++){
                unsigned bv[4];
                ldsm4t(bv, bb + ((k0 + lrow)*BS_H + wn*64 + j*16 + lcol8)*2);
                unsigned b0[2] = {bv[0], bv[1]};
                unsigned b1[2] = {bv[2], bv[3]};
                mma16(acc[2*j],   a, b0);
                mma16(acc[2*j+1], a, b1);
            }
        }
        if (kc + 1 < KC){ CPA_WAIT0(); __syncthreads(); }
    }

    if (EPI == EPI_H16 || EPI == EPI_RELU){
        __half* C = (__half*)Cv;
        int rl = row0 + wm*16 + g4;
        #pragma unroll
        for (int nt = 0; nt < 8; nt++){
            int col = n0 + wn*64 + nt*8 + 2*tig;
            float v0 = acc[nt][0], v1 = acc[nt][1];
            float v2 = acc[nt][2], v3 = acc[nt][3];
            if (EPI == EPI_RELU){
                v0=fmaxf(v0,0.f); v1=fmaxf(v1,0.f); v2=fmaxf(v2,0.f); v3=fmaxf(v3,0.f);
            }
            *(unsigned*)(C + rl*ldc + col)     = h2pk(v0, v1);
            *(unsigned*)(C + (rl+8)*ldc + col) = h2pk(v2, v3);
        }
    } else {   // EPI_LNR / EPI_LNH16
        __syncthreads();
        float2* red = (float2*)smraw;    // red[32][4]
        float s1[2] = {0,0}, s2[2] = {0,0};
        #pragma unroll
        for (int nt = 0; nt < 8; nt++){
            float c0=acc[nt][0], c1=acc[nt][1], c2=acc[nt][2], c3=acc[nt][3];
            s1[0] += c0+c1; s2[0] += c0*c0 + c1*c1;
            s1[1] += c2+c3; s2[1] += c2*c2 + c3*c3;
        }
        #pragma unroll
        for (int hb = 0; hb < 2; hb++){
            float v1 = s1[hb], v2 = s2[hb];
            v1 += __shfl_xor_sync(~0u, v1, 1); v1 += __shfl_xor_sync(~0u, v1, 2);
            v2 += __shfl_xor_sync(~0u, v2, 1); v2 += __shfl_xor_sync(~0u, v2, 2);
            if (tig == 0){
                int r = wm*16 + g4 + hb*8;
                red[r*4 + wn] = make_float2(v1, v2);
            }
        }
        __syncthreads();
        #pragma unroll
        for (int hb = 0; hb < 2; hb++){
            int r = wm*16 + g4 + hb*8;
            float S1 = 0.f, S2 = 0.f;
            #pragma unroll
            for (int j = 0; j < 4; j++){ float2 e = red[r*4+j]; S1 += e.x; S2 += e.y; }
            float mean = S1 * (1.f/256.f);
            float var  = S2 * (1.f/256.f) - mean*mean;
            float inv  = rsqrtf(var + 1e-5f);
            int grow = row0 + r;
            #pragma unroll
            for (int nt = 0; nt < 8; nt++){
                int col = wn*64 + nt*8 + 2*tig;
                float c0 = acc[nt][hb*2], c1 = acc[nt][hb*2+1];
                float o0 = (c0 - mean)*inv*gamma[col]   + beta[col];
                float o1 = (c1 - mean)*inv*gamma[col+1] + beta[col+1];
                if (EPI == EPI_LNR){
                    float* C = (float*)Cv;
                    o0 += resid[grow*256 + col];
                    o1 += resid[grow*256 + col + 1];
                    *(float2*)(C + grow*ldc + col) = make_float2(o0, o1);
                } else {
                    __half* C = (__half*)Cv;
                    *(unsigned*)(C + grow*ldc + col) = h2pk(o0, o1);
                }
            }
        }
    }
}

__global__ void __launch_bounds__(256) k_qkv(){
    if (blockIdx.z == 0)      gemm_h<256, false, EPI_H16>(g_xs, 0, g_Wqh, 256, 0, 0,0,0, g_Qh, 256);
    else if (blockIdx.z == 1) gemm_h<256, false, EPI_H16>(g_ss, 0, g_Wkh, 256, 0, 0,0,0, g_Kh, 256);
    else                      gemm_h<256, false, EPI_H16>(g_sv, 0, g_Wvh, 256, 0, 0,0,0, g_Vh, 256);
}
__global__ void __launch_bounds__(256) k_merge(const float* gg, const float* bb){
    gemm_h<256, false, EPI_LNH16>(g_Oh, 0, g_Wmgh, 256, 0, gg, bb, 0, g_msgh, 256);
}
__global__ void __launch_bounds__(256) k_mlp1(){
    gemm_h<512, true, EPI_RELU>(g_xp, g_msgh, g_Wm1h, 512, blockIdx.y*256, 0,0,0, g_hidh, 512);
}
__global__ void __launch_bounds__(256) k_mlp2(const float* gg, const float* bb,
                                              const float* x, float* out){
    gemm_h<512, false, EPI_LNR>(g_hidh, 0, g_Wm2h, 256, 0, gg, bb, x, out, 256);
}

// ---------------------------------------------------------------------------
// attnmerge: one thread per 8-col head segment -> pstat loads amortized 4x,
// uint4 loads/stores. grid = MROWS/8 blocks of 256.
// ---------------------------------------------------------------------------
__global__ void __launch_bounds__(256) k_attnmerge(){
    long idx = (long)blockIdx.x*256 + threadIdx.x;   // MROWS*32 threads
    long r = idx >> 5;
    int seg = (int)(idx & 31);
    int c = seg * 8;
    int h = c >> 6;
    float m0 = g_pstat[((0L*MROWS + r)*4 + h)*2];
    float s0 = g_pstat[((0L*MROWS + r)*4 + h)*2 + 1];
    float m1 = g_pstat[((1L*MROWS + r)*4 + h)*2];
    float s1 = g_pstat[((1L*MROWS + r)*4 + h)*2 + 1];
    float M = fmaxf(m0, m1);
    float w0 = fast_exp(m0 - M), w1 = fast_exp(m1 - M);
    float inv = 1.0f/(s0*w0 + s1*w1);
    w0 *= inv; w1 *= inv;
    uint4 q0 = *(const uint4*)(g_parth + (0L*MROWS + r)*256 + c);
    uint4 q1 = *(const uint4*)(g_parth + (1L*MROWS + r)*256 + c);
    const __half2* h0 = (const __half2*)&q0;
    const __half2* h1 = (const __half2*)&q1;
    uint4 out;
    unsigned* ou = (unsigned*)&out;
    #pragma unroll
    for (int i = 0; i < 4; i++){
        float2 a = __half22float2(h0[i]);
        float2 b = __half22float2(h1[i]);
        ou[i] = h2pk(a.x*w0 + b.x*w1, a.y*w0 + b.y*w1);
    }
    *(uint4*)(g_Oh + r*256 + c) = out;
}

// ---------------------------------------------------------------------------
// Flash attention v10: BM=64, 512 threads; cp.async double-buffered
// K/V/comp/mask; register P (FA2); Q FRAGMENTS HOISTED TO REGISTERS
// (1/8 scale pre-folded into Wq). fp16 partials out.
// ---------------------------------------------------------------------------
#define QH 264
#define CS_STR 36
// half offsets
#define AT_K   16896              // K bufs 2x8448
#define AT_V   33792              // V bufs 2x8448
// byte offsets
#define AT_CB  101376             // Cs: 2 x 64 x 36 floats
#define AT_SMS 119808             // sms: 2 x 32 ints
#define AT_XM  120064             // xm: 64 ints
#define ATTN_BYTES 120320

__device__ __forceinline__ void attn_issue_tile(
    const __half* __restrict__ Km, const __half* __restrict__ Vm,
    const float* __restrict__ comp, const int* __restrict__ smask,
    unsigned sb, int buf, int b, int l0, int s0, int tid)
{
    unsigned kdst = sb + (AT_K + buf*8448)*2;
    unsigned vdst = sb + (AT_V + buf*8448)*2;
    #pragma unroll
    for (int i = 0; i < 2; i++){
        int id = tid + i*512;
        int r = id >> 5, c8 = (id & 31) << 3;
        long grow = (long)(b*LQ + s0 + r)*256 + c8;
        cpa16(kdst + (r*QH + c8)*2, Km + grow);
        cpa16(vdst + (r*QH + c8)*2, Vm + grow);
    }
    {
        int r = tid >> 3, c4 = (tid & 7) << 2;
        unsigned cdst = sb + AT_CB + buf*(64*CS_STR*4) + (r*CS_STR + c4)*4;
        cpa16(cdst, comp + (long)(b*LQ + l0 + r)*LQ + s0 + c4);
    }
    if (tid < 32)
        cpa4(sb + AT_SMS + buf*128 + tid*4, smask + b*LQ + s0 + tid);
}

__global__ void __launch_bounds__(512, 1) k_attn(
    const __half* __restrict__ Qm, const __half* __restrict__ Km, const __half* __restrict__ Vm,
    const float* __restrict__ comp, const int* __restrict__ xmask, const int* __restrict__ smask)
{
    extern __shared__ unsigned char smraw[];
    __half* smh = (__half*)smraw;
    __half* Qh = smh;
    float*  CsBase = (float*)(smraw + AT_CB);
    int*    smsBase = (int*)(smraw + AT_SMS);
    int*    xm = (int*)(smraw + AT_XM);

    int tid = threadIdx.x;
    int w = tid >> 5, lane = tid & 31;
    int h = w & 3, wm = w >> 2;
    int g4 = lane >> 2, tig = lane & 3;
    int lrow = (lane & 7) + ((lane >> 3) & 1)*8;
    int lcol8 = (lane >> 4)*8;
    int l0 = blockIdx.x * 64;
    int sp = blockIdx.y, b = blockIdx.z;
    int dbase = h*64;

    unsigned sb = (unsigned)__cvta_generic_to_shared(smh);
    unsigned qb = sb;

    int sbase = sp*(LQ/SPLITS);
    attn_issue_tile(Km, Vm, comp, smask, sb, 0, b, l0, sbase, tid);
    CPA_COMMIT();

    // stage Q (64x256 halves, pure copy; 1/8 folded into Wq)
    #pragma unroll
    for (int i = 0; i < 4; i++){
        int id = tid + i*512;
        int r = id >> 5, c8 = (id & 31) << 3;
        *(uint4*)&Qh[r*QH + c8] = *(const uint4*)(Qm + (b*LQ + l0 + r)*256 + c8);
    }
    if (tid < 64) xm[tid] = xmask[b*LQ + l0 + tid];

    float o[8][4];
    #pragma unroll
    for (int nt = 0; nt < 8; nt++)
        #pragma unroll
        for (int i = 0; i < 4; i++) o[nt][i] = 0.f;
    float rmax[2] = {-1e30f, -1e30f};
    float rsum[2] = {0.f, 0.f};

    CPA_WAIT0();
    __syncthreads();

    // hoist Q A-fragments to registers (invariant over the KV loop)
    unsigned qa[4][4];
    #pragma unroll
    for (int kk = 0; kk < 4; kk++)
        ldsm4(qa[kk], qb + ((wm*16 + lrow)*QH + dbase + kk*16 + lcol8)*2);

    int rl = wm*16 + g4;
    const int NT = (LQ/SPLITS)/32;
    for (int t = 0; t < NT; t++){
        int buf = t & 1;
        unsigned kb = sb + (AT_K + buf*8448)*2;
        unsigned vb = sb + (AT_V + buf*8448)*2;
        float* Cs = CsBase + buf*(64*CS_STR);
        int*   sms = smsBase + buf*32;

        if (t + 1 < NT){
            attn_issue_tile(Km, Vm, comp, smask, sb, buf^1, b, l0, sbase + (t+1)*32, tid);
            CPA_COMMIT();
        }

        // ---- QK^T: S[16l x 32s] per warp ----
        float S[4][4];
        #pragma unroll
        for (int nt = 0; nt < 4; nt++)
            #pragma unroll
            for (int i = 0; i < 4; i++) S[nt][i] = 0.f;
        #pragma unroll
        for (int kk = 0; kk < 4; kk++){
            int k0 = dbase + kk*16;
            #pragma unroll
            for (int sh = 0; sh < 2; sh++){
                unsigned bk[4];
                ldsm4(bk, kb + ((sh*16 + lrow)*QH + k0 + lcol8)*2);
                unsigned b0[2] = {bk[0], bk[2]};
                unsigned b1[2] = {bk[1], bk[3]};
                mma16(S[sh*2],   qa[kk], b0);
                mma16(S[sh*2+1], qa[kk], b1);
            }
        }

        // ---- softmax; P packed straight into A-fragment registers ----
        int xml = xm[rl], xmh = xm[rl + 8];
        float tmaxl = -1e30f, tmaxh = -1e30f;
        #pragma unroll
        for (int nt = 0; nt < 4; nt++){
            int se = nt*8 + 2*tig, so = se + 1;
            int mse = sms[se], mso = sms[so];
            float ce = Cs[rl*CS_STR + se],      co = Cs[rl*CS_STR + so];
            float de = Cs[(rl+8)*CS_STR + se],  dox = Cs[(rl+8)*CS_STR + so];
            float v0 = (xml && !mse) ? -1e30f : S[nt][0]*ce;
            float v1 = (xml && !mso) ? -1e30f : S[nt][1]*co;
            float v2 = (xmh && !mse) ? -1e30f : S[nt][2]*de;
            float v3 = (xmh && !mso) ? -1e30f : S[nt][3]*dox;
            S[nt][0]=v0; S[nt][1]=v1; S[nt][2]=v2; S[nt][3]=v3;
            tmaxl = fmaxf(tmaxl, fmaxf(v0, v1));
            tmaxh = fmaxf(tmaxh, fmaxf(v2, v3));
        }
        tmaxl = fmaxf(tmaxl, __shfl_xor_sync(~0u, tmaxl, 1));
        tmaxl = fmaxf(tmaxl, __shfl_xor_sync(~0u, tmaxl, 2));
        tmaxh = fmaxf(tmaxh, __shfl_xor_sync(~0u, tmaxh, 1));
        tmaxh = fmaxf(tmaxh, __shfl_xor_sync(~0u, tmaxh, 2));
        float ml = fmaxf(rmax[0], tmaxl), mh = fmaxf(rmax[1], tmaxh);
        float al = fast_exp(rmax[0] - ml), ah = fast_exp(rmax[1] - mh);
        rmax[0] = ml; rmax[1] = mh;
        float tsl = 0.f, tsh = 0.f;
        unsigned Pa[4][2];
        #pragma unroll
        for (int nt = 0; nt < 4; nt++){
            float p0 = fast_exp(S[nt][0] - ml);
            float p1 = fast_exp(S[nt][1] - ml);
            float p2 = fast_exp(S[nt][2] - mh);
            float p3 = fast_exp(S[nt][3] - mh);
            tsl += p0 + p1; tsh += p2 + p3;
            Pa[nt][0] = h2pk(p0, p1);
            Pa[nt][1] = h2pk(p2, p3);
        }
        tsl += __shfl_xor_sync(~0u, tsl, 1); tsl += __shfl_xor_sync(~0u, tsl, 2);
        tsh += __shfl_xor_sync(~0u, tsh, 1); tsh += __shfl_xor_sync(~0u, tsh, 2);
        rsum[0] = rsum[0]*al + tsl;
        rsum[1] = rsum[1]*ah + tsh;
        #pragma unroll
        for (int nt = 0; nt < 8; nt++){
            o[nt][0] *= al; o[nt][1] *= al;
            o[nt][2] *= ah; o[nt][3] *= ah;
        }

        // ---- P @ V: A-frag = packed S fragments ----
        #pragma unroll
        for (int kk = 0; kk < 2; kk++){
            unsigned a[4] = {Pa[kk*2][0], Pa[kk*2][1], Pa[kk*2+1][0], Pa[kk*2+1][1]};
            #pragma unroll
            for (int j = 0; j < 4; j++){
                unsigned bv[4];
                ldsm4t(bv, vb + ((kk*16 + lrow)*QH + dbase + j*16 + lcol8)*2);
                unsigned b0[2] = {bv[0], bv[1]};
                unsigned b1[2] = {bv[2], bv[3]};
                mma16(o[2*j],   a, b0);
                mma16(o[2*j+1], a, b1);
            }
        }

        if (t + 1 < NT){
            CPA_WAIT0();
            __syncthreads();
        }
    }

    // ---- write unnormalized fp16 partials + stats ----
    long prow = (long)(sp*MROWS + b*LQ + l0 + rl);
    #pragma unroll
    for (int nt = 0; nt < 8; nt++){
        int col = dbase + nt*8 + 2*tig;
        *(unsigned*)(g_parth + prow*256 + col)     = h2pk(o[nt][0], o[nt][1]);
        *(unsigned*)(g_parth + (prow+8)*256 + col) = h2pk(o[nt][2], o[nt][3]);
    }
    if (tig == 0){
        long base = (prow*4 + h)*2;
        g_pstat[base]   = rmax[0];
        g_pstat[base+1] = rsum[0];
        long baseh = ((prow+8)*4 + h)*2;
        g_pstat[baseh]   = rmax[1];
        g_pstat[baseh+1] = rsum[1];
    }
}

// ---------------------------------------------------------------------------
extern "C" void kernel_launch(void* const* d_in, const int* in_sizes, int n_in,
                              void* d_out, int out_size)
{
    const float* x    = (const float*)d_in[0];
    const float* src  = (const float*)d_in[1];
    const float* xpe  = (const float*)d_in[2];
    const float* spe  = (const float*)d_in[3];
    const int* xmask  = (const int*)d_in[4];
    const int* smask  = (const int*)d_in[5];
    const float* comp = (const float*)d_in[6];
    const float* Wq   = (const float*)d_in[7];
    const float* Wk   = (const float*)d_in[8];
    const float* Wv   = (const float*)d_in[9];
    const float* Wmg  = (const float*)d_in[10];
    const float* Wm1  = (const float*)d_in[11];
    const float* Wm2  = (const float*)d_in[12];
    const float* ln1g = (const float*)d_in[13];
    const float* ln1b = (const float*)d_in[14];
    const float* ln2g = (const float*)d_in[15];
    const float* ln2b = (const float*)d_in[16];
    float* out = (float*)d_out;

    __half *Qp, *Kp, *Vp;
    cudaGetSymbolAddress((void**)&Qp, g_Qh);
    cudaGetSymbolAddress((void**)&Kp, g_Kh);
    cudaGetSymbolAddress((void**)&Vp, g_Vh);

    cudaFuncSetAttribute(k_attn, cudaFuncAttributeMaxDynamicSharedMemorySize, ATTN_BYTES);

    k_prep<<<(int)PREP_GRID, 256>>>(x, xpe, src, spe, Wq, Wk, Wv, Wmg, Wm1, Wm2);
    k_qkv <<<dim3(MROWS/32, 1, 3), 256, SM_GEMM>>>();
    k_attn<<<dim3(LQ/64, SPLITS, BSZ), 512, ATTN_BYTES>>>(Qp, Kp, Vp, comp, xmask, smask);
    k_attnmerge<<<MROWS/8, 256>>>();
    k_merge<<<MROWS/32,            256, SM_GEMM>>>(ln1g, ln1b);
    k_mlp1<<<dim3(MROWS/32, 2),    256, SM_GEMM>>>();
    k_mlp2<<<MROWS/32,             256, SM_GEMM>>>(ln2g, ln2b, x, out);
}

// round 16
// speedup vs baseline: 1.5668x; 1.0192x over previous
#include <cuda_runtime.h>
#include <cuda_fp16.h>
#include <cstdint>

#define BSZ 2
#define LQ 2048
#define DM 256
#define MROWS (BSZ*LQ)
#define SPLITS 2

// scratch
__device__ __half g_Qh[MROWS*DM];
__device__ __half g_Kh[MROWS*DM];
__device__ __half g_Vh[MROWS*DM];
__device__ __half g_msgh[MROWS*DM];
__device__ __half g_hidh[MROWS*2*DM];
__device__ __half g_Wqh[DM*DM];
__device__ __half g_Wkh[DM*DM];
__device__ __half g_Wvh[DM*DM];
__device__ __half g_Wmgh[DM*DM];
__device__ __half g_Wm1h[2*DM*2*DM];
__device__ __half g_Wm2h[2*DM*DM];
__device__ __half g_parth[SPLITS*MROWS*DM];
__device__ float g_pstat[SPLITS*MROWS*4*2];

// ---------------------------------------------------------------------------
__device__ __forceinline__ unsigned h2pk(float lo, float hi){
    unsigned r; asm("cvt.rn.f16x2.f32 %0, %1, %2;" : "=r"(r) : "f"(hi), "f"(lo)); return r;
}
__device__ __forceinline__ void ldsm4(unsigned* r, unsigned a){
    asm volatile("ldmatrix.sync.aligned.m8n8.x4.shared.b16 {%0,%1,%2,%3},[%4];"
        : "=r"(r[0]),"=r"(r[1]),"=r"(r[2]),"=r"(r[3]) : "r"(a));
}
__device__ __forceinline__ void ldsm4t(unsigned* r, unsigned a){
    asm volatile("ldmatrix.sync.aligned.m8n8.x4.trans.shared.b16 {%0,%1,%2,%3},[%4];"
        : "=r"(r[0]),"=r"(r[1]),"=r"(r[2]),"=r"(r[3]) : "r"(a));
}
__device__ __forceinline__ void mma16(float* c, const unsigned* a, const unsigned* b){
    asm volatile("mma.sync.aligned.m16n8k16.row.col.f32.f16.f16.f32 "
        "{%0,%1,%2,%3},{%4,%5,%6,%7},{%8,%9},{%0,%1,%2,%3};"
        : "+f"(c[0]), "+f"(c[1]), "+f"(c[2]), "+f"(c[3])
        : "r"(a[0]), "r"(a[1]), "r"(a[2]), "r"(a[3]), "r"(b[0]), "r"(b[1]));
}
__device__ __forceinline__ void cpa16(unsigned dst, const void* src){
    asm volatile("cp.async.cg.shared.global [%0], [%1], 16;" :: "r"(dst), "l"(src));
}
__device__ __forceinline__ void cpa4(unsigned dst, const void* src){
    asm volatile("cp.async.ca.shared.global [%0], [%1], 4;" :: "r"(dst), "l"(src));
}
#define CPA_COMMIT() asm volatile("cp.async.commit_group;" ::: "memory")
#define CPA_WAIT0()  asm volatile("cp.async.wait_group 0;" ::: "memory")

// e^x for x <= 0, FMA-pipe only. rel err ~2e-6.
__device__ __forceinline__ float fast_exp(float x){
    float y = x * 1.44269504f;
    y = fmaxf(y, -126.0f);
    float z = y + 12582912.0f;
    int   n = __float_as_int(z) - 0x4B400000;
    float f = y - (z - 12582912.0f);
    float p = 1.33336e-3f;
    p = fmaf(p, f, 9.61813e-3f);
    p = fmaf(p, f, 5.55041e-2f);
    p = fmaf(p, f, 2.40227e-1f);
    p = fmaf(p, f, 6.93147e-1f);
    p = fmaf(p, f, 1.0f);
    return p * __int_as_float((n + 127) << 23);
}

// ---------------------------------------------------------------------------
// prep: convert WEIGHTS ONLY to fp16. Wq pre-scaled by 1/8 (exact).
// ---------------------------------------------------------------------------
#define W_S0 16384L    // Wq
#define W_S1 32768L    // Wk
#define W_S2 49152L    // Wv
#define W_S3 65536L    // Wmg
#define W_S4 131072L   // Wm1
#define W_S5 163840L   // Wm2 end
#define PREP_GRID ((W_S5 + 255) / 256)

__global__ void __launch_bounds__(256) k_prep(
    const float* Wq, const float* Wk, const float* Wv, const float* Wmg,
    const float* Wm1, const float* Wm2)
{
    long i = (long)blockIdx.x*256 + threadIdx.x;
    if (i >= W_S5) return;
    float4 v; __half* dst;
    if (i < W_S0){
        v = ((const float4*)Wq)[i];
        v.x *= 0.125f; v.y *= 0.125f; v.z *= 0.125f; v.w *= 0.125f;
        dst = g_Wqh + i*4;
    } else if (i < W_S1){
        long j = i - W_S0; v = ((const float4*)Wk)[j]; dst = g_Wkh + j*4;
    } else if (i < W_S2){
        long j = i - W_S1; v = ((const float4*)Wv)[j]; dst = g_Wvh + j*4;
    } else if (i < W_S3){
        long j = i - W_S2; v = ((const float4*)Wmg)[j]; dst = g_Wmgh + j*4;
    } else if (i < W_S4){
        long j = i - W_S3; v = ((const float4*)Wm1)[j]; dst = g_Wm1h + j*4;
    } else {
        long j = i - W_S4; v = ((const float4*)Wm2)[j]; dst = g_Wm2h + j*4;
    }
    *(uint2*)dst = make_uint2(h2pk(v.x, v.y), h2pk(v.z, v.w));
}

// ---------------------------------------------------------------------------
// fp16 GEMM: BM=32, BN=256, BK=32, 256 threads; B via cp.async double-buffer;
// A modes: fp32 LDG+cvt (F32/F32ADD/CATFH) or fp16 cp.async (H16).
// ---------------------------------------------------------------------------
#define AM_F32    0
#define AM_F32ADD 1
#define AM_CATFH  2
#define AM_H16    3
#define EPI_RELU  1
#define EPI_LNR   3
#define EPI_H16   4

#define AS_H 40
#define BS_H 264
#define BUF_H (32*AS_H + 32*BS_H)
#define SM_GEMM (2*BUF_H*2)

template<int KD, int AM, int EPI>
__device__ __forceinline__ void gemm_h(
    const float* __restrict__ Af, const float* __restrict__ Af2,
    const __half* __restrict__ Ah,
    const __half* __restrict__ Bw, int ldb, int n0,
    const float* __restrict__ gamma, const float* __restrict__ beta,
    const float* __restrict__ resid, void* __restrict__ Cv, int ldc)
{
    extern __shared__ unsigned char smraw[];
    const int KC = KD/32;
    int tid = threadIdx.x;
    int w = tid >> 5, lane = tid & 31;
    int wm = w >> 2, wn = w & 3;
    int g4 = lane >> 2, tig = lane & 3;
    int lrow = (lane & 7) + ((lane >> 3) & 1)*8;
    int lcol8 = (lane >> 4)*8;
    int row0 = blockIdx.x * 32;
    unsigned sb = (unsigned)__cvta_generic_to_shared(smraw);

    float acc[8][4];
    #pragma unroll
    for (int nt = 0; nt < 8; nt++)
        #pragma unroll
        for (int i = 0; i < 4; i++) acc[nt][i] = 0.f;

    auto issueB = [&](int kc){
        unsigned ab = sb + ((kc & 1)*BUF_H)*2;
        unsigned bb = ab + 32*AS_H*2;
        if (AM == AM_H16 && tid < 128){
            int r = tid >> 2, c8 = (tid & 3) << 3;
            cpa16(ab + (r*AS_H + c8)*2, Ah + (row0+r)*KD + kc*32 + c8);
        }
        #pragma unroll
        for (int i = 0; i < 4; i++){
            int id = tid + i*256;
            int r = id >> 5, c8 = (id & 31) << 3;
            cpa16(bb + (r*BS_H + c8)*2, Bw + (kc*32 + r)*ldb + n0 + c8);
        }
    };

    float4 pa; uint2 pah; bool alow = true;
    auto ldgA = [&](int kc){
        if (AM == AM_H16) return;
        int r = tid >> 3, c4 = (tid & 7) << 2;
        int col = kc*32 + c4;
        if (AM == AM_F32){
            pa = *(const float4*)(Af + (row0+r)*KD + col);
        } else if (AM == AM_F32ADD){
            float4 a = *(const float4*)(Af  + (row0+r)*KD + col);
            float4 b = *(const float4*)(Af2 + (row0+r)*KD + col);
            pa = make_float4(a.x+b.x, a.y+b.y, a.z+b.z, a.w+b.w);
        } else { // CATFH
            alow = col < 256;
            if (alow) pa = *(const float4*)(Af + (row0+r)*256 + col);
            else      pah = *(const uint2*)(Ah + (row0+r)*256 + (col - 256));
        }
    };
    auto stsA = [&](int kc){
        if (AM == AM_H16) return;
        __half* Ab = (__half*)smraw + (kc & 1)*BUF_H;
        int r = tid >> 3, c4 = (tid & 7) << 2;
        uint2 u;
        if (AM == AM_CATFH && !alow) u = pah;
        else u = make_uint2(h2pk(pa.x, pa.y), h2pk(pa.z, pa.w));
        *(uint2*)&Ab[r*AS_H + c4] = u;
    };

    ldgA(0);
    issueB(0); CPA_COMMIT();
    stsA(0);
    CPA_WAIT0(); __syncthreads();

    for (int kc = 0; kc < KC; kc++){
        if (kc + 1 < KC){ issueB(kc+1); CPA_COMMIT(); ldgA(kc+1); }
        unsigned ab = sb + ((kc & 1)*BUF_H)*2;
        unsigned bb = ab + 32*AS_H*2;
        #pragma unroll
        for (int kk = 0; kk < 2; kk++){
            int k0 = kk*16;
            unsigned a[4];
            ldsm4(a, ab + ((wm*16 + lrow)*AS_H + k0 + lcol8)*2);
            #pragma unroll
            for (int j = 0; j < 4; j++){
                unsigned bv[4];
                ldsm4t(bv, bb + ((k0 + lrow)*BS_H + wn*64 + j*16 + lcol8)*2);
                unsigned b0[2] = {bv[0], bv[1]};
                unsigned b1[2] = {bv[2], bv[3]};
                mma16(acc[2*j],   a, b0);
                mma16(acc[2*j+1], a, b1);
            }
        }
        if (kc + 1 < KC){ stsA(kc+1); CPA_WAIT0(); __syncthreads(); }
    }

    if (EPI == EPI_H16 || EPI == EPI_RELU){
        __half* C = (__half*)Cv;
        int rl = row0 + wm*16 + g4;
        #pragma unroll
        for (int nt = 0; nt < 8; nt++){
            int col = n0 + wn*64 + nt*8 + 2*tig;
            float v0 = acc[nt][0], v1 = acc[nt][1];
            float v2 = acc[nt][2], v3 = acc[nt][3];
            if (EPI == EPI_RELU){
                v0=fmaxf(v0,0.f); v1=fmaxf(v1,0.f); v2=fmaxf(v2,0.f); v3=fmaxf(v3,0.f);
            }
            *(unsigned*)(C + rl*ldc + col)     = h2pk(v0, v1);
            *(unsigned*)(C + (rl+8)*ldc + col) = h2pk(v2, v3);
        }
    } else {   // EPI_LNR: LayerNorm + residual, fp32 out
        float* C = (float*)Cv;
        __syncthreads();
        float2* red = (float2*)smraw;
        float s1[2] = {0,0}, s2[2] = {0,0};
        #pragma unroll
        for (int nt = 0; nt < 8; nt++){
            float c0=acc[nt][0], c1=acc[nt][1], c2=acc[nt][2], c3=acc[nt][3];
            s1[0] += c0+c1; s2[0] += c0*c0 + c1*c1;
            s1[1] += c2+c3; s2[1] += c2*c2 + c3*c3;
        }
        #pragma unroll
        for (int hb = 0; hb < 2; hb++){
            float v1 = s1[hb], v2 = s2[hb];
            v1 += __shfl_xor_sync(~0u, v1, 1); v1 += __shfl_xor_sync(~0u, v1, 2);
            v2 += __shfl_xor_sync(~0u, v2, 1); v2 += __shfl_xor_sync(~0u, v2, 2);
            if (tig == 0){
                int r = wm*16 + g4 + hb*8;
                red[r*4 + wn] = make_float2(v1, v2);
            }
        }
        __syncthreads();
        #pragma unroll
        for (int hb = 0; hb < 2; hb++){
            int r = wm*16 + g4 + hb*8;
            float S1 = 0.f, S2 = 0.f;
            #pragma unroll
            for (int j = 0; j < 4; j++){ float2 e = red[r*4+j]; S1 += e.x; S2 += e.y; }
            float mean = S1 * (1.f/256.f);
            float var  = S2 * (1.f/256.f) - mean*mean;
            float inv  = rsqrtf(var + 1e-5f);
            int grow = row0 + r;
            #pragma unroll
            for (int nt = 0; nt < 8; nt++){
                int col = wn*64 + nt*8 + 2*tig;
                float c0 = acc[nt][hb*2], c1 = acc[nt][hb*2+1];
                float o0 = (c0 - mean)*inv*gamma[col]   + beta[col] + resid[grow*256 + col];
                float o1 = (c1 - mean)*inv*gamma[col+1] + beta[col+1] + resid[grow*256 + col + 1];
                *(float2*)(C + grow*ldc + col) = make_float2(o0, o1);
            }
        }
    }
}

__global__ void __launch_bounds__(256) k_qkv(
    const float* x, const float* xpe, const float* src, const float* spe)
{
    if (blockIdx.z == 0)      gemm_h<256, AM_F32ADD, EPI_H16>(x,   xpe, 0, g_Wqh, 256, 0, 0,0,0, g_Qh, 256);
    else if (blockIdx.z == 1) gemm_h<256, AM_F32ADD, EPI_H16>(src, spe, 0, g_Wkh, 256, 0, 0,0,0, g_Kh, 256);
    else                      gemm_h<256, AM_F32,    EPI_H16>(src, 0,   0, g_Wvh, 256, 0, 0,0,0, g_Vh, 256);
}
__global__ void __launch_bounds__(256) k_mlp1(const float* x){
    gemm_h<512, AM_CATFH, EPI_RELU>(x, 0, g_msgh, g_Wm1h, 512, blockIdx.y*256, 0,0,0, g_hidh, 512);
}
__global__ void __launch_bounds__(256) k_mlp2(const float* gg, const float* bb,
                                              const float* x, float* out){
    gemm_h<512, AM_H16, EPI_LNR>(0, 0, g_hidh, g_Wm2h, 256, 0, gg, bb, x, out, 256);
}

// ---------------------------------------------------------------------------
// k_merge: fused split-KV merge + GEMM + LN -> fp16 g_msgh.
// A (merged partials) staged ONCE into persistent smem; mainloop streams B.
// ---------------------------------------------------------------------------
#define MA_STR 264
#define MA_H   (32*MA_STR)                  // 8448 halves
#define SM_MERGE ((MA_H + 2*32*BS_H)*2)     // 50688 bytes (needs attribute!)

__global__ void __launch_bounds__(256) k_merge(const float* __restrict__ gamma,
                                               const float* __restrict__ beta)
{
    extern __shared__ unsigned char smraw[];
    __half* Areg = (__half*)smraw;
    int tid = threadIdx.x;
    int w = tid >> 5, lane = tid & 31;
    int wm = w >> 2, wn = w & 3;
    int g4 = lane >> 2, tig = lane & 3;
    int lrow = (lane & 7) + ((lane >> 3) & 1)*8;
    int lcol8 = (lane >> 4)*8;
    int row0 = blockIdx.x * 32;
    unsigned sb = (unsigned)__cvta_generic_to_shared(smraw);

    auto issueB = [&](int kc){
        unsigned bb = sb + (MA_H + (kc & 1)*32*BS_H)*2;
        #pragma unroll
        for (int i = 0; i < 4; i++){
            int id = tid + i*256;
            int r = id >> 5, c8 = (id & 31) << 3;
            cpa16(bb + (r*BS_H + c8)*2, g_Wmgh + (kc*32 + r)*256 + c8);
        }
    };

    issueB(0); CPA_COMMIT();

    // merge split partials into Areg (one pass, overlapped with B(0))
    {
        int r = tid >> 3, c0 = (tid & 7) * 32;
        long gr = row0 + r;
        int hh = c0 >> 6;
        float2 ms0 = *(const float2*)&g_pstat[((0L*MROWS + gr)*4 + hh)*2];
        float2 ms1 = *(const float2*)&g_pstat[((1L*MROWS + gr)*4 + hh)*2];
        float M = fmaxf(ms0.x, ms1.x);
        float w0 = fast_exp(ms0.x - M), w1 = fast_exp(ms1.x - M);
        float inv = 1.0f/(ms0.y*w0 + ms1.y*w1);
        w0 *= inv; w1 *= inv;
        #pragma unroll
        for (int i = 0; i < 4; i++){
            uint4 q0 = *(const uint4*)(g_parth + (0L*MROWS + gr)*256 + c0 + i*8);
            uint4 q1 = *(const uint4*)(g_parth + (1L*MROWS + gr)*256 + c0 + i*8);
            const __half2* p0 = (const __half2*)&q0;
            const __half2* p1 = (const __half2*)&q1;
            uint4 o; unsigned* ou = (unsigned*)&o;
            #pragma unroll
            for (int j = 0; j < 4; j++){
                float2 a = __half22float2(p0[j]);
                float2 b = __half22float2(p1[j]);
                ou[j] = h2pk(a.x*w0 + b.x*w1, a.y*w0 + b.y*w1);
            }
            *(uint4*)&Areg[r*MA_STR + c0 + i*8] = o;
        }
    }
    CPA_WAIT0(); __syncthreads();

    float acc[8][4];
    #pragma unroll
    for (int nt = 0; nt < 8; nt++)
        #pragma unroll
        for (int i = 0; i < 4; i++) acc[nt][i] = 0.f;

    for (int kc = 0; kc < 8; kc++){
        if (kc + 1 < 8){ issueB(kc+1); CPA_COMMIT(); }
        unsigned bb = sb + (MA_H + (kc & 1)*32*BS_H)*2;
        #pragma unroll
        for (int kk = 0; kk < 2; kk++){
            int k0 = kc*32 + kk*16;
            unsigned a[4];
            ldsm4(a, sb + ((wm*16 + lrow)*MA_STR + k0 + lcol8)*2);
            #pragma unroll
            for (int j = 0; j < 4; j++){
                unsigned bv[4];
                ldsm4t(bv, bb + ((kk*16 + lrow)*BS_H + wn*64 + j*16 + lcol8)*2);
                unsigned b0[2] = {bv[0], bv[1]};
                unsigned b1[2] = {bv[2], bv[3]};
                mma16(acc[2*j],   a, b0);
                mma16(acc[2*j+1], a, b1);
            }
        }
        if (kc + 1 < 8){ CPA_WAIT0(); __syncthreads(); }
    }

    // LN epilogue -> fp16 g_msgh
    __syncthreads();
    float2* red = (float2*)smraw;
    float s1[2] = {0,0}, s2[2] = {0,0};
    #pragma unroll
    for (int nt = 0; nt < 8; nt++){
        float c0=acc[nt][0], c1=acc[nt][1], c2=acc[nt][2], c3=acc[nt][3];
        s1[0] += c0+c1; s2[0] += c0*c0 + c1*c1;
        s1[1] += c2+c3; s2[1] += c2*c2 + c3*c3;
    }
    #pragma unroll
    for (int hb = 0; hb < 2; hb++){
        float v1 = s1[hb], v2 = s2[hb];
        v1 += __shfl_xor_sync(~0u, v1, 1); v1 += __shfl_xor_sync(~0u, v1, 2);
        v2 += __shfl_xor_sync(~0u, v2, 1); v2 += __shfl_xor_sync(~0u, v2, 2);
        if (tig == 0){
            int r = wm*16 + g4 + hb*8;
            red[r*4 + wn] = make_float2(v1, v2);
        }
    }
    __syncthreads();
    #pragma unroll
    for (int hb = 0; hb < 2; hb++){
        int r = wm*16 + g4 + hb*8;
        float S1 = 0.f, S2 = 0.f;
        #pragma unroll
        for (int j = 0; j < 4; j++){ float2 e = red[r*4+j]; S1 += e.x; S2 += e.y; }
        float mean = S1 * (1.f/256.f);
        float var  = S2 * (1.f/256.f) - mean*mean;
        float inv  = rsqrtf(var + 1e-5f);
        int grow = row0 + r;
        #pragma unroll
        for (int nt = 0; nt < 8; nt++){
            int col = wn*64 + nt*8 + 2*tig;
            float c0 = acc[nt][hb*2], c1 = acc[nt][hb*2+1];
            float o0 = (c0 - mean)*inv*gamma[col]   + beta[col];
            float o1 = (c1 - mean)*inv*gamma[col+1] + beta[col+1];
            *(unsigned*)(g_msgh + grow*256 + col) = h2pk(o0, o1);
        }
    }
}

// ---------------------------------------------------------------------------
// Flash attention v10 (R14 proven): BM=64, 512 threads; cp.async double-
// buffered K/V/comp/mask; register P; Q fragments hoisted; fp16 partials.
// ---------------------------------------------------------------------------
#define QH 264
#define CS_STR 36
#define AT_K   16896
#define AT_V   33792
#define AT_CB  101376
#define AT_SMS 119808
#define AT_XM  120064
#define ATTN_BYTES 120320

__device__ __forceinline__ void attn_issue_tile(
    const __half* __restrict__ Km, const __half* __restrict__ Vm,
    const float* __restrict__ comp, const int* __restrict__ smask,
    unsigned sb, int buf, int b, int l0, int s0, int tid)
{
    unsigned kdst = sb + (AT_K + buf*8448)*2;
    unsigned vdst = sb + (AT_V + buf*8448)*2;
    #pragma unroll
    for (int i = 0; i < 2; i++){
        int id = tid + i*512;
        int r = id >> 5, c8 = (id & 31) << 3;
        long grow = (long)(b*LQ + s0 + r)*256 + c8;
        cpa16(kdst + (r*QH + c8)*2, Km + grow);
        cpa16(vdst + (r*QH + c8)*2, Vm + grow);
    }
    {
        int r = tid >> 3, c4 = (tid & 7) << 2;
        unsigned cdst = sb + AT_CB + buf*(64*CS_STR*4) + (r*CS_STR + c4)*4;
        cpa16(cdst, comp + (long)(b*LQ + l0 + r)*LQ + s0 + c4);
    }
    if (tid < 32)
        cpa4(sb + AT_SMS + buf*128 + tid*4, smask + b*LQ + s0 + tid);
}

__global__ void __launch_bounds__(512, 1) k_attn(
    const __half* __restrict__ Qm, const __half* __restrict__ Km, const __half* __restrict__ Vm,
    const float* __restrict__ comp, const int* __restrict__ xmask, const int* __restrict__ smask)
{
    extern __shared__ unsigned char smraw[];
    __half* smh = (__half*)smraw;
    __half* Qh = smh;
    float*  CsBase = (float*)(smraw + AT_CB);
    int*    smsBase = (int*)(smraw + AT_SMS);
    int*    xm = (int*)(smraw + AT_XM);

    int tid = threadIdx.x;
    int w = tid >> 5, lane = tid & 31;
    int h = w & 3, wm = w >> 2;
    int g4 = lane >> 2, tig = lane & 3;
    int lrow = (lane & 7) + ((lane >> 3) & 1)*8;
    int lcol8 = (lane >> 4)*8;
    int l0 = blockIdx.x * 64;
    int sp = blockIdx.y, b = blockIdx.z;
    int dbase = h*64;

    unsigned sb = (unsigned)__cvta_generic_to_shared(smh);
    unsigned qb = sb;

    int sbase = sp*(LQ/SPLITS);
    attn_issue_tile(Km, Vm, comp, smask, sb, 0, b, l0, sbase, tid);
    CPA_COMMIT();

    #pragma unroll
    for (int i = 0; i < 4; i++){
        int id = tid + i*512;
        int r = id >> 5, c8 = (id & 31) << 3;
        *(uint4*)&Qh[r*QH + c8] = *(const uint4*)(Qm + (b*LQ + l0 + r)*256 + c8);
    }
    if (tid < 64) xm[tid] = xmask[b*LQ + l0 + tid];

    float o[8][4];
    #pragma unroll
    for (int nt = 0; nt < 8; nt++)
        #pragma unroll
        for (int i = 0; i < 4; i++) o[nt][i] = 0.f;
    float rmax[2] = {-1e30f, -1e30f};
    float rsum[2] = {0.f, 0.f};

    CPA_WAIT0();
    __syncthreads();

    unsigned qa[4][4];
    #pragma unroll
    for (int kk = 0; kk < 4; kk++)
        ldsm4(qa[kk], qb + ((wm*16 + lrow)*QH + dbase + kk*16 + lcol8)*2);

    int rl = wm*16 + g4;
    const int NT = (LQ/SPLITS)/32;
    for (int t = 0; t < NT; t++){
        int buf = t & 1;
        unsigned kb = sb + (AT_K + buf*8448)*2;
        unsigned vb = sb + (AT_V + buf*8448)*2;
        float* Cs = CsBase + buf*(64*CS_STR);
        int*   sms = smsBase + buf*32;

        if (t + 1 < NT){
            attn_issue_tile(Km, Vm, comp, smask, sb, buf^1, b, l0, sbase + (t+1)*32, tid);
            CPA_COMMIT();
        }

        float S[4][4];
        #pragma unroll
        for (int nt = 0; nt < 4; nt++)
            #pragma unroll
            for (int i = 0; i < 4; i++) S[nt][i] = 0.f;
        #pragma unroll
        for (int kk = 0; kk < 4; kk++){
            int k0 = dbase + kk*16;
            #pragma unroll
            for (int sh = 0; sh < 2; sh++){
                unsigned bk[4];
                ldsm4(bk, kb + ((sh*16 + lrow)*QH + k0 + lcol8)*2);
                unsigned b0[2] = {bk[0], bk[2]};
                unsigned b1[2] = {bk[1], bk[3]};
                mma16(S[sh*2],   qa[kk], b0);
                mma16(S[sh*2+1], qa[kk], b1);
            }
        }

        int xml = xm[rl], xmh = xm[rl + 8];
        float tmaxl = -1e30f, tmaxh = -1e30f;
        #pragma unroll
        for (int nt = 0; nt < 4; nt++){
            int se = nt*8 + 2*tig, so = se + 1;
            int mse = sms[se], mso = sms[so];
            float ce = Cs[rl*CS_STR + se],      co = Cs[rl*CS_STR + so];
            float de = Cs[(rl+8)*CS_STR + se],  dox = Cs[(rl+8)*CS_STR + so];
            float v0 = (xml && !mse) ? -1e30f : S[nt][0]*ce;
            float v1 = (xml && !mso) ? -1e30f : S[nt][1]*co;
            float v2 = (xmh && !mse) ? -1e30f : S[nt][2]*de;
            float v3 = (xmh && !mso) ? -1e30f : S[nt][3]*dox;
            S[nt][0]=v0; S[nt][1]=v1; S[nt][2]=v2; S[nt][3]=v3;
            tmaxl = fmaxf(tmaxl, fmaxf(v0, v1));
            tmaxh = fmaxf(tmaxh, fmaxf(v2, v3));
        }
        tmaxl = fmaxf(tmaxl, __shfl_xor_sync(~0u, tmaxl, 1));
        tmaxl = fmaxf(tmaxl, __shfl_xor_sync(~0u, tmaxl, 2));
        tmaxh = fmaxf(tmaxh, __shfl_xor_sync(~0u, tmaxh, 1));
        tmaxh = fmaxf(tmaxh, __shfl_xor_sync(~0u, tmaxh, 2));
        float ml = fmaxf(rmax[0], tmaxl), mh = fmaxf(rmax[1], tmaxh);
        float al = fast_exp(rmax[0] - ml), ah = fast_exp(rmax[1] - mh);
        rmax[0] = ml; rmax[1] = mh;
        float tsl = 0.f, tsh = 0.f;
        unsigned Pa[4][2];
        #pragma unroll
        for (int nt = 0; nt < 4; nt++){
            float p0 = fast_exp(S[nt][0] - ml);
            float p1 = fast_exp(S[nt][1] - ml);
            float p2 = fast_exp(S[nt][2] - mh);
            float p3 = fast_exp(S[nt][3] - mh);
            tsl += p0 + p1; tsh += p2 + p3;
            Pa[nt][0] = h2pk(p0, p1);
            Pa[nt][1] = h2pk(p2, p3);
        }
        tsl += __shfl_xor_sync(~0u, tsl, 1); tsl += __shfl_xor_sync(~0u, tsl, 2);
        tsh += __shfl_xor_sync(~0u, tsh, 1); tsh += __shfl_xor_sync(~0u, tsh, 2);
        rsum[0] = rsum[0]*al + tsl;
        rsum[1] = rsum[1]*ah + tsh;
        #pragma unroll
        for (int nt = 0; nt < 8; nt++){
            o[nt][0] *= al; o[nt][1] *= al;
            o[nt][2] *= ah; o[nt][3] *= ah;
        }

        #pragma unroll
        for (int kk = 0; kk < 2; kk++){
            unsigned a[4] = {Pa[kk*2][0], Pa[kk*2][1], Pa[kk*2+1][0], Pa[kk*2+1][1]};
            #pragma unroll
            for (int j = 0; j < 4; j++){
                unsigned bv[4];
                ldsm4t(bv, vb + ((kk*16 + lrow)*QH + dbase + j*16 + lcol8)*2);
                unsigned b0[2] = {bv[0], bv[1]};
                unsigned b1[2] = {bv[2], bv[3]};
                mma16(o[2*j],   a, b0);
                mma16(o[2*j+1], a, b1);
            }
        }

        if (t + 1 < NT){
            CPA_WAIT0();
            __syncthreads();
        }
    }

    long prow = (long)(sp*MROWS + b*LQ + l0 + rl);
    #pragma unroll
    for (int nt = 0; nt < 8; nt++){
        int col = dbase + nt*8 + 2*tig;
        *(unsigned*)(g_parth + prow*256 + col)     = h2pk(o[nt][0], o[nt][1]);
        *(unsigned*)(g_parth + (prow+8)*256 + col) = h2pk(o[nt][2], o[nt][3]);
    }
    if (tig == 0){
        long base = (prow*4 + h)*2;
        g_pstat[base]   = rmax[0];
        g_pstat[base+1] = rsum[0];
        long baseh = ((prow+8)*4 + h)*2;
        g_pstat[baseh]   = rmax[1];
        g_pstat[baseh+1] = rsum[1];
    }
}

// ---------------------------------------------------------------------------
extern "C" void kernel_launch(void* const* d_in, const int* in_sizes, int n_in,
                              void* d_out, int out_size)
{
    const float* x    = (const float*)d_in[0];
    const float* src  = (const float*)d_in[1];
    const float* xpe  = (const float*)d_in[2];
    const float* spe  = (const float*)d_in[3];
    const int* xmask  = (const int*)d_in[4];
    const int* smask  = (const int*)d_in[5];
    const float* comp = (const float*)d_in[6];
    const float* Wq   = (const float*)d_in[7];
    const float* Wk   = (const float*)d_in[8];
    const float* Wv   = (const float*)d_in[9];
    const float* Wmg  = (const float*)d_in[10];
    const float* Wm1  = (const float*)d_in[11];
    const float* Wm2  = (const float*)d_in[12];
    const float* ln1g = (const float*)d_in[13];
    const float* ln1b = (const float*)d_in[14];
    const float* ln2g = (const float*)d_in[15];
    const float* ln2b = (const float*)d_in[16];
    float* out = (float*)d_out;

    __half *Qp, *Kp, *Vp;
    cudaGetSymbolAddress((void**)&Qp, g_Qh);
    cudaGetSymbolAddress((void**)&Kp, g_Kh);
    cudaGetSymbolAddress((void**)&Vp, g_Vh);

    cudaFuncSetAttribute(k_attn,  cudaFuncAttributeMaxDynamicSharedMemorySize, ATTN_BYTES);
    cudaFuncSetAttribute(k_merge, cudaFuncAttributeMaxDynamicSharedMemorySize, SM_MERGE);

    k_prep<<<(int)PREP_GRID, 256>>>(Wq, Wk, Wv, Wmg, Wm1, Wm2);
    k_qkv <<<dim3(MROWS/32, 1, 3), 256, SM_GEMM>>>(x, xpe, src, spe);
    k_attn<<<dim3(LQ/64, SPLITS, BSZ), 512, ATTN_BYTES>>>(Qp, Kp, Vp, comp, xmask, smask);
    k_merge<<<MROWS/32, 256, SM_MERGE>>>(ln1g, ln1b);
    k_mlp1<<<dim3(MROWS/32, 2), 256, SM_GEMM>>>(x);
    k_mlp2<<<MROWS/32, 256, SM_GEMM>>>(ln2g, ln2b, x, out);
}